// round 1
// baseline (speedup 1.0000x reference)
#include <cuda_runtime.h>

#define D_DIM 2048
#define E_NUM 8
#define F_DIM 768
#define T_MAX 2048
#define BM 64
#define BN 64
#define BK 16

// ---------------- static device scratch (no allocations allowed) ----------------
__device__ int   g_cnt[E_NUM];
__device__ int   g_cursor[E_NUM];
__device__ int   g_off[E_NUM + 1];
__device__ int   g_topk_idx[T_MAX * 2];
__device__ float g_topk_w[T_MAX * 2];
__device__ int   g_tok_of_slot[T_MAX * 2];
__device__ int   g_slot_of[T_MAX * 2];
__device__ float g_H[(size_t)T_MAX * 2 * F_DIM];   // hidden (post-SwiGLU), per slot
__device__ float g_O[(size_t)T_MAX * 2 * D_DIM];   // down-proj output, per slot

// ---------------- f32x2 packed math helpers ----------------
__device__ __forceinline__ unsigned long long fma2(unsigned long long a,
                                                   unsigned long long b,
                                                   unsigned long long c) {
    unsigned long long d;
    asm("fma.rn.f32x2 %0, %1, %2, %3;" : "=l"(d) : "l"(a), "l"(b), "l"(c));
    return d;
}
__device__ __forceinline__ unsigned long long pack2(float x) {
    unsigned long long r;
    asm("mov.b64 %0, {%1, %1};" : "=l"(r) : "r"(__float_as_uint(x)));
    return r;
}
__device__ __forceinline__ float2 unpack2(unsigned long long v) {
    unsigned int lo, hi;
    asm("mov.b64 {%0, %1}, %2;" : "=r"(lo), "=r"(hi) : "l"(v));
    float2 f;
    f.x = __uint_as_float(lo);
    f.y = __uint_as_float(hi);
    return f;
}

// ---------------- phase 0: reset counters ----------------
__global__ void reset_kernel() {
    if (threadIdx.x < E_NUM) g_cnt[threadIdx.x] = 0;
}

// ---------------- phase 1: router (one warp per token) ----------------
__global__ void router_kernel(const float* __restrict__ x,
                              const float* __restrict__ wr, int T) {
    int warp = threadIdx.x >> 5;
    int lane = threadIdx.x & 31;
    int t = blockIdx.x * 8 + warp;
    if (t >= T) return;

    const float4* x4 = (const float4*)(x + (size_t)t * D_DIM);
    const float4* w4 = (const float4*)wr;

    float acc[E_NUM];
#pragma unroll
    for (int e = 0; e < E_NUM; e++) acc[e] = 0.f;

    for (int d4 = lane; d4 < D_DIM / 4; d4 += 32) {
        float4 xv = x4[d4];
#pragma unroll
        for (int e = 0; e < E_NUM; e++) {
            float4 wv = w4[e * (D_DIM / 4) + d4];
            acc[e] += xv.x * wv.x + xv.y * wv.y + xv.z * wv.z + xv.w * wv.w;
        }
    }
#pragma unroll
    for (int e = 0; e < E_NUM; e++) {
#pragma unroll
        for (int o = 16; o > 0; o >>= 1)
            acc[e] += __shfl_xor_sync(0xffffffffu, acc[e], o);
    }
    if (lane == 0) {
        float s0 = -1e30f, s1 = -1e30f;
        int i0 = 0, i1 = 0;
#pragma unroll
        for (int e = 0; e < E_NUM; e++) {
            float v = acc[e];
            if (v > s0) { s1 = s0; i1 = i0; s0 = v; i0 = e; }
            else if (v > s1) { s1 = v; i1 = e; }
        }
        float p1 = expf(s1 - s0);
        float inv = 1.f / (1.f + p1);
        g_topk_idx[2 * t] = i0;
        g_topk_idx[2 * t + 1] = i1;
        g_topk_w[2 * t] = inv;
        g_topk_w[2 * t + 1] = p1 * inv;
        atomicAdd(&g_cnt[i0], 1);
        atomicAdd(&g_cnt[i1], 1);
    }
}

// ---------------- phase 2: offsets (exclusive scan over 8 counts) ----------------
__global__ void offsets_kernel() {
    if (threadIdx.x == 0) {
        int o = 0;
        for (int e = 0; e < E_NUM; e++) {
            g_off[e] = o;
            o += g_cnt[e];
            g_cursor[e] = 0;
        }
        g_off[E_NUM] = o;
    }
}

// ---------------- phase 3: assignment -> slots ----------------
__global__ void assign_kernel(int T) {
    int i = blockIdx.x * 256 + threadIdx.x;
    if (i >= 2 * T) return;
    int e = g_topk_idx[i];
    int pos = atomicAdd(&g_cursor[e], 1);
    int slot = g_off[e] + pos;
    g_tok_of_slot[slot] = i >> 1;
    g_slot_of[i] = slot;
}

// ---------------- phase 4: GEMM1 (gate + up fused, SiLU epilogue) ----------------
// H[slot, f] = silu(X[tok] . Wg[e,f,:]) * (X[tok] . Wu[e,f,:])
__global__ __launch_bounds__(256) void gemm1_kernel(const float* __restrict__ x,
                                                    const float* __restrict__ wg,
                                                    const float* __restrict__ wu) {
    int e = blockIdx.z;
    int cnt = g_cnt[e];
    int m0 = blockIdx.y * BM;
    if (m0 >= cnt) return;
    int off = g_off[e];
    int f0 = blockIdx.x * BN;

    __shared__ float As[BK][BM + 4];
    __shared__ float Bg[BK][BN + 4];
    __shared__ float Bu[BK][BN + 4];

    int tid = threadIdx.x;
    int lr = tid >> 2;   // 0..63
    int lc = tid & 3;    // 0..3 (float4 within 16-wide K slab)

    const float4* arow = nullptr;
    {
        int mrow = m0 + lr;
        if (mrow < cnt) {
            int tok = g_tok_of_slot[off + mrow];
            arow = (const float4*)(x + (size_t)tok * D_DIM);
        }
    }
    const float4* grow = (const float4*)(wg + ((size_t)e * F_DIM + (f0 + lr)) * D_DIM);
    const float4* urow = (const float4*)(wu + ((size_t)e * F_DIM + (f0 + lr)) * D_DIM);

    int ty = tid >> 4, tx = tid & 15;
    unsigned long long accG[4][2], accU[4][2];
#pragma unroll
    for (int i = 0; i < 4; i++)
#pragma unroll
        for (int j = 0; j < 2; j++) { accG[i][j] = 0ull; accU[i][j] = 0ull; }

    for (int kk = 0; kk < D_DIM / BK; kk++) {
        float4 av = arow ? arow[kk * 4 + lc] : make_float4(0.f, 0.f, 0.f, 0.f);
        float4 gv = grow[kk * 4 + lc];
        float4 uv = urow[kk * 4 + lc];
        As[lc * 4 + 0][lr] = av.x; As[lc * 4 + 1][lr] = av.y;
        As[lc * 4 + 2][lr] = av.z; As[lc * 4 + 3][lr] = av.w;
        Bg[lc * 4 + 0][lr] = gv.x; Bg[lc * 4 + 1][lr] = gv.y;
        Bg[lc * 4 + 2][lr] = gv.z; Bg[lc * 4 + 3][lr] = gv.w;
        Bu[lc * 4 + 0][lr] = uv.x; Bu[lc * 4 + 1][lr] = uv.y;
        Bu[lc * 4 + 2][lr] = uv.z; Bu[lc * 4 + 3][lr] = uv.w;
        __syncthreads();
#pragma unroll
        for (int k = 0; k < BK; k++) {
            float4 a4 = *(const float4*)&As[k][ty * 4];
            ulonglong2 bg = *(const ulonglong2*)&Bg[k][tx * 4];
            ulonglong2 bu = *(const ulonglong2*)&Bu[k][tx * 4];
            unsigned long long ap;
#define MOE_STEP(i, aval)                                                   \
            ap = pack2(aval);                                               \
            accG[i][0] = fma2(ap, bg.x, accG[i][0]);                        \
            accG[i][1] = fma2(ap, bg.y, accG[i][1]);                        \
            accU[i][0] = fma2(ap, bu.x, accU[i][0]);                        \
            accU[i][1] = fma2(ap, bu.y, accU[i][1]);
            MOE_STEP(0, a4.x)
            MOE_STEP(1, a4.y)
            MOE_STEP(2, a4.z)
            MOE_STEP(3, a4.w)
#undef MOE_STEP
        }
        __syncthreads();
    }

#pragma unroll
    for (int i = 0; i < 4; i++) {
        int m = m0 + ty * 4 + i;
        if (m >= cnt) continue;
        float2 g01 = unpack2(accG[i][0]);
        float2 g23 = unpack2(accG[i][1]);
        float2 u01 = unpack2(accU[i][0]);
        float2 u23 = unpack2(accU[i][1]);
        float4 h;
        h.x = g01.x / (1.f + expf(-g01.x)) * u01.x;
        h.y = g01.y / (1.f + expf(-g01.y)) * u01.y;
        h.z = g23.x / (1.f + expf(-g23.x)) * u23.x;
        h.w = g23.y / (1.f + expf(-g23.y)) * u23.y;
        *(float4*)&g_H[(size_t)(off + m) * F_DIM + f0 + tx * 4] = h;
    }
}

// ---------------- phase 5: GEMM2 (down projection) ----------------
// O[slot, d] = H[slot, :] . Wd[e, d, :]
__global__ __launch_bounds__(256) void gemm2_kernel(const float* __restrict__ wd) {
    int e = blockIdx.z;
    int cnt = g_cnt[e];
    int m0 = blockIdx.y * BM;
    if (m0 >= cnt) return;
    int off = g_off[e];
    int n0 = blockIdx.x * BN;

    __shared__ float As[BK][BM + 4];
    __shared__ float Bs[BK][BN + 4];

    int tid = threadIdx.x;
    int lr = tid >> 2;
    int lc = tid & 3;

    const float4* arow = nullptr;
    {
        int mrow = m0 + lr;
        if (mrow < cnt)
            arow = (const float4*)&g_H[(size_t)(off + mrow) * F_DIM];
    }
    const float4* brow = (const float4*)(wd + ((size_t)e * D_DIM + (n0 + lr)) * F_DIM);

    int ty = tid >> 4, tx = tid & 15;
    unsigned long long acc[4][2];
#pragma unroll
    for (int i = 0; i < 4; i++) { acc[i][0] = 0ull; acc[i][1] = 0ull; }

    for (int kk = 0; kk < F_DIM / BK; kk++) {
        float4 av = arow ? arow[kk * 4 + lc] : make_float4(0.f, 0.f, 0.f, 0.f);
        float4 bv = brow[kk * 4 + lc];
        As[lc * 4 + 0][lr] = av.x; As[lc * 4 + 1][lr] = av.y;
        As[lc * 4 + 2][lr] = av.z; As[lc * 4 + 3][lr] = av.w;
        Bs[lc * 4 + 0][lr] = bv.x; Bs[lc * 4 + 1][lr] = bv.y;
        Bs[lc * 4 + 2][lr] = bv.z; Bs[lc * 4 + 3][lr] = bv.w;
        __syncthreads();
#pragma unroll
        for (int k = 0; k < BK; k++) {
            float4 a4 = *(const float4*)&As[k][ty * 4];
            ulonglong2 b2 = *(const ulonglong2*)&Bs[k][tx * 4];
            unsigned long long ap;
            ap = pack2(a4.x);
            acc[0][0] = fma2(ap, b2.x, acc[0][0]);
            acc[0][1] = fma2(ap, b2.y, acc[0][1]);
            ap = pack2(a4.y);
            acc[1][0] = fma2(ap, b2.x, acc[1][0]);
            acc[1][1] = fma2(ap, b2.y, acc[1][1]);
            ap = pack2(a4.z);
            acc[2][0] = fma2(ap, b2.x, acc[2][0]);
            acc[2][1] = fma2(ap, b2.y, acc[2][1]);
            ap = pack2(a4.w);
            acc[3][0] = fma2(ap, b2.x, acc[3][0]);
            acc[3][1] = fma2(ap, b2.y, acc[3][1]);
        }
        __syncthreads();
    }

#pragma unroll
    for (int i = 0; i < 4; i++) {
        int m = m0 + ty * 4 + i;
        if (m >= cnt) continue;
        float2 c01 = unpack2(acc[i][0]);
        float2 c23 = unpack2(acc[i][1]);
        float4 v;
        v.x = c01.x; v.y = c01.y; v.z = c23.x; v.w = c23.y;
        *(float4*)&g_O[(size_t)(off + m) * D_DIM + n0 + tx * 4] = v;
    }
}

// ---------------- phase 6: weighted combine (deterministic, no atomics) ----------------
__global__ void combine_kernel(float* __restrict__ out, int T) {
    int t = blockIdx.x;
    int d4 = blockIdx.y * blockDim.x + threadIdx.x;  // 0..511 (float4 granularity)
    float w0 = g_topk_w[2 * t];
    float w1 = g_topk_w[2 * t + 1];
    int s0 = g_slot_of[2 * t];
    int s1 = g_slot_of[2 * t + 1];
    const float4* o0 = (const float4*)&g_O[(size_t)s0 * D_DIM];
    const float4* o1 = (const float4*)&g_O[(size_t)s1 * D_DIM];
    float4 a = o0[d4];
    float4 b = o1[d4];
    float4 r;
    r.x = w0 * a.x + w1 * b.x;
    r.y = w0 * a.y + w1 * b.y;
    r.z = w0 * a.z + w1 * b.z;
    r.w = w0 * a.w + w1 * b.w;
    ((float4*)out)[(size_t)t * (D_DIM / 4) + d4] = r;
}

// ---------------- launch ----------------
extern "C" void kernel_launch(void* const* d_in, const int* in_sizes, int n_in,
                              void* d_out, int out_size) {
    const float* x  = (const float*)d_in[0];
    const float* wr = (const float*)d_in[1];
    const float* wg = (const float*)d_in[2];
    const float* wu = (const float*)d_in[3];
    const float* wd = (const float*)d_in[4];
    int T = in_sizes[0] / D_DIM;  // 2048

    reset_kernel<<<1, 32>>>();
    router_kernel<<<(T + 7) / 8, 256>>>(x, wr, T);
    offsets_kernel<<<1, 1>>>();
    assign_kernel<<<(2 * T + 255) / 256, 256>>>(T);

    dim3 g1(F_DIM / BN, (T + BM - 1) / BM, E_NUM);
    gemm1_kernel<<<g1, 256>>>(x, wg, wu);

    dim3 g2(D_DIM / BN, (T + BM - 1) / BM, E_NUM);
    gemm2_kernel<<<g2, 256>>>(wd);

    combine_kernel<<<dim3(T, 2), 256>>>((float*)d_out, T);
}

// round 3
// speedup vs baseline: 1.5304x; 1.5304x over previous
#include <cuda_runtime.h>
#include <cuda_bf16.h>
#include <cstdint>

#define D_DIM 2048
#define E_NUM 8
#define F_DIM 768
#define T_MAX 2048
#define SLOTS 4096

#define KT 32
#define NBUF 3
#define STG_BYTES 32768
#define SMEM_TOTAL (NBUF * STG_BYTES)

// ---------------- static device scratch ----------------
__device__ int   g_cnt[E_NUM];
__device__ int   g_cursor[E_NUM];
__device__ int   g_off[E_NUM + 1];
__device__ int   g_topk_idx[SLOTS];
__device__ float g_topk_w[SLOTS];
__device__ int   g_tok_of_slot[SLOTS];
__device__ int   g_slot_of[SLOTS];

__device__ __nv_bfloat16 g_xhi[T_MAX * D_DIM];
__device__ __nv_bfloat16 g_xlo[T_MAX * D_DIM];
__device__ __nv_bfloat16 g_wghi[E_NUM * F_DIM * D_DIM];
__device__ __nv_bfloat16 g_wglo[E_NUM * F_DIM * D_DIM];
__device__ __nv_bfloat16 g_wuhi[E_NUM * F_DIM * D_DIM];
__device__ __nv_bfloat16 g_wulo[E_NUM * F_DIM * D_DIM];
__device__ __nv_bfloat16 g_wdhi[E_NUM * D_DIM * F_DIM];
__device__ __nv_bfloat16 g_wdlo[E_NUM * D_DIM * F_DIM];
__device__ __nv_bfloat16 g_Hhi[(size_t)SLOTS * F_DIM];
__device__ __nv_bfloat16 g_Hlo[(size_t)SLOTS * F_DIM];
__device__ float g_O[(size_t)SLOTS * D_DIM];

// ---------------- helpers ----------------
__device__ __forceinline__ uint32_t smem_u32(const void* p) {
    uint32_t a;
    asm("{ .reg .u64 t; cvta.to.shared.u64 t, %1; cvt.u32.u64 %0, t; }" : "=r"(a) : "l"(p));
    return a;
}
__device__ __forceinline__ uint32_t lds32(uint32_t addr) {
    uint32_t v;
    asm volatile("ld.shared.b32 %0, [%1];" : "=r"(v) : "r"(addr));
    return v;
}
__device__ __forceinline__ void cp16(uint32_t dst, const void* src) {
    asm volatile("cp.async.cg.shared.global [%0], [%1], 16;" :: "r"(dst), "l"(src) : "memory");
}
__device__ __forceinline__ void cp_commit() { asm volatile("cp.async.commit_group;" ::: "memory"); }
template <int N>
__device__ __forceinline__ void cp_wait() { asm volatile("cp.async.wait_group %0;" :: "n"(N) : "memory"); }

__device__ __forceinline__ void mma_bf16(float* c, const uint32_t* a, uint32_t b0, uint32_t b1) {
    asm volatile(
        "mma.sync.aligned.m16n8k16.row.col.f32.bf16.bf16.f32 "
        "{%0,%1,%2,%3}, {%4,%5,%6,%7}, {%8,%9}, {%0,%1,%2,%3};"
        : "+f"(c[0]), "+f"(c[1]), "+f"(c[2]), "+f"(c[3])
        : "r"(a[0]), "r"(a[1]), "r"(a[2]), "r"(a[3]), "r"(b0), "r"(b1));
}

// fragment-order smem offsets (per 16B chunk of row r, chunk-col c in [0,4))
// A region: [mblock r>>4][slab c>>1][plane][ (r&7)*16 ]  plane = (c&1)*2 + ((r>>3)&1)
__device__ __forceinline__ uint32_t aoff(int m, int c) {
    return (uint32_t)((m >> 4) * 1024 + (c >> 1) * 512 +
                      (((c & 1) << 1) + ((m >> 3) & 1)) * 128 + (m & 7) * 16);
}
// B region: [ngroup n>>3][slab c>>1][plane c&1][ (n&7)*16 ]
__device__ __forceinline__ uint32_t boff(int n, int c) {
    return (uint32_t)((n >> 3) * 512 + (c >> 1) * 256 + (c & 1) * 128 + (n & 7) * 16);
}

// ---------------- small kernels ----------------
__global__ void reset_kernel() {
    if (threadIdx.x < E_NUM) g_cnt[threadIdx.x] = 0;
}

__global__ void convert_kernel(const float* __restrict__ src, int which, int n4) {
    int i = blockIdx.x * 256 + threadIdx.x;
    if (i >= n4) return;
    __nv_bfloat16 *hi, *lo;
    switch (which) {
        case 0: hi = g_xhi;  lo = g_xlo;  break;
        case 1: hi = g_wghi; lo = g_wglo; break;
        case 2: hi = g_wuhi; lo = g_wulo; break;
        default: hi = g_wdhi; lo = g_wdlo; break;
    }
    float4 v = ((const float4*)src)[i];
    __nv_bfloat162 h01, h23, l01, l23;
    h01.x = __float2bfloat16_rn(v.x); l01.x = __float2bfloat16_rn(v.x - __bfloat162float(h01.x));
    h01.y = __float2bfloat16_rn(v.y); l01.y = __float2bfloat16_rn(v.y - __bfloat162float(h01.y));
    h23.x = __float2bfloat16_rn(v.z); l23.x = __float2bfloat16_rn(v.z - __bfloat162float(h23.x));
    h23.y = __float2bfloat16_rn(v.w); l23.y = __float2bfloat16_rn(v.w - __bfloat162float(h23.y));
    ((__nv_bfloat162*)hi)[2 * i]     = h01;
    ((__nv_bfloat162*)hi)[2 * i + 1] = h23;
    ((__nv_bfloat162*)lo)[2 * i]     = l01;
    ((__nv_bfloat162*)lo)[2 * i + 1] = l23;
}

__global__ void router_kernel(const float* __restrict__ x,
                              const float* __restrict__ wr, int T) {
    int warp = threadIdx.x >> 5;
    int lane = threadIdx.x & 31;
    int t = blockIdx.x * 8 + warp;
    if (t >= T) return;

    const float4* x4 = (const float4*)(x + (size_t)t * D_DIM);
    const float4* w4 = (const float4*)wr;
    float acc[E_NUM];
#pragma unroll
    for (int e = 0; e < E_NUM; e++) acc[e] = 0.f;
    for (int d4 = lane; d4 < D_DIM / 4; d4 += 32) {
        float4 xv = x4[d4];
#pragma unroll
        for (int e = 0; e < E_NUM; e++) {
            float4 wv = w4[e * (D_DIM / 4) + d4];
            acc[e] += xv.x * wv.x + xv.y * wv.y + xv.z * wv.z + xv.w * wv.w;
        }
    }
#pragma unroll
    for (int e = 0; e < E_NUM; e++) {
#pragma unroll
        for (int o = 16; o > 0; o >>= 1)
            acc[e] += __shfl_xor_sync(0xffffffffu, acc[e], o);
    }
    if (lane == 0) {
        float s0 = -1e30f, s1 = -1e30f;
        int i0 = 0, i1 = 0;
#pragma unroll
        for (int e = 0; e < E_NUM; e++) {
            float v = acc[e];
            if (v > s0) { s1 = s0; i1 = i0; s0 = v; i0 = e; }
            else if (v > s1) { s1 = v; i1 = e; }
        }
        float p1 = expf(s1 - s0);
        float inv = 1.f / (1.f + p1);
        g_topk_idx[2 * t] = i0;
        g_topk_idx[2 * t + 1] = i1;
        g_topk_w[2 * t] = inv;
        g_topk_w[2 * t + 1] = p1 * inv;
        atomicAdd(&g_cnt[i0], 1);
        atomicAdd(&g_cnt[i1], 1);
    }
}

__global__ void offsets_kernel() {
    if (threadIdx.x == 0) {
        int o = 0;
        for (int e = 0; e < E_NUM; e++) {
            g_off[e] = o;
            o += g_cnt[e];
            g_cursor[e] = 0;
        }
        g_off[E_NUM] = o;
    }
}

__global__ void assign_kernel(int T) {
    int i = blockIdx.x * 256 + threadIdx.x;
    if (i >= 2 * T) return;
    int e = g_topk_idx[i];
    int pos = atomicAdd(&g_cursor[e], 1);
    int slot = g_off[e] + pos;
    g_tok_of_slot[slot] = i >> 1;
    g_slot_of[i] = slot;
}

// ================= GEMM1: H = SwiGLU(X Wg^T, X Wu^T) =================
// CTA tile M=128 x N=128 (B rows 0..63 gate f0+n, 64..127 up f0+n-64), K=2048.
__global__ __launch_bounds__(256, 1) void gemm1_mma() {
    int e = blockIdx.z;
    int cnt = g_cnt[e];
    int m0 = blockIdx.y * 128;
    if (m0 >= cnt) return;
    int off = g_off[e];
    int f0 = blockIdx.x * 64;

    extern __shared__ __align__(16) char smem[];
    uint32_t sb = smem_u32(smem);
    int tid = threadIdx.x, w = tid >> 5, lane = tid & 31;

    // ---- per-thread cp.async chunk setup ----
    int rA = tid >> 2, cA = tid & 3;            // A rows rA, rA+64
    int rB = tid >> 2, cB = tid & 3;            // B rows rB (gate), rB+64 (up)
    int mA0 = m0 + rA;      if (mA0 >= cnt) mA0 = cnt - 1;
    int mA1 = m0 + rA + 64; if (mA1 >= cnt) mA1 = cnt - 1;
    const char* aP0 = (const char*)(g_xhi + (size_t)g_tok_of_slot[off + mA0] * D_DIM + cA * 8);
    const char* aP1 = (const char*)(g_xhi + (size_t)g_tok_of_slot[off + mA1] * D_DIM + cA * 8);
    const char* bP0 = (const char*)(g_wghi + ((size_t)e * F_DIM + f0 + rB) * D_DIM + cB * 8);
    const char* bP1 = (const char*)(g_wuhi + ((size_t)e * F_DIM + f0 + rB) * D_DIM + cB * 8);
    const ptrdiff_t dX = (const char*)g_xlo - (const char*)g_xhi;
    const ptrdiff_t dG = (const char*)g_wglo - (const char*)g_wghi;
    const ptrdiff_t dU = (const char*)g_wulo - (const char*)g_wuhi;
    uint32_t oA0 = aoff(rA, cA), oA1 = aoff(rA + 64, cA);
    uint32_t oB0 = 16384u + boff(rB, cB), oB1 = 16384u + boff(rB + 64, cB);

    float acc[16][4];
#pragma unroll
    for (int g = 0; g < 16; g++)
#pragma unroll
        for (int i = 0; i < 4; i++) acc[g][i] = 0.f;

    const int NS = D_DIM / KT;  // 64

    // prologue: stages 0,1
#pragma unroll
    for (int s = 0; s < 2; s++) {
        uint32_t stb = sb + (uint32_t)s * STG_BYTES;
        cp16(stb + oA0, aP0);           cp16(stb + oA1, aP1);
        cp16(stb + 8192 + oA0, aP0 + dX); cp16(stb + 8192 + oA1, aP1 + dX);
        cp16(stb + oB0, bP0);           cp16(stb + oB1, bP1);
        cp16(stb + 8192 + oB0, bP0 + dG); cp16(stb + 8192 + oB1, bP1 + dU);
        aP0 += 64; aP1 += 64; bP0 += 64; bP1 += 64;
        cp_commit();
    }

    for (int s = 0; s < NS; s++) {
        cp_wait<1>();
        __syncthreads();
        if (s + 2 < NS) {
            uint32_t stb = sb + (uint32_t)((s + 2) % NBUF) * STG_BYTES;
            cp16(stb + oA0, aP0);           cp16(stb + oA1, aP1);
            cp16(stb + 8192 + oA0, aP0 + dX); cp16(stb + 8192 + oA1, aP1 + dX);
            cp16(stb + oB0, bP0);           cp16(stb + oB1, bP1);
            cp16(stb + 8192 + oB0, bP0 + dG); cp16(stb + 8192 + oB1, bP1 + dU);
            aP0 += 64; aP1 += 64; bP0 += 64; bP1 += 64;
        }
        cp_commit();

        uint32_t st = sb + (uint32_t)(s % NBUF) * STG_BYTES;
#pragma unroll
        for (int s2 = 0; s2 < 2; s2++) {
            uint32_t baseA = st + (uint32_t)w * 1024 + (uint32_t)s2 * 512 + (uint32_t)lane * 4;
            uint32_t ah[4], al[4];
#pragma unroll
            for (int p = 0; p < 4; p++) {
                ah[p] = lds32(baseA + p * 128);
                al[p] = lds32(baseA + 8192 + p * 128);
            }
#pragma unroll
            for (int g = 0; g < 16; g++) {
                uint32_t baseB = st + 16384u + (uint32_t)g * 512 + (uint32_t)s2 * 256 + (uint32_t)lane * 4;
                uint32_t bh0 = lds32(baseB);
                uint32_t bh1 = lds32(baseB + 128);
                uint32_t bl0 = lds32(baseB + 8192);
                uint32_t bl1 = lds32(baseB + 8192 + 128);
                mma_bf16(acc[g], ah, bh0, bh1);
                mma_bf16(acc[g], ah, bl0, bl1);
                mma_bf16(acc[g], al, bh0, bh1);
            }
        }
    }

    // epilogue: SwiGLU + bf16 hi/lo split, warp w owns rows m0+w*16 + {q, q+8}
    int q = lane >> 2, t4 = lane & 3;
    int row0 = m0 + w * 16 + q;
    int row1 = row0 + 8;
#pragma unroll
    for (int g = 0; g < 8; g++) {
        int fi = f0 + g * 8 + t4 * 2;
        if (row0 < cnt) {
            float g0 = acc[g][0], g1 = acc[g][1];
            float u0 = acc[g + 8][0], u1 = acc[g + 8][1];
            float h0 = g0 / (1.f + __expf(-g0)) * u0;
            float h1 = g1 / (1.f + __expf(-g1)) * u1;
            __nv_bfloat162 hh, hl;
            hh.x = __float2bfloat16_rn(h0); hl.x = __float2bfloat16_rn(h0 - __bfloat162float(hh.x));
            hh.y = __float2bfloat16_rn(h1); hl.y = __float2bfloat16_rn(h1 - __bfloat162float(hh.y));
            *(__nv_bfloat162*)&g_Hhi[(size_t)(off + row0) * F_DIM + fi] = hh;
            *(__nv_bfloat162*)&g_Hlo[(size_t)(off + row0) * F_DIM + fi] = hl;
        }
        if (row1 < cnt) {
            float g0 = acc[g][2], g1 = acc[g][3];
            float u0 = acc[g + 8][2], u1 = acc[g + 8][3];
            float h0 = g0 / (1.f + __expf(-g0)) * u0;
            float h1 = g1 / (1.f + __expf(-g1)) * u1;
            __nv_bfloat162 hh, hl;
            hh.x = __float2bfloat16_rn(h0); hl.x = __float2bfloat16_rn(h0 - __bfloat162float(hh.x));
            hh.y = __float2bfloat16_rn(h1); hl.y = __float2bfloat16_rn(h1 - __bfloat162float(hh.y));
            *(__nv_bfloat162*)&g_Hhi[(size_t)(off + row1) * F_DIM + fi] = hh;
            *(__nv_bfloat162*)&g_Hlo[(size_t)(off + row1) * F_DIM + fi] = hl;
        }
    }
}

// ================= GEMM2: O = H Wd^T =================
// CTA tile M=128 x N=128, K=768.
__global__ __launch_bounds__(256, 1) void gemm2_mma() {
    int e = blockIdx.z;
    int cnt = g_cnt[e];
    int m0 = blockIdx.y * 128;
    if (m0 >= cnt) return;
    int off = g_off[e];
    int n0 = blockIdx.x * 128;

    extern __shared__ __align__(16) char smem[];
    uint32_t sb = smem_u32(smem);
    int tid = threadIdx.x, w = tid >> 5, lane = tid & 31;

    int rA = tid >> 2, cA = tid & 3;
    int rB = tid >> 2, cB = tid & 3;
    int mA0 = m0 + rA;      if (mA0 >= cnt) mA0 = cnt - 1;
    int mA1 = m0 + rA + 64; if (mA1 >= cnt) mA1 = cnt - 1;
    const char* aP0 = (const char*)(g_Hhi + (size_t)(off + mA0) * F_DIM + cA * 8);
    const char* aP1 = (const char*)(g_Hhi + (size_t)(off + mA1) * F_DIM + cA * 8);
    const char* bP0 = (const char*)(g_wdhi + ((size_t)e * D_DIM + n0 + rB) * F_DIM + cB * 8);
    const char* bP1 = (const char*)(g_wdhi + ((size_t)e * D_DIM + n0 + rB + 64) * F_DIM + cB * 8);
    const ptrdiff_t dH = (const char*)g_Hlo - (const char*)g_Hhi;
    const ptrdiff_t dD = (const char*)g_wdlo - (const char*)g_wdhi;
    uint32_t oA0 = aoff(rA, cA), oA1 = aoff(rA + 64, cA);
    uint32_t oB0 = 16384u + boff(rB, cB), oB1 = 16384u + boff(rB + 64, cB);

    float acc[16][4];
#pragma unroll
    for (int g = 0; g < 16; g++)
#pragma unroll
        for (int i = 0; i < 4; i++) acc[g][i] = 0.f;

    const int NS = F_DIM / KT;  // 24

#pragma unroll
    for (int s = 0; s < 2; s++) {
        uint32_t stb = sb + (uint32_t)s * STG_BYTES;
        cp16(stb + oA0, aP0);           cp16(stb + oA1, aP1);
        cp16(stb + 8192 + oA0, aP0 + dH); cp16(stb + 8192 + oA1, aP1 + dH);
        cp16(stb + oB0, bP0);           cp16(stb + oB1, bP1);
        cp16(stb + 8192 + oB0, bP0 + dD); cp16(stb + 8192 + oB1, bP1 + dD);
        aP0 += 64; aP1 += 64; bP0 += 64; bP1 += 64;
        cp_commit();
    }

    for (int s = 0; s < NS; s++) {
        cp_wait<1>();
        __syncthreads();
        if (s + 2 < NS) {
            uint32_t stb = sb + (uint32_t)((s + 2) % NBUF) * STG_BYTES;
            cp16(stb + oA0, aP0);           cp16(stb + oA1, aP1);
            cp16(stb + 8192 + oA0, aP0 + dH); cp16(stb + 8192 + oA1, aP1 + dH);
            cp16(stb + oB0, bP0);           cp16(stb + oB1, bP1);
            cp16(stb + 8192 + oB0, bP0 + dD); cp16(stb + 8192 + oB1, bP1 + dD);
            aP0 += 64; aP1 += 64; bP0 += 64; bP1 += 64;
        }
        cp_commit();

        uint32_t st = sb + (uint32_t)(s % NBUF) * STG_BYTES;
#pragma unroll
        for (int s2 = 0; s2 < 2; s2++) {
            uint32_t baseA = st + (uint32_t)w * 1024 + (uint32_t)s2 * 512 + (uint32_t)lane * 4;
            uint32_t ah[4], al[4];
#pragma unroll
            for (int p = 0; p < 4; p++) {
                ah[p] = lds32(baseA + p * 128);
                al[p] = lds32(baseA + 8192 + p * 128);
            }
#pragma unroll
            for (int g = 0; g < 16; g++) {
                uint32_t baseB = st + 16384u + (uint32_t)g * 512 + (uint32_t)s2 * 256 + (uint32_t)lane * 4;
                uint32_t bh0 = lds32(baseB);
                uint32_t bh1 = lds32(baseB + 128);
                uint32_t bl0 = lds32(baseB + 8192);
                uint32_t bl1 = lds32(baseB + 8192 + 128);
                mma_bf16(acc[g], ah, bh0, bh1);
                mma_bf16(acc[g], ah, bl0, bl1);
                mma_bf16(acc[g], al, bh0, bh1);
            }
        }
    }

    // epilogue: fp32 store to g_O
    int q = lane >> 2, t4 = lane & 3;
    int row0 = m0 + w * 16 + q;
    int row1 = row0 + 8;
#pragma unroll
    for (int g = 0; g < 16; g++) {
        int ni = n0 + g * 8 + t4 * 2;
        if (row0 < cnt) {
            float2 v; v.x = acc[g][0]; v.y = acc[g][1];
            *(float2*)&g_O[(size_t)(off + row0) * D_DIM + ni] = v;
        }
        if (row1 < cnt) {
            float2 v; v.x = acc[g][2]; v.y = acc[g][3];
            *(float2*)&g_O[(size_t)(off + row1) * D_DIM + ni] = v;
        }
    }
}

// ---------------- combine ----------------
__global__ void combine_kernel(float* __restrict__ out, int T) {
    int t = blockIdx.x;
    int d4 = blockIdx.y * blockDim.x + threadIdx.x;
    float w0 = g_topk_w[2 * t];
    float w1 = g_topk_w[2 * t + 1];
    int s0 = g_slot_of[2 * t];
    int s1 = g_slot_of[2 * t + 1];
    float4 a = ((const float4*)&g_O[(size_t)s0 * D_DIM])[d4];
    float4 b = ((const float4*)&g_O[(size_t)s1 * D_DIM])[d4];
    float4 r;
    r.x = w0 * a.x + w1 * b.x;
    r.y = w0 * a.y + w1 * b.y;
    r.z = w0 * a.z + w1 * b.z;
    r.w = w0 * a.w + w1 * b.w;
    ((float4*)out)[(size_t)t * (D_DIM / 4) + d4] = r;
}

// ---------------- launch ----------------
extern "C" void kernel_launch(void* const* d_in, const int* in_sizes, int n_in,
                              void* d_out, int out_size) {
    const float* x  = (const float*)d_in[0];
    const float* wr = (const float*)d_in[1];
    const float* wg = (const float*)d_in[2];
    const float* wu = (const float*)d_in[3];
    const float* wd = (const float*)d_in[4];
    int T = in_sizes[0] / D_DIM;  // 2048

    static int configured = 0;
    if (!configured) {
        cudaFuncSetAttribute(gemm1_mma, cudaFuncAttributeMaxDynamicSharedMemorySize, SMEM_TOTAL);
        cudaFuncSetAttribute(gemm2_mma, cudaFuncAttributeMaxDynamicSharedMemorySize, SMEM_TOTAL);
        configured = 1;
    }

    reset_kernel<<<1, 32>>>();

    int n4x = T * D_DIM / 4;
    int n4w = E_NUM * F_DIM * D_DIM / 4;
    convert_kernel<<<(n4x + 255) / 256, 256>>>(x, 0, n4x);
    convert_kernel<<<(n4w + 255) / 256, 256>>>(wg, 1, n4w);
    convert_kernel<<<(n4w + 255) / 256, 256>>>(wu, 2, n4w);
    convert_kernel<<<(n4w + 255) / 256, 256>>>(wd, 3, n4w);

    router_kernel<<<(T + 7) / 8, 256>>>(x, wr, T);
    offsets_kernel<<<1, 1>>>();
    assign_kernel<<<(2 * T + 255) / 256, 256>>>(T);

    dim3 g1(F_DIM / 64, (2 * T) / 128, E_NUM);      // (12, 32, 8); y covers worst case
    g1.y = 16;                                      // per-expert slots <= 2048 -> 16 m-tiles
    gemm1_mma<<<g1, 256, SMEM_TOTAL>>>();

    dim3 g2(D_DIM / 128, 16, E_NUM);
    gemm2_mma<<<g2, 256, SMEM_TOTAL>>>();

    combine_kernel<<<dim3(T, 2), 256>>>((float*)d_out, T);
}

// round 4
// speedup vs baseline: 1.5615x; 1.0203x over previous
#include <cuda_runtime.h>
#include <cuda_bf16.h>
#include <cstdint>

#define D_DIM 2048
#define E_NUM 8
#define F_DIM 768
#define T_MAX 2048
#define SLOTS 4096

#define KT 32
#define NBUF 3
#define STG_BYTES 32768
#define SMEM_TOTAL (NBUF * STG_BYTES)

// ---------------- static device scratch ----------------
__device__ int   g_cnt[E_NUM];
__device__ int   g_cursor[E_NUM];
__device__ int   g_off[E_NUM + 1];
__device__ int   g_topk_idx[SLOTS];
__device__ float g_topk_w[SLOTS];
__device__ int   g_tok_of_slot[SLOTS];
__device__ int   g_slot_of[SLOTS];

__device__ __nv_bfloat16 g_xhi[T_MAX * D_DIM];
__device__ __nv_bfloat16 g_xlo[T_MAX * D_DIM];
__device__ __nv_bfloat16 g_wghi[E_NUM * F_DIM * D_DIM];
__device__ __nv_bfloat16 g_wglo[E_NUM * F_DIM * D_DIM];
__device__ __nv_bfloat16 g_wuhi[E_NUM * F_DIM * D_DIM];
__device__ __nv_bfloat16 g_wulo[E_NUM * F_DIM * D_DIM];
__device__ __nv_bfloat16 g_wdhi[E_NUM * D_DIM * F_DIM];
__device__ __nv_bfloat16 g_wdlo[E_NUM * D_DIM * F_DIM];
__device__ __nv_bfloat16 g_Hhi[(size_t)SLOTS * F_DIM];
__device__ __nv_bfloat16 g_Hlo[(size_t)SLOTS * F_DIM];
__device__ float g_O[(size_t)SLOTS * D_DIM];

// ---------------- helpers ----------------
__device__ __forceinline__ uint32_t smem_u32(const void* p) {
    uint32_t a;
    asm("{ .reg .u64 t; cvta.to.shared.u64 t, %1; cvt.u32.u64 %0, t; }" : "=r"(a) : "l"(p));
    return a;
}
__device__ __forceinline__ void ldsm4(uint32_t* r, uint32_t addr) {
    asm volatile("ldmatrix.sync.aligned.m8n8.x4.shared.b16 {%0,%1,%2,%3}, [%4];"
        : "=r"(r[0]), "=r"(r[1]), "=r"(r[2]), "=r"(r[3]) : "r"(addr));
}
__device__ __forceinline__ void cp16(uint32_t dst, const void* src) {
    asm volatile("cp.async.cg.shared.global [%0], [%1], 16;" :: "r"(dst), "l"(src) : "memory");
}
__device__ __forceinline__ void cp_commit() { asm volatile("cp.async.commit_group;" ::: "memory"); }
template <int N>
__device__ __forceinline__ void cp_wait() { asm volatile("cp.async.wait_group %0;" :: "n"(N) : "memory"); }

__device__ __forceinline__ void mma_bf16(float* c, const uint32_t* a, uint32_t b0, uint32_t b1) {
    asm volatile(
        "mma.sync.aligned.m16n8k16.row.col.f32.bf16.bf16.f32 "
        "{%0,%1,%2,%3}, {%4,%5,%6,%7}, {%8,%9}, {%0,%1,%2,%3};"
        : "+f"(c[0]), "+f"(c[1]), "+f"(c[2]), "+f"(c[3])
        : "r"(a[0]), "r"(a[1]), "r"(a[2]), "r"(a[3]), "r"(b0), "r"(b1));
}

// fragment-order smem offsets (per 16B chunk of row r, chunk-col c in [0,4))
__device__ __forceinline__ uint32_t aoff(int m, int c) {
    return (uint32_t)((m >> 4) * 1024 + (c >> 1) * 512 +
                      (((c & 1) << 1) + ((m >> 3) & 1)) * 128 + (m & 7) * 16);
}
__device__ __forceinline__ uint32_t boff(int n, int c) {
    return (uint32_t)((n >> 3) * 512 + (c >> 1) * 256 + (c & 1) * 128 + (n & 7) * 16);
}

// ---------------- small kernels ----------------
__global__ void reset_kernel() {
    if (threadIdx.x < E_NUM) g_cnt[threadIdx.x] = 0;
}

__global__ void convert_kernel(const float* __restrict__ src, int which, int n4) {
    int i = blockIdx.x * 256 + threadIdx.x;
    if (i >= n4) return;
    __nv_bfloat16 *hi, *lo;
    switch (which) {
        case 0: hi = g_xhi;  lo = g_xlo;  break;
        case 1: hi = g_wghi; lo = g_wglo; break;
        case 2: hi = g_wuhi; lo = g_wulo; break;
        default: hi = g_wdhi; lo = g_wdlo; break;
    }
    float4 v = ((const float4*)src)[i];
    __nv_bfloat162 h01, h23, l01, l23;
    h01.x = __float2bfloat16_rn(v.x); l01.x = __float2bfloat16_rn(v.x - __bfloat162float(h01.x));
    h01.y = __float2bfloat16_rn(v.y); l01.y = __float2bfloat16_rn(v.y - __bfloat162float(h01.y));
    h23.x = __float2bfloat16_rn(v.z); l23.x = __float2bfloat16_rn(v.z - __bfloat162float(h23.x));
    h23.y = __float2bfloat16_rn(v.w); l23.y = __float2bfloat16_rn(v.w - __bfloat162float(h23.y));
    ((__nv_bfloat162*)hi)[2 * i]     = h01;
    ((__nv_bfloat162*)hi)[2 * i + 1] = h23;
    ((__nv_bfloat162*)lo)[2 * i]     = l01;
    ((__nv_bfloat162*)lo)[2 * i + 1] = l23;
}

__global__ void router_kernel(const float* __restrict__ x,
                              const float* __restrict__ wr, int T) {
    int warp = threadIdx.x >> 5;
    int lane = threadIdx.x & 31;
    int t = blockIdx.x * 8 + warp;
    if (t >= T) return;

    const float4* x4 = (const float4*)(x + (size_t)t * D_DIM);
    const float4* w4 = (const float4*)wr;
    float acc[E_NUM];
#pragma unroll
    for (int e = 0; e < E_NUM; e++) acc[e] = 0.f;
    for (int d4 = lane; d4 < D_DIM / 4; d4 += 32) {
        float4 xv = x4[d4];
#pragma unroll
        for (int e = 0; e < E_NUM; e++) {
            float4 wv = w4[e * (D_DIM / 4) + d4];
            acc[e] += xv.x * wv.x + xv.y * wv.y + xv.z * wv.z + xv.w * wv.w;
        }
    }
#pragma unroll
    for (int e = 0; e < E_NUM; e++) {
#pragma unroll
        for (int o = 16; o > 0; o >>= 1)
            acc[e] += __shfl_xor_sync(0xffffffffu, acc[e], o);
    }
    if (lane == 0) {
        float s0 = -1e30f, s1 = -1e30f;
        int i0 = 0, i1 = 0;
#pragma unroll
        for (int e = 0; e < E_NUM; e++) {
            float v = acc[e];
            if (v > s0) { s1 = s0; i1 = i0; s0 = v; i0 = e; }
            else if (v > s1) { s1 = v; i1 = e; }
        }
        float p1 = expf(s1 - s0);
        float inv = 1.f / (1.f + p1);
        g_topk_idx[2 * t] = i0;
        g_topk_idx[2 * t + 1] = i1;
        g_topk_w[2 * t] = inv;
        g_topk_w[2 * t + 1] = p1 * inv;
        atomicAdd(&g_cnt[i0], 1);
        atomicAdd(&g_cnt[i1], 1);
    }
}

__global__ void offsets_kernel() {
    if (threadIdx.x == 0) {
        int o = 0;
        for (int e = 0; e < E_NUM; e++) {
            g_off[e] = o;
            o += g_cnt[e];
            g_cursor[e] = 0;
        }
        g_off[E_NUM] = o;
    }
}

__global__ void assign_kernel(int T) {
    int i = blockIdx.x * 256 + threadIdx.x;
    if (i >= 2 * T) return;
    int e = g_topk_idx[i];
    int pos = atomicAdd(&g_cursor[e], 1);
    int slot = g_off[e] + pos;
    g_tok_of_slot[slot] = i >> 1;
    g_slot_of[i] = slot;
}

// ---- shared mainloop compute for one K-stage buffer (term-major, ldmatrix) ----
__device__ __forceinline__ void stage_mma(uint32_t st, int w, uint32_t aLaneOff,
                                          uint32_t bLaneOff, float acc[16][4]) {
#pragma unroll
    for (int s2 = 0; s2 < 2; s2++) {
        uint32_t aA = st + (uint32_t)w * 1024 + (uint32_t)s2 * 512 + aLaneOff;
        uint32_t ah[4], al[4];
        ldsm4(ah, aA);
        ldsm4(al, aA + 8192);
#pragma unroll
        for (int h = 0; h < 2; h++) {
            uint32_t bh[16], bl[16];
            uint32_t bBase = st + 16384u + (uint32_t)(h * 8) * 512 + (uint32_t)s2 * 256 + bLaneOff;
#pragma unroll
            for (int gg = 0; gg < 4; gg++) ldsm4(&bh[gg * 4], bBase + gg * 1024);
#pragma unroll
            for (int g = 0; g < 8; g++) mma_bf16(acc[h * 8 + g], ah, bh[2 * g], bh[2 * g + 1]);
#pragma unroll
            for (int gg = 0; gg < 4; gg++) ldsm4(&bl[gg * 4], bBase + 8192 + gg * 1024);
#pragma unroll
            for (int g = 0; g < 8; g++) mma_bf16(acc[h * 8 + g], al, bh[2 * g], bh[2 * g + 1]);
#pragma unroll
            for (int g = 0; g < 8; g++) mma_bf16(acc[h * 8 + g], ah, bl[2 * g], bl[2 * g + 1]);
        }
    }
}

// ================= GEMM1: H = SwiGLU(X Wg^T, X Wu^T) =================
__global__ __launch_bounds__(256, 1) void gemm1_mma() {
    int e = blockIdx.z;
    int cnt = g_cnt[e];
    int m0 = blockIdx.y * 128;
    if (m0 >= cnt) return;
    int off = g_off[e];
    int f0 = blockIdx.x * 64;

    extern __shared__ __align__(16) char smem[];
    uint32_t sb = smem_u32(smem);
    int tid = threadIdx.x, w = tid >> 5, lane = tid & 31;
    uint32_t aLaneOff = (uint32_t)((lane >> 3) * 128 + (lane & 7) * 16);
    uint32_t bLaneOff = (uint32_t)((lane >> 4) * 512 + ((lane >> 3) & 1) * 128 + (lane & 7) * 16);

    int rA = tid >> 2, cA = tid & 3;
    int mA0 = m0 + rA;      if (mA0 >= cnt) mA0 = cnt - 1;
    int mA1 = m0 + rA + 64; if (mA1 >= cnt) mA1 = cnt - 1;
    const char* aP0 = (const char*)(g_xhi + (size_t)g_tok_of_slot[off + mA0] * D_DIM + cA * 8);
    const char* aP1 = (const char*)(g_xhi + (size_t)g_tok_of_slot[off + mA1] * D_DIM + cA * 8);
    const char* bP0 = (const char*)(g_wghi + ((size_t)e * F_DIM + f0 + rA) * D_DIM + cA * 8);
    const char* bP1 = (const char*)(g_wuhi + ((size_t)e * F_DIM + f0 + rA) * D_DIM + cA * 8);
    const ptrdiff_t dX = (const char*)g_xlo - (const char*)g_xhi;
    const ptrdiff_t dG = (const char*)g_wglo - (const char*)g_wghi;
    const ptrdiff_t dU = (const char*)g_wulo - (const char*)g_wuhi;
    uint32_t oA0 = aoff(rA, cA), oA1 = aoff(rA + 64, cA);
    uint32_t oB0 = 16384u + boff(rA, cA), oB1 = 16384u + boff(rA + 64, cA);

    float acc[16][4];
#pragma unroll
    for (int g = 0; g < 16; g++)
#pragma unroll
        for (int i = 0; i < 4; i++) acc[g][i] = 0.f;

    const int NS = D_DIM / KT;  // 64

#pragma unroll
    for (int s = 0; s < 2; s++) {
        uint32_t stb = sb + (uint32_t)s * STG_BYTES;
        cp16(stb + oA0, aP0);             cp16(stb + oA1, aP1);
        cp16(stb + 8192 + oA0, aP0 + dX); cp16(stb + 8192 + oA1, aP1 + dX);
        cp16(stb + oB0, bP0);             cp16(stb + oB1, bP1);
        cp16(stb + 8192 + oB0, bP0 + dG); cp16(stb + 8192 + oB1, bP1 + dU);
        aP0 += 64; aP1 += 64; bP0 += 64; bP1 += 64;
        cp_commit();
    }

    for (int s = 0; s < NS; s++) {
        cp_wait<1>();
        __syncthreads();
        if (s + 2 < NS) {
            uint32_t stb = sb + (uint32_t)((s + 2) % NBUF) * STG_BYTES;
            cp16(stb + oA0, aP0);             cp16(stb + oA1, aP1);
            cp16(stb + 8192 + oA0, aP0 + dX); cp16(stb + 8192 + oA1, aP1 + dX);
            cp16(stb + oB0, bP0);             cp16(stb + oB1, bP1);
            cp16(stb + 8192 + oB0, bP0 + dG); cp16(stb + 8192 + oB1, bP1 + dU);
            aP0 += 64; aP1 += 64; bP0 += 64; bP1 += 64;
        }
        cp_commit();

        stage_mma(sb + (uint32_t)(s % NBUF) * STG_BYTES, w, aLaneOff, bLaneOff, acc);
    }

    // epilogue: SwiGLU + bf16 hi/lo split
    int q = lane >> 2, t4 = lane & 3;
    int row0 = m0 + w * 16 + q;
    int row1 = row0 + 8;
#pragma unroll
    for (int g = 0; g < 8; g++) {
        int fi = f0 + g * 8 + t4 * 2;
        if (row0 < cnt) {
            float g0 = acc[g][0], g1 = acc[g][1];
            float u0 = acc[g + 8][0], u1 = acc[g + 8][1];
            float h0 = g0 / (1.f + __expf(-g0)) * u0;
            float h1 = g1 / (1.f + __expf(-g1)) * u1;
            __nv_bfloat162 hh, hl;
            hh.x = __float2bfloat16_rn(h0); hl.x = __float2bfloat16_rn(h0 - __bfloat162float(hh.x));
            hh.y = __float2bfloat16_rn(h1); hl.y = __float2bfloat16_rn(h1 - __bfloat162float(hh.y));
            *(__nv_bfloat162*)&g_Hhi[(size_t)(off + row0) * F_DIM + fi] = hh;
            *(__nv_bfloat162*)&g_Hlo[(size_t)(off + row0) * F_DIM + fi] = hl;
        }
        if (row1 < cnt) {
            float g0 = acc[g][2], g1 = acc[g][3];
            float u0 = acc[g + 8][2], u1 = acc[g + 8][3];
            float h0 = g0 / (1.f + __expf(-g0)) * u0;
            float h1 = g1 / (1.f + __expf(-g1)) * u1;
            __nv_bfloat162 hh, hl;
            hh.x = __float2bfloat16_rn(h0); hl.x = __float2bfloat16_rn(h0 - __bfloat162float(hh.x));
            hh.y = __float2bfloat16_rn(h1); hl.y = __float2bfloat16_rn(h1 - __bfloat162float(hh.y));
            *(__nv_bfloat162*)&g_Hhi[(size_t)(off + row1) * F_DIM + fi] = hh;
            *(__nv_bfloat162*)&g_Hlo[(size_t)(off + row1) * F_DIM + fi] = hl;
        }
    }
}

// ================= GEMM2: O = H Wd^T =================
__global__ __launch_bounds__(256, 1) void gemm2_mma() {
    int e = blockIdx.z;
    int cnt = g_cnt[e];
    int m0 = blockIdx.y * 128;
    if (m0 >= cnt) return;
    int off = g_off[e];
    int n0 = blockIdx.x * 128;

    extern __shared__ __align__(16) char smem[];
    uint32_t sb = smem_u32(smem);
    int tid = threadIdx.x, w = tid >> 5, lane = tid & 31;
    uint32_t aLaneOff = (uint32_t)((lane >> 3) * 128 + (lane & 7) * 16);
    uint32_t bLaneOff = (uint32_t)((lane >> 4) * 512 + ((lane >> 3) & 1) * 128 + (lane & 7) * 16);

    int rA = tid >> 2, cA = tid & 3;
    int mA0 = m0 + rA;      if (mA0 >= cnt) mA0 = cnt - 1;
    int mA1 = m0 + rA + 64; if (mA1 >= cnt) mA1 = cnt - 1;
    const char* aP0 = (const char*)(g_Hhi + (size_t)(off + mA0) * F_DIM + cA * 8);
    const char* aP1 = (const char*)(g_Hhi + (size_t)(off + mA1) * F_DIM + cA * 8);
    const char* bP0 = (const char*)(g_wdhi + ((size_t)e * D_DIM + n0 + rA) * F_DIM + cA * 8);
    const char* bP1 = (const char*)(g_wdhi + ((size_t)e * D_DIM + n0 + rA + 64) * F_DIM + cA * 8);
    const ptrdiff_t dH = (const char*)g_Hlo - (const char*)g_Hhi;
    const ptrdiff_t dD = (const char*)g_wdlo - (const char*)g_wdhi;
    uint32_t oA0 = aoff(rA, cA), oA1 = aoff(rA + 64, cA);
    uint32_t oB0 = 16384u + boff(rA, cA), oB1 = 16384u + boff(rA + 64, cA);

    float acc[16][4];
#pragma unroll
    for (int g = 0; g < 16; g++)
#pragma unroll
        for (int i = 0; i < 4; i++) acc[g][i] = 0.f;

    const int NS = F_DIM / KT;  // 24

#pragma unroll
    for (int s = 0; s < 2; s++) {
        uint32_t stb = sb + (uint32_t)s * STG_BYTES;
        cp16(stb + oA0, aP0);             cp16(stb + oA1, aP1);
        cp16(stb + 8192 + oA0, aP0 + dH); cp16(stb + 8192 + oA1, aP1 + dH);
        cp16(stb + oB0, bP0);             cp16(stb + oB1, bP1);
        cp16(stb + 8192 + oB0, bP0 + dD); cp16(stb + 8192 + oB1, bP1 + dD);
        aP0 += 64; aP1 += 64; bP0 += 64; bP1 += 64;
        cp_commit();
    }

    for (int s = 0; s < NS; s++) {
        cp_wait<1>();
        __syncthreads();
        if (s + 2 < NS) {
            uint32_t stb = sb + (uint32_t)((s + 2) % NBUF) * STG_BYTES;
            cp16(stb + oA0, aP0);             cp16(stb + oA1, aP1);
            cp16(stb + 8192 + oA0, aP0 + dH); cp16(stb + 8192 + oA1, aP1 + dH);
            cp16(stb + oB0, bP0);             cp16(stb + oB1, bP1);
            cp16(stb + 8192 + oB0, bP0 + dD); cp16(stb + 8192 + oB1, bP1 + dD);
            aP0 += 64; aP1 += 64; bP0 += 64; bP1 += 64;
        }
        cp_commit();

        stage_mma(sb + (uint32_t)(s % NBUF) * STG_BYTES, w, aLaneOff, bLaneOff, acc);
    }

    // epilogue: fp32 store to g_O
    int q = lane >> 2, t4 = lane & 3;
    int row0 = m0 + w * 16 + q;
    int row1 = row0 + 8;
#pragma unroll
    for (int g = 0; g < 16; g++) {
        int ni = n0 + g * 8 + t4 * 2;
        if (row0 < cnt) {
            float2 v; v.x = acc[g][0]; v.y = acc[g][1];
            *(float2*)&g_O[(size_t)(off + row0) * D_DIM + ni] = v;
        }
        if (row1 < cnt) {
            float2 v; v.x = acc[g][2]; v.y = acc[g][3];
            *(float2*)&g_O[(size_t)(off + row1) * D_DIM + ni] = v;
        }
    }
}

// ---------------- combine ----------------
__global__ void combine_kernel(float* __restrict__ out, int T) {
    int t = blockIdx.x;
    int d4 = blockIdx.y * blockDim.x + threadIdx.x;
    float w0 = g_topk_w[2 * t];
    float w1 = g_topk_w[2 * t + 1];
    int s0 = g_slot_of[2 * t];
    int s1 = g_slot_of[2 * t + 1];
    float4 a = ((const float4*)&g_O[(size_t)s0 * D_DIM])[d4];
    float4 b = ((const float4*)&g_O[(size_t)s1 * D_DIM])[d4];
    float4 r;
    r.x = w0 * a.x + w1 * b.x;
    r.y = w0 * a.y + w1 * b.y;
    r.z = w0 * a.z + w1 * b.z;
    r.w = w0 * a.w + w1 * b.w;
    ((float4*)out)[(size_t)t * (D_DIM / 4) + d4] = r;
}

// ---------------- launch ----------------
extern "C" void kernel_launch(void* const* d_in, const int* in_sizes, int n_in,
                              void* d_out, int out_size) {
    const float* x  = (const float*)d_in[0];
    const float* wr = (const float*)d_in[1];
    const float* wg = (const float*)d_in[2];
    const float* wu = (const float*)d_in[3];
    const float* wd = (const float*)d_in[4];
    int T = in_sizes[0] / D_DIM;  // 2048

    cudaFuncSetAttribute(gemm1_mma, cudaFuncAttributeMaxDynamicSharedMemorySize, SMEM_TOTAL);
    cudaFuncSetAttribute(gemm2_mma, cudaFuncAttributeMaxDynamicSharedMemorySize, SMEM_TOTAL);

    reset_kernel<<<1, 32>>>();

    int n4x = T * D_DIM / 4;
    int n4w = E_NUM * F_DIM * D_DIM / 4;
    convert_kernel<<<(n4x + 255) / 256, 256>>>(x, 0, n4x);
    convert_kernel<<<(n4w + 255) / 256, 256>>>(wg, 1, n4w);
    convert_kernel<<<(n4w + 255) / 256, 256>>>(wu, 2, n4w);
    convert_kernel<<<(n4w + 255) / 256, 256>>>(wd, 3, n4w);

    router_kernel<<<(T + 7) / 8, 256>>>(x, wr, T);
    offsets_kernel<<<1, 1>>>();
    assign_kernel<<<(2 * T + 255) / 256, 256>>>(T);

    dim3 g1(F_DIM / 64, 16, E_NUM);
    gemm1_mma<<<g1, 256, SMEM_TOTAL>>>();

    dim3 g2(D_DIM / 128, 16, E_NUM);
    gemm2_mma<<<g2, 256, SMEM_TOTAL>>>();

    combine_kernel<<<dim3(T, 2), 256>>>((float*)d_out, T);
}

// round 5
// speedup vs baseline: 2.1590x; 1.3827x over previous
#include <cuda_runtime.h>
#include <cuda_bf16.h>
#include <cstdint>

#define D_DIM 2048
#define E_NUM 8
#define F_DIM 768
#define T_MAX 2048
#define SLOTS 4096

#define KT 64
#define ROW_STRIDE 272
#define B_REG 34816            // 128 * 272
#define STG_BYTES 69632        // 2 * 34816
#define STAGE_TX 65536         // 256 rows * 256B
#define SMEM_TOTAL (1024 + 2 * STG_BYTES)

// ---------------- static device scratch ----------------
__device__ int   g_cnt[E_NUM];
__device__ int   g_cursor[E_NUM];
__device__ int   g_off[E_NUM + 1];
__device__ int   g_topk_idx[SLOTS];
__device__ float g_topk_w[SLOTS];
__device__ int   g_tok_of_slot[SLOTS];
__device__ int   g_slot_of[SLOTS];

// interleaved hi/lo layout: row = [ks chunks][hi 64 | lo 64] bf16
__device__ __nv_bfloat16 g_xi[(size_t)T_MAX * 2 * D_DIM];
__device__ __nv_bfloat16 g_wgi[(size_t)E_NUM * F_DIM * 2 * D_DIM];
__device__ __nv_bfloat16 g_wui[(size_t)E_NUM * F_DIM * 2 * D_DIM];
__device__ __nv_bfloat16 g_wdi[(size_t)E_NUM * D_DIM * 2 * F_DIM];
__device__ __nv_bfloat16 g_Hi[(size_t)SLOTS * 2 * F_DIM];
__device__ float g_O[(size_t)SLOTS * D_DIM];

// ---------------- helpers ----------------
__device__ __forceinline__ uint32_t smem_u32(const void* p) {
    uint32_t a;
    asm("{ .reg .u64 t; cvta.to.shared.u64 t, %1; cvt.u32.u64 %0, t; }" : "=r"(a) : "l"(p));
    return a;
}
__device__ __forceinline__ void ldsm4(uint32_t* r, uint32_t addr) {
    asm volatile("ldmatrix.sync.aligned.m8n8.x4.shared.b16 {%0,%1,%2,%3}, [%4];"
        : "=r"(r[0]), "=r"(r[1]), "=r"(r[2]), "=r"(r[3]) : "r"(addr));
}
__device__ __forceinline__ void bulk_ld(uint32_t dst, const void* src, uint32_t bytes, uint32_t mbar) {
    asm volatile(
        "cp.async.bulk.shared::cluster.global.mbarrier::complete_tx::bytes [%0], [%1], %2, [%3];"
        :: "r"(dst), "l"(src), "r"(bytes), "r"(mbar) : "memory");
}
#define MBARRIER_INIT(addr, cnt) \
    asm volatile("mbarrier.init.shared.b64 [%0], %1;" :: "r"((uint32_t)(addr)), "r"((uint32_t)(cnt)) : "memory")
#define MBARRIER_EXPECT_TX(addr, bytes) \
    asm volatile("mbarrier.arrive.expect_tx.shared.b64 _, [%0], %1;" :: "r"((uint32_t)(addr)), "r"((uint32_t)(bytes)) : "memory")
#define MBARRIER_WAIT_PARITY(mbar_smem_addr, phase_parity) do { \
    uint32_t _mbar = (uint32_t)(mbar_smem_addr); \
    uint32_t _parity = (uint32_t)(phase_parity); \
    uint32_t _done; \
    asm volatile( \
        "{\n\t.reg .pred p;\n\t" \
        "mbarrier.try_wait.parity.acquire.cta.shared::cta.b64 p, [%1], %2;\n\t" \
        "selp.b32 %0, 1, 0, p;\n\t}" \
        : "=r"(_done) : "r"(_mbar), "r"(_parity) : "memory"); \
    if (!_done) { \
        asm volatile( \
            "{\n\t.reg .pred P1;\n\t" \
            "WAIT_LOOP_%=:\n\t" \
            "mbarrier.try_wait.parity.acquire.cta.shared::cta.b64 P1, [%0], %1, 0x989680;\n\t" \
            "@P1 bra.uni WAIT_DONE_%=;\n\t" \
            "bra.uni WAIT_LOOP_%=;\n\t" \
            "WAIT_DONE_%=:\n\t}" \
            :: "r"(_mbar), "r"(_parity) : "memory"); \
    } \
} while (0)

__device__ __forceinline__ void mma_bf16(float* c, const uint32_t* a, uint32_t b0, uint32_t b1) {
    asm volatile(
        "mma.sync.aligned.m16n8k16.row.col.f32.bf16.bf16.f32 "
        "{%0,%1,%2,%3}, {%4,%5,%6,%7}, {%8,%9}, {%0,%1,%2,%3};"
        : "+f"(c[0]), "+f"(c[1]), "+f"(c[2]), "+f"(c[3])
        : "r"(a[0]), "r"(a[1]), "r"(a[2]), "r"(a[3]), "r"(b0), "r"(b1));
}

// ---------------- small kernels ----------------
__global__ void reset_kernel() {
    if (threadIdx.x < E_NUM) g_cnt[threadIdx.x] = 0;
}

// fp32 [rows][rl] -> interleaved bf16 [rows][rl/64][hi64|lo64]
__global__ void convert_kernel(const float* __restrict__ src, int which, int rl4, int n4) {
    int i = blockIdx.x * 256 + threadIdx.x;
    if (i >= n4) return;
    __nv_bfloat16* dst;
    switch (which) {
        case 0: dst = g_xi;  break;
        case 1: dst = g_wgi; break;
        case 2: dst = g_wui; break;
        default: dst = g_wdi; break;
    }
    int row = i / rl4;
    int kk = (i - row * rl4) * 4;
    float4 v = ((const float4*)src)[i];
    __nv_bfloat162 h01, h23, l01, l23;
    h01.x = __float2bfloat16_rn(v.x); l01.x = __float2bfloat16_rn(v.x - __bfloat162float(h01.x));
    h01.y = __float2bfloat16_rn(v.y); l01.y = __float2bfloat16_rn(v.y - __bfloat162float(h01.y));
    h23.x = __float2bfloat16_rn(v.z); l23.x = __float2bfloat16_rn(v.z - __bfloat162float(h23.x));
    h23.y = __float2bfloat16_rn(v.w); l23.y = __float2bfloat16_rn(v.w - __bfloat162float(h23.y));
    size_t ob = (size_t)row * (size_t)(rl4 * 8) + (size_t)((kk >> 6) << 7) + (size_t)(kk & 63);
    *(__nv_bfloat162*)&dst[ob]          = h01;
    *(__nv_bfloat162*)&dst[ob + 2]      = h23;
    *(__nv_bfloat162*)&dst[ob + 64]     = l01;
    *(__nv_bfloat162*)&dst[ob + 64 + 2] = l23;
}

__global__ void router_kernel(const float* __restrict__ x,
                              const float* __restrict__ wr, int T) {
    int warp = threadIdx.x >> 5;
    int lane = threadIdx.x & 31;
    int t = blockIdx.x * 8 + warp;
    if (t >= T) return;

    const float4* x4 = (const float4*)(x + (size_t)t * D_DIM);
    const float4* w4 = (const float4*)wr;
    float acc[E_NUM];
#pragma unroll
    for (int e = 0; e < E_NUM; e++) acc[e] = 0.f;
    for (int d4 = lane; d4 < D_DIM / 4; d4 += 32) {
        float4 xv = x4[d4];
#pragma unroll
        for (int e = 0; e < E_NUM; e++) {
            float4 wv = w4[e * (D_DIM / 4) + d4];
            acc[e] += xv.x * wv.x + xv.y * wv.y + xv.z * wv.z + xv.w * wv.w;
        }
    }
#pragma unroll
    for (int e = 0; e < E_NUM; e++) {
#pragma unroll
        for (int o = 16; o > 0; o >>= 1)
            acc[e] += __shfl_xor_sync(0xffffffffu, acc[e], o);
    }
    if (lane == 0) {
        float s0 = -1e30f, s1 = -1e30f;
        int i0 = 0, i1 = 0;
#pragma unroll
        for (int e = 0; e < E_NUM; e++) {
            float v = acc[e];
            if (v > s0) { s1 = s0; i1 = i0; s0 = v; i0 = e; }
            else if (v > s1) { s1 = v; i1 = e; }
        }
        float p1 = expf(s1 - s0);
        float inv = 1.f / (1.f + p1);
        g_topk_idx[2 * t] = i0;
        g_topk_idx[2 * t + 1] = i1;
        g_topk_w[2 * t] = inv;
        g_topk_w[2 * t + 1] = p1 * inv;
        atomicAdd(&g_cnt[i0], 1);
        atomicAdd(&g_cnt[i1], 1);
    }
}

__global__ void offsets_kernel() {
    if (threadIdx.x == 0) {
        int o = 0;
        for (int e = 0; e < E_NUM; e++) {
            g_off[e] = o;
            o += g_cnt[e];
            g_cursor[e] = 0;
        }
        g_off[E_NUM] = o;
    }
}

__global__ void assign_kernel(int T) {
    int i = blockIdx.x * 256 + threadIdx.x;
    if (i >= 2 * T) return;
    int e = g_topk_idx[i];
    int pos = atomicAdd(&g_cursor[e], 1);
    int slot = g_off[e] + pos;
    g_tok_of_slot[slot] = i >> 1;
    g_slot_of[i] = slot;
}

// ---- mainloop compute for one K-stage (KT=64), 8 warps, 128x128 tile ----
__device__ __forceinline__ void stage_mma(uint32_t stg, int w, int lane, float acc[16][4]) {
    uint32_t aBase = stg + (uint32_t)(w * 16 + (lane & 7) + ((lane >> 3) & 1) * 8) * ROW_STRIDE
                     + (uint32_t)((lane >> 4) * 16);
    uint32_t bBase = stg + B_REG + (uint32_t)((lane & 7) + ((lane >> 4) & 1) * 8) * ROW_STRIDE
                     + (uint32_t)(((lane >> 3) & 1) * 16);
#pragma unroll
    for (int ks = 0; ks < 4; ks++) {
        uint32_t ka = (uint32_t)(ks * 32);
        uint32_t ah[4], al[4];
        ldsm4(ah, aBase + ka);
        ldsm4(al, aBase + ka + 128);
        uint32_t bh[32], bl[32];
#pragma unroll
        for (int g2 = 0; g2 < 8; g2++)
            ldsm4(&bh[g2 * 4], bBase + (uint32_t)g2 * (16 * ROW_STRIDE) + ka);
#pragma unroll
        for (int g2 = 0; g2 < 8; g2++) {
            mma_bf16(acc[g2 * 2 + 0], ah, bh[g2 * 4 + 0], bh[g2 * 4 + 1]);
            mma_bf16(acc[g2 * 2 + 1], ah, bh[g2 * 4 + 2], bh[g2 * 4 + 3]);
        }
#pragma unroll
        for (int g2 = 0; g2 < 8; g2++)
            ldsm4(&bl[g2 * 4], bBase + (uint32_t)g2 * (16 * ROW_STRIDE) + ka + 128);
#pragma unroll
        for (int g2 = 0; g2 < 8; g2++) {
            mma_bf16(acc[g2 * 2 + 0], al, bh[g2 * 4 + 0], bh[g2 * 4 + 1]);
            mma_bf16(acc[g2 * 2 + 1], al, bh[g2 * 4 + 2], bh[g2 * 4 + 3]);
        }
#pragma unroll
        for (int g2 = 0; g2 < 8; g2++) {
            mma_bf16(acc[g2 * 2 + 0], ah, bl[g2 * 4 + 0], bl[g2 * 4 + 1]);
            mma_bf16(acc[g2 * 2 + 1], ah, bl[g2 * 4 + 2], bl[g2 * 4 + 3]);
        }
    }
}

// ================= GEMM1: H = SwiGLU(X Wg^T, X Wu^T) =================
__global__ __launch_bounds__(256, 1) void gemm1_mma() {
    int e = blockIdx.z;
    int cnt = g_cnt[e];
    int m0 = blockIdx.y * 128;
    if (m0 >= cnt) return;
    int off = g_off[e];
    int f0 = blockIdx.x * 64;

    extern __shared__ __align__(16) char smem[];
    uint32_t sb = smem_u32(smem);
    int tid = threadIdx.x, w = tid >> 5, lane = tid & 31;

    // per-thread bulk source row (A: rows 0..127, B: rows 0..127 -> gate/up)
    const char* src;
    uint32_t dstOff;
    if (tid < 128) {
        int m = m0 + tid; if (m >= cnt) m = cnt - 1;
        src = (const char*)(g_xi + (size_t)g_tok_of_slot[off + m] * (2 * D_DIM));
        dstOff = 1024u + (uint32_t)tid * ROW_STRIDE;
    } else {
        int r = tid - 128;
        if (r < 64)
            src = (const char*)(g_wgi + ((size_t)e * F_DIM + f0 + r) * (2 * D_DIM));
        else
            src = (const char*)(g_wui + ((size_t)e * F_DIM + f0 + (r - 64)) * (2 * D_DIM));
        dstOff = 1024u + B_REG + (uint32_t)r * ROW_STRIDE;
    }

    if (tid == 0) { MBARRIER_INIT(sb + 0, 1); MBARRIER_INIT(sb + 16, 1); }
    __syncthreads();

    const int NS = D_DIM / KT;  // 32
    // prologue stages 0,1
#pragma unroll
    for (int s = 0; s < 2; s++) {
        if (tid == 0) MBARRIER_EXPECT_TX(sb + s * 16, STAGE_TX);
        bulk_ld(sb + dstOff + (uint32_t)s * STG_BYTES, src + s * 256, 256u, sb + s * 16);
    }

    float acc[16][4];
#pragma unroll
    for (int g = 0; g < 16; g++)
#pragma unroll
        for (int i = 0; i < 4; i++) acc[g][i] = 0.f;

    for (int s = 0; s < NS; s++) {
        MBARRIER_WAIT_PARITY(sb + (s & 1) * 16, (s >> 1) & 1);
        stage_mma(sb + 1024 + (uint32_t)(s & 1) * STG_BYTES, w, lane, acc);
        __syncthreads();
        if (s + 2 < NS) {
            if (tid == 0) MBARRIER_EXPECT_TX(sb + (s & 1) * 16, STAGE_TX);
            bulk_ld(sb + dstOff + (uint32_t)(s & 1) * STG_BYTES, src + (s + 2) * 256, 256u,
                    sb + (s & 1) * 16);
        }
    }

    // epilogue: SwiGLU + interleaved bf16 hi/lo into g_Hi
    int q = lane >> 2, t4 = lane & 3;
    int row0 = m0 + w * 16 + q;
    int row1 = row0 + 8;
    int chunkBase = (f0 >> 6) << 7;   // (f0/64)*128
#pragma unroll
    for (int g = 0; g < 8; g++) {
        int inner = g * 8 + t4 * 2;
        if (row0 < cnt) {
            float g0 = acc[g][0], g1 = acc[g][1];
            float u0 = acc[g + 8][0], u1 = acc[g + 8][1];
            float h0 = g0 / (1.f + __expf(-g0)) * u0;
            float h1 = g1 / (1.f + __expf(-g1)) * u1;
            __nv_bfloat162 hh, hl;
            hh.x = __float2bfloat16_rn(h0); hl.x = __float2bfloat16_rn(h0 - __bfloat162float(hh.x));
            hh.y = __float2bfloat16_rn(h1); hl.y = __float2bfloat16_rn(h1 - __bfloat162float(hh.y));
            size_t ob = (size_t)(off + row0) * (2 * F_DIM) + chunkBase + inner;
            *(__nv_bfloat162*)&g_Hi[ob]      = hh;
            *(__nv_bfloat162*)&g_Hi[ob + 64] = hl;
        }
        if (row1 < cnt) {
            float g0 = acc[g][2], g1 = acc[g][3];
            float u0 = acc[g + 8][2], u1 = acc[g + 8][3];
            float h0 = g0 / (1.f + __expf(-g0)) * u0;
            float h1 = g1 / (1.f + __expf(-g1)) * u1;
            __nv_bfloat162 hh, hl;
            hh.x = __float2bfloat16_rn(h0); hl.x = __float2bfloat16_rn(h0 - __bfloat162float(hh.x));
            hh.y = __float2bfloat16_rn(h1); hl.y = __float2bfloat16_rn(h1 - __bfloat162float(hh.y));
            size_t ob = (size_t)(off + row1) * (2 * F_DIM) + chunkBase + inner;
            *(__nv_bfloat162*)&g_Hi[ob]      = hh;
            *(__nv_bfloat162*)&g_Hi[ob + 64] = hl;
        }
    }
}

// ================= GEMM2: O = H Wd^T =================
__global__ __launch_bounds__(256, 1) void gemm2_mma() {
    int e = blockIdx.z;
    int cnt = g_cnt[e];
    int m0 = blockIdx.y * 128;
    if (m0 >= cnt) return;
    int off = g_off[e];
    int n0 = blockIdx.x * 128;

    extern __shared__ __align__(16) char smem[];
    uint32_t sb = smem_u32(smem);
    int tid = threadIdx.x, w = tid >> 5, lane = tid & 31;

    const char* src;
    uint32_t dstOff;
    if (tid < 128) {
        int m = m0 + tid; if (m >= cnt) m = cnt - 1;
        src = (const char*)(g_Hi + (size_t)(off + m) * (2 * F_DIM));
        dstOff = 1024u + (uint32_t)tid * ROW_STRIDE;
    } else {
        int r = tid - 128;
        src = (const char*)(g_wdi + ((size_t)e * D_DIM + n0 + r) * (2 * F_DIM));
        dstOff = 1024u + B_REG + (uint32_t)r * ROW_STRIDE;
    }

    if (tid == 0) { MBARRIER_INIT(sb + 0, 1); MBARRIER_INIT(sb + 16, 1); }
    __syncthreads();

    const int NS = F_DIM / KT;  // 12
#pragma unroll
    for (int s = 0; s < 2; s++) {
        if (tid == 0) MBARRIER_EXPECT_TX(sb + s * 16, STAGE_TX);
        bulk_ld(sb + dstOff + (uint32_t)s * STG_BYTES, src + s * 256, 256u, sb + s * 16);
    }

    float acc[16][4];
#pragma unroll
    for (int g = 0; g < 16; g++)
#pragma unroll
        for (int i = 0; i < 4; i++) acc[g][i] = 0.f;

    for (int s = 0; s < NS; s++) {
        MBARRIER_WAIT_PARITY(sb + (s & 1) * 16, (s >> 1) & 1);
        stage_mma(sb + 1024 + (uint32_t)(s & 1) * STG_BYTES, w, lane, acc);
        __syncthreads();
        if (s + 2 < NS) {
            if (tid == 0) MBARRIER_EXPECT_TX(sb + (s & 1) * 16, STAGE_TX);
            bulk_ld(sb + dstOff + (uint32_t)(s & 1) * STG_BYTES, src + (s + 2) * 256, 256u,
                    sb + (s & 1) * 16);
        }
    }

    // epilogue: fp32 store to g_O
    int q = lane >> 2, t4 = lane & 3;
    int row0 = m0 + w * 16 + q;
    int row1 = row0 + 8;
#pragma unroll
    for (int g = 0; g < 16; g++) {
        int ni = n0 + g * 8 + t4 * 2;
        if (row0 < cnt) {
            float2 v; v.x = acc[g][0]; v.y = acc[g][1];
            *(float2*)&g_O[(size_t)(off + row0) * D_DIM + ni] = v;
        }
        if (row1 < cnt) {
            float2 v; v.x = acc[g][2]; v.y = acc[g][3];
            *(float2*)&g_O[(size_t)(off + row1) * D_DIM + ni] = v;
        }
    }
}

// ---------------- combine ----------------
__global__ void combine_kernel(float* __restrict__ out, int T) {
    int t = blockIdx.x;
    int d4 = blockIdx.y * blockDim.x + threadIdx.x;
    float w0 = g_topk_w[2 * t];
    float w1 = g_topk_w[2 * t + 1];
    int s0 = g_slot_of[2 * t];
    int s1 = g_slot_of[2 * t + 1];
    float4 a = ((const float4*)&g_O[(size_t)s0 * D_DIM])[d4];
    float4 b = ((const float4*)&g_O[(size_t)s1 * D_DIM])[d4];
    float4 r;
    r.x = w0 * a.x + w1 * b.x;
    r.y = w0 * a.y + w1 * b.y;
    r.z = w0 * a.z + w1 * b.z;
    r.w = w0 * a.w + w1 * b.w;
    ((float4*)out)[(size_t)t * (D_DIM / 4) + d4] = r;
}

// ---------------- launch ----------------
extern "C" void kernel_launch(void* const* d_in, const int* in_sizes, int n_in,
                              void* d_out, int out_size) {
    const float* x  = (const float*)d_in[0];
    const float* wr = (const float*)d_in[1];
    const float* wg = (const float*)d_in[2];
    const float* wu = (const float*)d_in[3];
    const float* wd = (const float*)d_in[4];
    int T = in_sizes[0] / D_DIM;  // 2048

    cudaFuncSetAttribute(gemm1_mma, cudaFuncAttributeMaxDynamicSharedMemorySize, SMEM_TOTAL);
    cudaFuncSetAttribute(gemm2_mma, cudaFuncAttributeMaxDynamicSharedMemorySize, SMEM_TOTAL);

    reset_kernel<<<1, 32>>>();

    int n4x = T * D_DIM / 4;
    int n4w = E_NUM * F_DIM * D_DIM / 4;
    convert_kernel<<<(n4x + 255) / 256, 256>>>(x, 0, D_DIM / 4, n4x);
    convert_kernel<<<(n4w + 255) / 256, 256>>>(wg, 1, D_DIM / 4, n4w);
    convert_kernel<<<(n4w + 255) / 256, 256>>>(wu, 2, D_DIM / 4, n4w);
    convert_kernel<<<(n4w + 255) / 256, 256>>>(wd, 3, F_DIM / 4, n4w);

    router_kernel<<<(T + 7) / 8, 256>>>(x, wr, T);
    offsets_kernel<<<1, 1>>>();
    assign_kernel<<<(2 * T + 255) / 256, 256>>>(T);

    dim3 g1(F_DIM / 64, 16, E_NUM);
    gemm1_mma<<<g1, 256, SMEM_TOTAL>>>();

    dim3 g2(D_DIM / 128, 16, E_NUM);
    gemm2_mma<<<g2, 256, SMEM_TOTAL>>>();

    combine_kernel<<<dim3(T, 2), 256>>>((float*)d_out, T);
}

// round 6
// speedup vs baseline: 2.1966x; 1.0174x over previous
#include <cuda_runtime.h>
#include <cuda_bf16.h>
#include <cstdint>

#define D_DIM 2048
#define E_NUM 8
#define F_DIM 768
#define T_MAX 2048
#define SLOTS 4096

#define KT 64
#define ROW_STRIDE 272
#define B_REG 34816            // 128 * 272
#define STG_BYTES 69632        // 2 * 34816
#define STAGE_TX 65536         // 256 rows * 256B
#define NSTG 3
#define SMEM_TOTAL (1024 + NSTG * STG_BYTES)

// ---------------- static device scratch ----------------
__device__ int   g_cnt[E_NUM];
__device__ int   g_cursor[E_NUM];
__device__ int   g_off[E_NUM + 1];
__device__ int   g_topk_idx[SLOTS];
__device__ float g_topk_w[SLOTS];
__device__ int   g_tok_of_slot[SLOTS];
__device__ int   g_slot_of[SLOTS];

// interleaved hi/lo layout: row = [ks chunks of 64][hi 64 | lo 64] bf16
__device__ __nv_bfloat16 g_xi[(size_t)T_MAX * 2 * D_DIM];
__device__ __nv_bfloat16 g_wgi[(size_t)E_NUM * F_DIM * 2 * D_DIM];
__device__ __nv_bfloat16 g_wui[(size_t)E_NUM * F_DIM * 2 * D_DIM];
__device__ __nv_bfloat16 g_wdi[(size_t)E_NUM * D_DIM * 2 * F_DIM];
__device__ __nv_bfloat16 g_Hi[(size_t)SLOTS * 2 * F_DIM];
__device__ float g_O[(size_t)SLOTS * D_DIM];

// ---------------- helpers ----------------
__device__ __forceinline__ uint32_t smem_u32(const void* p) {
    uint32_t a;
    asm("{ .reg .u64 t; cvta.to.shared.u64 t, %1; cvt.u32.u64 %0, t; }" : "=r"(a) : "l"(p));
    return a;
}
__device__ __forceinline__ void ldsm4(uint32_t* r, uint32_t addr) {
    asm volatile("ldmatrix.sync.aligned.m8n8.x4.shared.b16 {%0,%1,%2,%3}, [%4];"
        : "=r"(r[0]), "=r"(r[1]), "=r"(r[2]), "=r"(r[3]) : "r"(addr));
}
__device__ __forceinline__ void bulk_ld(uint32_t dst, const void* src, uint32_t bytes, uint32_t mbar) {
    asm volatile(
        "cp.async.bulk.shared::cluster.global.mbarrier::complete_tx::bytes [%0], [%1], %2, [%3];"
        :: "r"(dst), "l"(src), "r"(bytes), "r"(mbar) : "memory");
}
#define MBARRIER_INIT(addr, cnt) \
    asm volatile("mbarrier.init.shared.b64 [%0], %1;" :: "r"((uint32_t)(addr)), "r"((uint32_t)(cnt)) : "memory")
#define MBARRIER_EXPECT_TX(addr, bytes) \
    asm volatile("mbarrier.arrive.expect_tx.shared.b64 _, [%0], %1;" :: "r"((uint32_t)(addr)), "r"((uint32_t)(bytes)) : "memory")
#define MBARRIER_WAIT_PARITY(mbar_smem_addr, phase_parity) do { \
    uint32_t _mbar = (uint32_t)(mbar_smem_addr); \
    uint32_t _parity = (uint32_t)(phase_parity); \
    uint32_t _done; \
    asm volatile( \
        "{\n\t.reg .pred p;\n\t" \
        "mbarrier.try_wait.parity.acquire.cta.shared::cta.b64 p, [%1], %2;\n\t" \
        "selp.b32 %0, 1, 0, p;\n\t}" \
        : "=r"(_done) : "r"(_mbar), "r"(_parity) : "memory"); \
    if (!_done) { \
        asm volatile( \
            "{\n\t.reg .pred P1;\n\t" \
            "WAIT_LOOP_%=:\n\t" \
            "mbarrier.try_wait.parity.acquire.cta.shared::cta.b64 P1, [%0], %1, 0x989680;\n\t" \
            "@P1 bra.uni WAIT_DONE_%=;\n\t" \
            "bra.uni WAIT_LOOP_%=;\n\t" \
            "WAIT_DONE_%=:\n\t}" \
            :: "r"(_mbar), "r"(_parity) : "memory"); \
    } \
} while (0)

__device__ __forceinline__ void mma_bf16(float* c, const uint32_t* a, uint32_t b0, uint32_t b1) {
    asm volatile(
        "mma.sync.aligned.m16n8k16.row.col.f32.bf16.bf16.f32 "
        "{%0,%1,%2,%3}, {%4,%5,%6,%7}, {%8,%9}, {%0,%1,%2,%3};"
        : "+f"(c[0]), "+f"(c[1]), "+f"(c[2]), "+f"(c[3])
        : "r"(a[0]), "r"(a[1]), "r"(a[2]), "r"(a[3]), "r"(b0), "r"(b1));
}

// ---------------- small kernels ----------------
__global__ void reset_kernel() {
    if (threadIdx.x < E_NUM) g_cnt[threadIdx.x] = 0;
}

// fp32 [rows][rl] -> interleaved bf16 [rows][rl/64][hi64|lo64]
__global__ void convert_kernel(const float* __restrict__ src, int which, int rl4, int n4) {
    int i = blockIdx.x * 256 + threadIdx.x;
    if (i >= n4) return;
    __nv_bfloat16* dst;
    switch (which) {
        case 0: dst = g_xi;  break;
        case 1: dst = g_wgi; break;
        case 2: dst = g_wui; break;
        default: dst = g_wdi; break;
    }
    int row = i / rl4;
    int kk = (i - row * rl4) * 4;
    float4 v = ((const float4*)src)[i];
    __nv_bfloat162 h01, h23, l01, l23;
    h01.x = __float2bfloat16_rn(v.x); l01.x = __float2bfloat16_rn(v.x - __bfloat162float(h01.x));
    h01.y = __float2bfloat16_rn(v.y); l01.y = __float2bfloat16_rn(v.y - __bfloat162float(h01.y));
    h23.x = __float2bfloat16_rn(v.z); l23.x = __float2bfloat16_rn(v.z - __bfloat162float(h23.x));
    h23.y = __float2bfloat16_rn(v.w); l23.y = __float2bfloat16_rn(v.w - __bfloat162float(h23.y));
    size_t ob = (size_t)row * (size_t)(rl4 * 8) + (size_t)((kk >> 6) << 7) + (size_t)(kk & 63);
    *(__nv_bfloat162*)&dst[ob]          = h01;
    *(__nv_bfloat162*)&dst[ob + 2]      = h23;
    *(__nv_bfloat162*)&dst[ob + 64]     = l01;
    *(__nv_bfloat162*)&dst[ob + 64 + 2] = l23;
}

__global__ void router_kernel(const float* __restrict__ x,
                              const float* __restrict__ wr, int T) {
    int warp = threadIdx.x >> 5;
    int lane = threadIdx.x & 31;
    int t = blockIdx.x * 8 + warp;
    if (t >= T) return;

    const float4* x4 = (const float4*)(x + (size_t)t * D_DIM);
    const float4* w4 = (const float4*)wr;
    float acc[E_NUM];
#pragma unroll
    for (int e = 0; e < E_NUM; e++) acc[e] = 0.f;
    for (int d4 = lane; d4 < D_DIM / 4; d4 += 32) {
        float4 xv = x4[d4];
#pragma unroll
        for (int e = 0; e < E_NUM; e++) {
            float4 wv = w4[e * (D_DIM / 4) + d4];
            acc[e] += xv.x * wv.x + xv.y * wv.y + xv.z * wv.z + xv.w * wv.w;
        }
    }
#pragma unroll
    for (int e = 0; e < E_NUM; e++) {
#pragma unroll
        for (int o = 16; o > 0; o >>= 1)
            acc[e] += __shfl_xor_sync(0xffffffffu, acc[e], o);
    }
    if (lane == 0) {
        float s0 = -1e30f, s1 = -1e30f;
        int i0 = 0, i1 = 0;
#pragma unroll
        for (int e = 0; e < E_NUM; e++) {
            float v = acc[e];
            if (v > s0) { s1 = s0; i1 = i0; s0 = v; i0 = e; }
            else if (v > s1) { s1 = v; i1 = e; }
        }
        float p1 = expf(s1 - s0);
        float inv = 1.f / (1.f + p1);
        g_topk_idx[2 * t] = i0;
        g_topk_idx[2 * t + 1] = i1;
        g_topk_w[2 * t] = inv;
        g_topk_w[2 * t + 1] = p1 * inv;
        atomicAdd(&g_cnt[i0], 1);
        atomicAdd(&g_cnt[i1], 1);
    }
}

__global__ void offsets_kernel() {
    if (threadIdx.x == 0) {
        int o = 0;
        for (int e = 0; e < E_NUM; e++) {
            g_off[e] = o;
            o += g_cnt[e];
            g_cursor[e] = 0;
        }
        g_off[E_NUM] = o;
    }
}

__global__ void assign_kernel(int T) {
    int i = blockIdx.x * 256 + threadIdx.x;
    if (i >= 2 * T) return;
    int e = g_topk_idx[i];
    int pos = atomicAdd(&g_cursor[e], 1);
    int slot = g_off[e] + pos;
    g_tok_of_slot[slot] = i >> 1;
    g_slot_of[i] = slot;
}

// ---- mainloop compute for one K-stage (KT=64), warp tile 32x64 (4m x 2n grid) ----
__device__ __forceinline__ void stage_mma(uint32_t stg, int wm, int wn, int lane,
                                          float acc[16][4]) {
    uint32_t aBase = stg + (uint32_t)(wm * 32 + (lane & 7) + ((lane >> 3) & 1) * 8) * ROW_STRIDE
                     + (uint32_t)((lane >> 4) * 16);
    uint32_t bBase = stg + B_REG + (uint32_t)(wn * 64 + (lane & 7) + ((lane >> 4) & 1) * 8) * ROW_STRIDE
                     + (uint32_t)(((lane >> 3) & 1) * 16);
#pragma unroll
    for (int ks = 0; ks < 4; ks++) {
        uint32_t ka = (uint32_t)(ks * 32);
        uint32_t ah[2][4], al[2][4];
        ldsm4(ah[0], aBase + ka);
        ldsm4(ah[1], aBase + 16 * ROW_STRIDE + ka);
        ldsm4(al[0], aBase + ka + 128);
        ldsm4(al[1], aBase + 16 * ROW_STRIDE + ka + 128);
        uint32_t bh[4][4], bl[4][4];
#pragma unroll
        for (int g2 = 0; g2 < 4; g2++)
            ldsm4(bh[g2], bBase + (uint32_t)g2 * (16 * ROW_STRIDE) + ka);
        // hh: 16 independent MMAs
#pragma unroll
        for (int g2 = 0; g2 < 4; g2++)
#pragma unroll
            for (int t = 0; t < 2; t++) {
                mma_bf16(acc[t * 8 + g2 * 2 + 0], ah[t], bh[g2][0], bh[g2][1]);
                mma_bf16(acc[t * 8 + g2 * 2 + 1], ah[t], bh[g2][2], bh[g2][3]);
            }
        // lh
#pragma unroll
        for (int g2 = 0; g2 < 4; g2++)
            ldsm4(bl[g2], bBase + (uint32_t)g2 * (16 * ROW_STRIDE) + ka + 128);
#pragma unroll
        for (int g2 = 0; g2 < 4; g2++)
#pragma unroll
            for (int t = 0; t < 2; t++) {
                mma_bf16(acc[t * 8 + g2 * 2 + 0], al[t], bh[g2][0], bh[g2][1]);
                mma_bf16(acc[t * 8 + g2 * 2 + 1], al[t], bh[g2][2], bh[g2][3]);
            }
        // hl
#pragma unroll
        for (int g2 = 0; g2 < 4; g2++)
#pragma unroll
            for (int t = 0; t < 2; t++) {
                mma_bf16(acc[t * 8 + g2 * 2 + 0], ah[t], bl[g2][0], bl[g2][1]);
                mma_bf16(acc[t * 8 + g2 * 2 + 1], ah[t], bl[g2][2], bl[g2][3]);
            }
    }
}

// ================= GEMM1: H = SwiGLU(X Wg^T, X Wu^T) =================
// B rows (per n-half wn): [wn*64 .. wn*64+32) = gate f0+wn*32+i, [+32..+64) = up same f.
__global__ __launch_bounds__(256, 1) void gemm1_mma() {
    int e = blockIdx.z;
    int cnt = g_cnt[e];
    int m0 = blockIdx.y * 128;
    if (m0 >= cnt) return;
    int off = g_off[e];
    int f0 = blockIdx.x * 64;

    extern __shared__ __align__(16) char smem[];
    uint32_t sb = smem_u32(smem);
    int tid = threadIdx.x, w = tid >> 5, lane = tid & 31;
    int wm = w >> 1, wn = w & 1;

    const char* src;
    uint32_t dstOff;
    if (tid < 128) {
        int m = m0 + tid; if (m >= cnt) m = cnt - 1;
        src = (const char*)(g_xi + (size_t)g_tok_of_slot[off + m] * (2 * D_DIM));
        dstOff = 1024u + (uint32_t)tid * ROW_STRIDE;
    } else {
        int r = tid - 128;
        int grp = r >> 6, idx = r & 63;
        int f = f0 + grp * 32 + (idx & 31);
        if (idx < 32)
            src = (const char*)(g_wgi + ((size_t)e * F_DIM + f) * (2 * D_DIM));
        else
            src = (const char*)(g_wui + ((size_t)e * F_DIM + f) * (2 * D_DIM));
        dstOff = 1024u + B_REG + (uint32_t)r * ROW_STRIDE;
    }

    if (tid < NSTG) MBARRIER_INIT(sb + tid * 16, 1);
    __syncthreads();

    const int NS = D_DIM / KT;  // 32
#pragma unroll
    for (int s = 0; s < NSTG; s++) {
        if (tid == 0) MBARRIER_EXPECT_TX(sb + s * 16, STAGE_TX);
        bulk_ld(sb + dstOff + (uint32_t)s * STG_BYTES, src + s * 256, 256u, sb + s * 16);
    }

    float acc[16][4];
#pragma unroll
    for (int g = 0; g < 16; g++)
#pragma unroll
        for (int i = 0; i < 4; i++) acc[g][i] = 0.f;

    for (int s = 0; s < NS; s++) {
        int b = s % NSTG;
        MBARRIER_WAIT_PARITY(sb + b * 16, (s / NSTG) & 1);
        stage_mma(sb + 1024 + (uint32_t)b * STG_BYTES, wm, wn, lane, acc);
        __syncthreads();
        if (s + NSTG < NS) {
            if (tid == 0) MBARRIER_EXPECT_TX(sb + b * 16, STAGE_TX);
            bulk_ld(sb + dstOff + (uint32_t)b * STG_BYTES, src + (s + NSTG) * 256, 256u,
                    sb + b * 16);
        }
    }

    // epilogue: SwiGLU + interleaved bf16 hi/lo into g_Hi
    int q = lane >> 2, t4 = lane & 3;
#pragma unroll
    for (int t = 0; t < 2; t++) {
        int row0 = m0 + wm * 32 + t * 16 + q;
        int row1 = row0 + 8;
#pragma unroll
        for (int g = 0; g < 4; g++) {
            int f = f0 + wn * 32 + g * 8 + t4 * 2;
            int pos = ((f >> 6) << 7) + (f & 63);
            const float* ga = acc[t * 8 + g];
            const float* ua = acc[t * 8 + 4 + g];
            if (row0 < cnt) {
                float g0 = ga[0], g1 = ga[1], u0 = ua[0], u1 = ua[1];
                float h0 = g0 / (1.f + __expf(-g0)) * u0;
                float h1 = g1 / (1.f + __expf(-g1)) * u1;
                __nv_bfloat162 hh, hl;
                hh.x = __float2bfloat16_rn(h0); hl.x = __float2bfloat16_rn(h0 - __bfloat162float(hh.x));
                hh.y = __float2bfloat16_rn(h1); hl.y = __float2bfloat16_rn(h1 - __bfloat162float(hh.y));
                size_t ob = (size_t)(off + row0) * (2 * F_DIM) + pos;
                *(__nv_bfloat162*)&g_Hi[ob]      = hh;
                *(__nv_bfloat162*)&g_Hi[ob + 64] = hl;
            }
            if (row1 < cnt) {
                float g0 = ga[2], g1 = ga[3], u0 = ua[2], u1 = ua[3];
                float h0 = g0 / (1.f + __expf(-g0)) * u0;
                float h1 = g1 / (1.f + __expf(-g1)) * u1;
                __nv_bfloat162 hh, hl;
                hh.x = __float2bfloat16_rn(h0); hl.x = __float2bfloat16_rn(h0 - __bfloat162float(hh.x));
                hh.y = __float2bfloat16_rn(h1); hl.y = __float2bfloat16_rn(h1 - __bfloat162float(hh.y));
                size_t ob = (size_t)(off + row1) * (2 * F_DIM) + pos;
                *(__nv_bfloat162*)&g_Hi[ob]      = hh;
                *(__nv_bfloat162*)&g_Hi[ob + 64] = hl;
            }
        }
    }
}

// ================= GEMM2: O = H Wd^T =================
__global__ __launch_bounds__(256, 1) void gemm2_mma() {
    int e = blockIdx.z;
    int cnt = g_cnt[e];
    int m0 = blockIdx.y * 128;
    if (m0 >= cnt) return;
    int off = g_off[e];
    int n0 = blockIdx.x * 128;

    extern __shared__ __align__(16) char smem[];
    uint32_t sb = smem_u32(smem);
    int tid = threadIdx.x, w = tid >> 5, lane = tid & 31;
    int wm = w >> 1, wn = w & 1;

    const char* src;
    uint32_t dstOff;
    if (tid < 128) {
        int m = m0 + tid; if (m >= cnt) m = cnt - 1;
        src = (const char*)(g_Hi + (size_t)(off + m) * (2 * F_DIM));
        dstOff = 1024u + (uint32_t)tid * ROW_STRIDE;
    } else {
        int r = tid - 128;
        src = (const char*)(g_wdi + ((size_t)e * D_DIM + n0 + r) * (2 * F_DIM));
        dstOff = 1024u + B_REG + (uint32_t)r * ROW_STRIDE;
    }

    if (tid < NSTG) MBARRIER_INIT(sb + tid * 16, 1);
    __syncthreads();

    const int NS = F_DIM / KT;  // 12
#pragma unroll
    for (int s = 0; s < NSTG; s++) {
        if (tid == 0) MBARRIER_EXPECT_TX(sb + s * 16, STAGE_TX);
        bulk_ld(sb + dstOff + (uint32_t)s * STG_BYTES, src + s * 256, 256u, sb + s * 16);
    }

    float acc[16][4];
#pragma unroll
    for (int g = 0; g < 16; g++)
#pragma unroll
        for (int i = 0; i < 4; i++) acc[g][i] = 0.f;

    for (int s = 0; s < NS; s++) {
        int b = s % NSTG;
        MBARRIER_WAIT_PARITY(sb + b * 16, (s / NSTG) & 1);
        stage_mma(sb + 1024 + (uint32_t)b * STG_BYTES, wm, wn, lane, acc);
        __syncthreads();
        if (s + NSTG < NS) {
            if (tid == 0) MBARRIER_EXPECT_TX(sb + b * 16, STAGE_TX);
            bulk_ld(sb + dstOff + (uint32_t)b * STG_BYTES, src + (s + NSTG) * 256, 256u,
                    sb + b * 16);
        }
    }

    // epilogue: fp32 store to g_O
    int q = lane >> 2, t4 = lane & 3;
#pragma unroll
    for (int t = 0; t < 2; t++) {
        int row0 = m0 + wm * 32 + t * 16 + q;
        int row1 = row0 + 8;
#pragma unroll
        for (int g = 0; g < 8; g++) {
            int ni = n0 + wn * 64 + g * 8 + t4 * 2;
            if (row0 < cnt) {
                float2 v; v.x = acc[t * 8 + g][0]; v.y = acc[t * 8 + g][1];
                *(float2*)&g_O[(size_t)(off + row0) * D_DIM + ni] = v;
            }
            if (row1 < cnt) {
                float2 v; v.x = acc[t * 8 + g][2]; v.y = acc[t * 8 + g][3];
                *(float2*)&g_O[(size_t)(off + row1) * D_DIM + ni] = v;
            }
        }
    }
}

// ---------------- combine ----------------
__global__ void combine_kernel(float* __restrict__ out, int T) {
    int t = blockIdx.x;
    int d4 = blockIdx.y * blockDim.x + threadIdx.x;
    float w0 = g_topk_w[2 * t];
    float w1 = g_topk_w[2 * t + 1];
    int s0 = g_slot_of[2 * t];
    int s1 = g_slot_of[2 * t + 1];
    float4 a = ((const float4*)&g_O[(size_t)s0 * D_DIM])[d4];
    float4 b = ((const float4*)&g_O[(size_t)s1 * D_DIM])[d4];
    float4 r;
    r.x = w0 * a.x + w1 * b.x;
    r.y = w0 * a.y + w1 * b.y;
    r.z = w0 * a.z + w1 * b.z;
    r.w = w0 * a.w + w1 * b.w;
    ((float4*)out)[(size_t)t * (D_DIM / 4) + d4] = r;
}

// ---------------- launch ----------------
extern "C" void kernel_launch(void* const* d_in, const int* in_sizes, int n_in,
                              void* d_out, int out_size) {
    const float* x  = (const float*)d_in[0];
    const float* wr = (const float*)d_in[1];
    const float* wg = (const float*)d_in[2];
    const float* wu = (const float*)d_in[3];
    const float* wd = (const float*)d_in[4];
    int T = in_sizes[0] / D_DIM;  // 2048

    cudaFuncSetAttribute(gemm1_mma, cudaFuncAttributeMaxDynamicSharedMemorySize, SMEM_TOTAL);
    cudaFuncSetAttribute(gemm2_mma, cudaFuncAttributeMaxDynamicSharedMemorySize, SMEM_TOTAL);

    reset_kernel<<<1, 32>>>();

    int n4x = T * D_DIM / 4;
    int n4w = E_NUM * F_DIM * D_DIM / 4;
    convert_kernel<<<(n4x + 255) / 256, 256>>>(x, 0, D_DIM / 4, n4x);
    convert_kernel<<<(n4w + 255) / 256, 256>>>(wg, 1, D_DIM / 4, n4w);
    convert_kernel<<<(n4w + 255) / 256, 256>>>(wu, 2, D_DIM / 4, n4w);
    convert_kernel<<<(n4w + 255) / 256, 256>>>(wd, 3, F_DIM / 4, n4w);

    router_kernel<<<(T + 7) / 8, 256>>>(x, wr, T);
    offsets_kernel<<<1, 1>>>();
    assign_kernel<<<(2 * T + 255) / 256, 256>>>(T);

    dim3 g1(F_DIM / 64, 16, E_NUM);
    gemm1_mma<<<g1, 256, SMEM_TOTAL>>>();

    dim3 g2(D_DIM / 128, 16, E_NUM);
    gemm2_mma<<<g2, 256, SMEM_TOTAL>>>();

    combine_kernel<<<dim3(T, 2), 256>>>((float*)d_out, T);
}

// round 7
// speedup vs baseline: 2.9039x; 1.3220x over previous
#include <cuda_runtime.h>
#include <cuda_bf16.h>
#include <cstdint>

#define D_DIM 2048
#define E_NUM 8
#define F_DIM 768
#define T_MAX 2048
#define PSLOTS 5120            // padded slots (each expert padded to 128)
#define NTILES 40              // PSLOTS / 128

#define KT 64
#define NS1 32                 // D_DIM / KT
#define NS2 12                 // F_DIM / KT
#define OP_BYTES 32768         // one operand stage block: 128 rows x 256B
#define STG_BYTES 65536        // A + B
#define NSTG 3
#define SMEM_TOTAL (1024 + NSTG * STG_BYTES)

// ---------------- static device scratch ----------------
__device__ int   g_cnt[E_NUM];
__device__ int   g_cursor[E_NUM];
__device__ int   g_off_pad[E_NUM + 1];
__device__ int   g_topk_idx[2 * T_MAX];
__device__ float g_topk_w[2 * T_MAX];
__device__ int   g_tok_of_slot[PSLOTS];
__device__ int   g_slot_of[2 * T_MAX];

// stage-major packed operands, in-layout swizzled (chunk ^= row&7)
__device__ __align__(16) char g_w1p[(size_t)E_NUM * 12 * NS1 * OP_BYTES];   // gate+up
__device__ __align__(16) char g_w2p[(size_t)E_NUM * 16 * NS2 * OP_BYTES];   // down
__device__ __align__(16) char g_xg[(size_t)NTILES * NS1 * OP_BYTES];        // gathered X
__device__ __align__(16) char g_hp[(size_t)NTILES * NS2 * OP_BYTES];        // hidden H
__device__ float g_O[(size_t)PSLOTS * D_DIM];

// ---------------- helpers ----------------
__device__ __forceinline__ uint32_t smem_u32(const void* p) {
    uint32_t a;
    asm("{ .reg .u64 t; cvta.to.shared.u64 t, %1; cvt.u32.u64 %0, t; }" : "=r"(a) : "l"(p));
    return a;
}
__device__ __forceinline__ uint32_t swz(uint32_t row, uint32_t chunk) {
    return row * 256u + ((chunk ^ (row & 7u)) << 4);
}
__device__ __forceinline__ void ldsm4(uint32_t* r, uint32_t addr) {
    asm volatile("ldmatrix.sync.aligned.m8n8.x4.shared.b16 {%0,%1,%2,%3}, [%4];"
        : "=r"(r[0]), "=r"(r[1]), "=r"(r[2]), "=r"(r[3]) : "r"(addr));
}
__device__ __forceinline__ void bulk_ld(uint32_t dst, const void* src, uint32_t bytes, uint32_t mbar) {
    asm volatile(
        "cp.async.bulk.shared::cluster.global.mbarrier::complete_tx::bytes [%0], [%1], %2, [%3];"
        :: "r"(dst), "l"(src), "r"(bytes), "r"(mbar) : "memory");
}
#define MBARRIER_INIT(addr, cnt) \
    asm volatile("mbarrier.init.shared.b64 [%0], %1;" :: "r"((uint32_t)(addr)), "r"((uint32_t)(cnt)) : "memory")
#define MBARRIER_EXPECT_TX(addr, bytes) \
    asm volatile("mbarrier.arrive.expect_tx.shared.b64 _, [%0], %1;" :: "r"((uint32_t)(addr)), "r"((uint32_t)(bytes)) : "memory")
#define MBARRIER_WAIT_PARITY(mbar_smem_addr, phase_parity) do { \
    uint32_t _mbar = (uint32_t)(mbar_smem_addr); \
    uint32_t _parity = (uint32_t)(phase_parity); \
    uint32_t _done; \
    asm volatile( \
        "{\n\t.reg .pred p;\n\t" \
        "mbarrier.try_wait.parity.acquire.cta.shared::cta.b64 p, [%1], %2;\n\t" \
        "selp.b32 %0, 1, 0, p;\n\t}" \
        : "=r"(_done) : "r"(_mbar), "r"(_parity) : "memory"); \
    if (!_done) { \
        asm volatile( \
            "{\n\t.reg .pred P1;\n\t" \
            "WAIT_LOOP_%=:\n\t" \
            "mbarrier.try_wait.parity.acquire.cta.shared::cta.b64 P1, [%0], %1, 0x989680;\n\t" \
            "@P1 bra.uni WAIT_DONE_%=;\n\t" \
            "bra.uni WAIT_LOOP_%=;\n\t" \
            "WAIT_DONE_%=:\n\t}" \
            :: "r"(_mbar), "r"(_parity) : "memory"); \
    } \
} while (0)

__device__ __forceinline__ void mma_bf16(float* c, const uint32_t* a, uint32_t b0, uint32_t b1) {
    asm volatile(
        "mma.sync.aligned.m16n8k16.row.col.f32.bf16.bf16.f32 "
        "{%0,%1,%2,%3}, {%4,%5,%6,%7}, {%8,%9}, {%0,%1,%2,%3};"
        : "+f"(c[0]), "+f"(c[1]), "+f"(c[2]), "+f"(c[3])
        : "r"(a[0]), "r"(a[1]), "r"(a[2]), "r"(a[3]), "r"(b0), "r"(b1));
}
__device__ __forceinline__ void split2(float a, float b, uint32_t& h, uint32_t& l) {
    __nv_bfloat162 hh, ll;
    hh.x = __float2bfloat16_rn(a); ll.x = __float2bfloat16_rn(a - __bfloat162float(hh.x));
    hh.y = __float2bfloat16_rn(b); ll.y = __float2bfloat16_rn(b - __bfloat162float(hh.y));
    h = *(uint32_t*)&hh; l = *(uint32_t*)&ll;
}

// ---------------- small kernels ----------------
__global__ void reset_kernel() {
    if (threadIdx.x < E_NUM) g_cnt[threadIdx.x] = 0;
}
__global__ void prefill_kernel() {
    int i = blockIdx.x * 256 + threadIdx.x;
    if (i < PSLOTS) g_tok_of_slot[i] = 0;
}

// gate/up weights -> g_w1p  [e][ftile 12][stage 32][row 128][256B swz]
__global__ void convert_w1(const float* __restrict__ src, int isUp, int njobs) {
    int id = blockIdx.x * 256 + threadIdx.x;
    if (id >= njobs) return;
    int e = id / (F_DIM * 256);
    int rem = id - e * (F_DIM * 256);
    int f = rem >> 8;
    int kc = rem & 255;
    const float4* s4 = (const float4*)(src + ((size_t)e * F_DIM + f) * D_DIM + kc * 8);
    float4 v0 = s4[0], v1 = s4[1];
    uint4 h, l;
    split2(v0.x, v0.y, h.x, l.x); split2(v0.z, v0.w, h.y, l.y);
    split2(v1.x, v1.y, h.z, l.z); split2(v1.z, v1.w, h.w, l.w);
    int ftile = f >> 6, fl = f & 63;
    int wn = fl >> 5, idx = fl & 31;
    int r = wn * 64 + (isUp ? 32 : 0) + idx;
    int s = kc >> 3, kcs = kc & 7;
    char* base = g_w1p + ((size_t)((e * 12 + ftile) * NS1 + s)) * OP_BYTES;
    *(uint4*)(base + swz(r, kcs)) = h;
    *(uint4*)(base + swz(r, kcs + 8)) = l;
}

// down weights -> g_w2p  [e][ntile 16][stage 12][row 128][256B swz]
__global__ void convert_w2(const float* __restrict__ src, int njobs) {
    int id = blockIdx.x * 256 + threadIdx.x;
    if (id >= njobs) return;
    int e = id / (D_DIM * 96);
    int rem = id - e * (D_DIM * 96);
    int n = rem / 96;
    int kc = rem - n * 96;
    const float4* s4 = (const float4*)(src + ((size_t)e * D_DIM + n) * F_DIM + kc * 8);
    float4 v0 = s4[0], v1 = s4[1];
    uint4 h, l;
    split2(v0.x, v0.y, h.x, l.x); split2(v0.z, v0.w, h.y, l.y);
    split2(v1.x, v1.y, h.z, l.z); split2(v1.z, v1.w, h.w, l.w);
    int ntile = n >> 7, r = n & 127;
    int s = kc >> 3, kcs = kc & 7;
    char* base = g_w2p + ((size_t)((e * 16 + ntile) * NS2 + s)) * OP_BYTES;
    *(uint4*)(base + swz(r, kcs)) = h;
    *(uint4*)(base + swz(r, kcs + 8)) = l;
}

// gather + split X by padded slot -> g_xg [tile][stage 32][row 128][256B swz]
__global__ void gather_x(const float* __restrict__ x) {
    int id = blockIdx.x * 256 + threadIdx.x;   // PSLOTS*256 jobs
    int p = id >> 8;
    int kc = id & 255;
    if (p >= PSLOTS) return;
    int tok = g_tok_of_slot[p];
    const float4* s4 = (const float4*)(x + (size_t)tok * D_DIM + kc * 8);
    float4 v0 = s4[0], v1 = s4[1];
    uint4 h, l;
    split2(v0.x, v0.y, h.x, l.x); split2(v0.z, v0.w, h.y, l.y);
    split2(v1.x, v1.y, h.z, l.z); split2(v1.z, v1.w, h.w, l.w);
    int tile = p >> 7, r = p & 127;
    int s = kc >> 3, kcs = kc & 7;
    char* base = g_xg + ((size_t)(tile * NS1 + s)) * OP_BYTES;
    *(uint4*)(base + swz(r, kcs)) = h;
    *(uint4*)(base + swz(r, kcs + 8)) = l;
}

__global__ void router_kernel(const float* __restrict__ x,
                              const float* __restrict__ wr, int T) {
    int warp = threadIdx.x >> 5;
    int lane = threadIdx.x & 31;
    int t = blockIdx.x * 8 + warp;
    if (t >= T) return;

    const float4* x4 = (const float4*)(x + (size_t)t * D_DIM);
    const float4* w4 = (const float4*)wr;
    float acc[E_NUM];
#pragma unroll
    for (int e = 0; e < E_NUM; e++) acc[e] = 0.f;
    for (int d4 = lane; d4 < D_DIM / 4; d4 += 32) {
        float4 xv = x4[d4];
#pragma unroll
        for (int e = 0; e < E_NUM; e++) {
            float4 wv = w4[e * (D_DIM / 4) + d4];
            acc[e] += xv.x * wv.x + xv.y * wv.y + xv.z * wv.z + xv.w * wv.w;
        }
    }
#pragma unroll
    for (int e = 0; e < E_NUM; e++) {
#pragma unroll
        for (int o = 16; o > 0; o >>= 1)
            acc[e] += __shfl_xor_sync(0xffffffffu, acc[e], o);
    }
    if (lane == 0) {
        float s0 = -1e30f, s1 = -1e30f;
        int i0 = 0, i1 = 0;
#pragma unroll
        for (int e = 0; e < E_NUM; e++) {
            float v = acc[e];
            if (v > s0) { s1 = s0; i1 = i0; s0 = v; i0 = e; }
            else if (v > s1) { s1 = v; i1 = e; }
        }
        float p1 = expf(s1 - s0);
        float inv = 1.f / (1.f + p1);
        g_topk_idx[2 * t] = i0;
        g_topk_idx[2 * t + 1] = i1;
        g_topk_w[2 * t] = inv;
        g_topk_w[2 * t + 1] = p1 * inv;
        atomicAdd(&g_cnt[i0], 1);
        atomicAdd(&g_cnt[i1], 1);
    }
}

__global__ void offsets_kernel() {
    if (threadIdx.x == 0) {
        int op = 0;
        for (int e = 0; e < E_NUM; e++) {
            g_off_pad[e] = op;
            op += ((g_cnt[e] + 127) >> 7) << 7;
            g_cursor[e] = 0;
        }
        g_off_pad[E_NUM] = op;
    }
}

__global__ void assign_kernel(int T) {
    int i = blockIdx.x * 256 + threadIdx.x;
    if (i >= 2 * T) return;
    int e = g_topk_idx[i];
    int pos = atomicAdd(&g_cursor[e], 1);
    int slot = g_off_pad[e] + pos;
    g_tok_of_slot[slot] = i >> 1;
    g_slot_of[i] = slot;
}

// ---- mainloop compute for one K-stage (KT=64), warp tile 32x64, swizzled 256B rows ----
__device__ __forceinline__ void stage_mma(uint32_t stg, int wm, int wn, int lane,
                                          float acc[16][4]) {
    uint32_t rs = (uint32_t)(lane & 7);
    uint32_t rowA0 = (uint32_t)(wm * 32 + (lane & 7) + ((lane >> 3) & 1) * 8);
    uint32_t rowB  = (uint32_t)(wn * 64 + (lane & 7) + ((lane >> 4) & 1) * 8);
    uint32_t cbA = (uint32_t)(lane >> 4);
    uint32_t cbB = (uint32_t)((lane >> 3) & 1);
    uint32_t aA0 = stg + rowA0 * 256;
    uint32_t aA1 = aA0 + 16 * 256;
    uint32_t aB  = stg + (uint32_t)OP_BYTES + rowB * 256;
#pragma unroll
    for (int ks = 0; ks < 4; ks++) {
        uint32_t chAh = ((cbA + (uint32_t)(ks * 2)) ^ rs) << 4;
        uint32_t chAl = ((cbA + (uint32_t)(ks * 2) + 8u) ^ rs) << 4;
        uint32_t chBh = ((cbB + (uint32_t)(ks * 2)) ^ rs) << 4;
        uint32_t chBl = ((cbB + (uint32_t)(ks * 2) + 8u) ^ rs) << 4;
        uint32_t ah[2][4], al[2][4];
        ldsm4(ah[0], aA0 + chAh);
        ldsm4(ah[1], aA1 + chAh);
        ldsm4(al[0], aA0 + chAl);
        ldsm4(al[1], aA1 + chAl);
        uint32_t bh[4][4], bl[4][4];
#pragma unroll
        for (int g2 = 0; g2 < 4; g2++)
            ldsm4(bh[g2], aB + (uint32_t)g2 * (16 * 256) + chBh);
#pragma unroll
        for (int g2 = 0; g2 < 4; g2++)
#pragma unroll
            for (int t = 0; t < 2; t++) {
                mma_bf16(acc[t * 8 + g2 * 2 + 0], ah[t], bh[g2][0], bh[g2][1]);
                mma_bf16(acc[t * 8 + g2 * 2 + 1], ah[t], bh[g2][2], bh[g2][3]);
            }
#pragma unroll
        for (int g2 = 0; g2 < 4; g2++)
            ldsm4(bl[g2], aB + (uint32_t)g2 * (16 * 256) + chBl);
#pragma unroll
        for (int g2 = 0; g2 < 4; g2++)
#pragma unroll
            for (int t = 0; t < 2; t++) {
                mma_bf16(acc[t * 8 + g2 * 2 + 0], al[t], bh[g2][0], bh[g2][1]);
                mma_bf16(acc[t * 8 + g2 * 2 + 1], al[t], bh[g2][2], bh[g2][3]);
            }
#pragma unroll
        for (int g2 = 0; g2 < 4; g2++)
#pragma unroll
            for (int t = 0; t < 2; t++) {
                mma_bf16(acc[t * 8 + g2 * 2 + 0], ah[t], bl[g2][0], bl[g2][1]);
                mma_bf16(acc[t * 8 + g2 * 2 + 1], ah[t], bl[g2][2], bl[g2][3]);
            }
    }
}

// ================= GEMM1: H = SwiGLU(X Wg^T, X Wu^T) =================
__global__ __launch_bounds__(256, 1) void gemm1_mma() {
    int e = blockIdx.z;
    int cnt = g_cnt[e];
    int m0 = blockIdx.y * 128;
    if (m0 >= cnt) return;
    int off_pad = g_off_pad[e];
    int tile = (off_pad >> 7) + blockIdx.y;
    int f0 = blockIdx.x * 64;

    extern __shared__ __align__(16) char smem[];
    uint32_t sb = smem_u32(smem);
    int tid = threadIdx.x, w = tid >> 5, lane = tid & 31;
    int wm = w >> 1, wn = w & 1;

    const char* aSrc = g_xg + (size_t)tile * NS1 * OP_BYTES;
    const char* bSrc = g_w1p + (size_t)((e * 12 + blockIdx.x) * NS1) * OP_BYTES;

    if (tid < NSTG) MBARRIER_INIT(sb + tid * 16, 1);
    __syncthreads();

#pragma unroll
    for (int s = 0; s < NSTG; s++) {
        if (tid == 0) {
            MBARRIER_EXPECT_TX(sb + s * 16, STG_BYTES);
            uint32_t db = sb + 1024 + (uint32_t)s * STG_BYTES;
            bulk_ld(db, aSrc + (size_t)s * OP_BYTES, OP_BYTES, sb + s * 16);
            bulk_ld(db + OP_BYTES, bSrc + (size_t)s * OP_BYTES, OP_BYTES, sb + s * 16);
        }
    }

    float acc[16][4];
#pragma unroll
    for (int g = 0; g < 16; g++)
#pragma unroll
        for (int i = 0; i < 4; i++) acc[g][i] = 0.f;

    for (int s = 0; s < NS1; s++) {
        int b = s % NSTG;
        MBARRIER_WAIT_PARITY(sb + b * 16, (s / NSTG) & 1);
        stage_mma(sb + 1024 + (uint32_t)b * STG_BYTES, wm, wn, lane, acc);
        __syncthreads();
        if (s + NSTG < NS1 && tid == 0) {
            MBARRIER_EXPECT_TX(sb + b * 16, STG_BYTES);
            uint32_t db = sb + 1024 + (uint32_t)b * STG_BYTES;
            bulk_ld(db, aSrc + (size_t)(s + NSTG) * OP_BYTES, OP_BYTES, sb + b * 16);
            bulk_ld(db + OP_BYTES, bSrc + (size_t)(s + NSTG) * OP_BYTES, OP_BYTES, sb + b * 16);
        }
    }

    // epilogue: SwiGLU + write H into g_hp stage-major swizzled layout
    int q = lane >> 2, t4 = lane & 3;
    char* hBase = g_hp + (size_t)tile * NS2 * OP_BYTES;
#pragma unroll
    for (int t = 0; t < 2; t++) {
        int rl0 = wm * 32 + t * 16 + q;
        int rl1 = rl0 + 8;
#pragma unroll
        for (int g = 0; g < 4; g++) {
            int f = f0 + wn * 32 + g * 8 + t4 * 2;
            int s2 = f >> 6;
            int col = 2 * (f & 63);
            int chunk = col >> 4, inc = col & 15;
            const float* ga = acc[t * 8 + g];
            const float* ua = acc[t * 8 + 4 + g];
            char* sbase = hBase + (size_t)s2 * OP_BYTES;
            if (m0 + rl0 < cnt) {
                float g0 = ga[0], g1 = ga[1], u0 = ua[0], u1 = ua[1];
                float h0 = g0 / (1.f + __expf(-g0)) * u0;
                float h1 = g1 / (1.f + __expf(-g1)) * u1;
                uint32_t hh, hl;
                split2(h0, h1, hh, hl);
                *(uint32_t*)(sbase + swz(rl0, chunk) + inc)     = hh;
                *(uint32_t*)(sbase + swz(rl0, chunk + 8) + inc) = hl;
            }
            if (m0 + rl1 < cnt) {
                float g0 = ga[2], g1 = ga[3], u0 = ua[2], u1 = ua[3];
                float h0 = g0 / (1.f + __expf(-g0)) * u0;
                float h1 = g1 / (1.f + __expf(-g1)) * u1;
                uint32_t hh, hl;
                split2(h0, h1, hh, hl);
                *(uint32_t*)(sbase + swz(rl1, chunk) + inc)     = hh;
                *(uint32_t*)(sbase + swz(rl1, chunk + 8) + inc) = hl;
            }
        }
    }
}

// ================= GEMM2: O = H Wd^T =================
__global__ __launch_bounds__(256, 1) void gemm2_mma() {
    int e = blockIdx.z;
    int cnt = g_cnt[e];
    int m0 = blockIdx.y * 128;
    if (m0 >= cnt) return;
    int off_pad = g_off_pad[e];
    int tile = (off_pad >> 7) + blockIdx.y;
    int n0 = blockIdx.x * 128;

    extern __shared__ __align__(16) char smem[];
    uint32_t sb = smem_u32(smem);
    int tid = threadIdx.x, w = tid >> 5, lane = tid & 31;
    int wm = w >> 1, wn = w & 1;

    const char* aSrc = g_hp + (size_t)tile * NS2 * OP_BYTES;
    const char* bSrc = g_w2p + (size_t)((e * 16 + blockIdx.x) * NS2) * OP_BYTES;

    if (tid < NSTG) MBARRIER_INIT(sb + tid * 16, 1);
    __syncthreads();

#pragma unroll
    for (int s = 0; s < NSTG; s++) {
        if (tid == 0) {
            MBARRIER_EXPECT_TX(sb + s * 16, STG_BYTES);
            uint32_t db = sb + 1024 + (uint32_t)s * STG_BYTES;
            bulk_ld(db, aSrc + (size_t)s * OP_BYTES, OP_BYTES, sb + s * 16);
            bulk_ld(db + OP_BYTES, bSrc + (size_t)s * OP_BYTES, OP_BYTES, sb + s * 16);
        }
    }

    float acc[16][4];
#pragma unroll
    for (int g = 0; g < 16; g++)
#pragma unroll
        for (int i = 0; i < 4; i++) acc[g][i] = 0.f;

    for (int s = 0; s < NS2; s++) {
        int b = s % NSTG;
        MBARRIER_WAIT_PARITY(sb + b * 16, (s / NSTG) & 1);
        stage_mma(sb + 1024 + (uint32_t)b * STG_BYTES, wm, wn, lane, acc);
        __syncthreads();
        if (s + NSTG < NS2 && tid == 0) {
            MBARRIER_EXPECT_TX(sb + b * 16, STG_BYTES);
            uint32_t db = sb + 1024 + (uint32_t)b * STG_BYTES;
            bulk_ld(db, aSrc + (size_t)(s + NSTG) * OP_BYTES, OP_BYTES, sb + b * 16);
            bulk_ld(db + OP_BYTES, bSrc + (size_t)(s + NSTG) * OP_BYTES, OP_BYTES, sb + b * 16);
        }
    }

    // epilogue: fp32 store to g_O (padded-slot rows)
    int q = lane >> 2, t4 = lane & 3;
#pragma unroll
    for (int t = 0; t < 2; t++) {
        int rl0 = wm * 32 + t * 16 + q;
        int rl1 = rl0 + 8;
#pragma unroll
        for (int g = 0; g < 8; g++) {
            int ni = n0 + wn * 64 + g * 8 + t4 * 2;
            if (m0 + rl0 < cnt) {
                float2 v; v.x = acc[t * 8 + g][0]; v.y = acc[t * 8 + g][1];
                *(float2*)&g_O[(size_t)(off_pad + m0 + rl0) * D_DIM + ni] = v;
            }
            if (m0 + rl1 < cnt) {
                float2 v; v.x = acc[t * 8 + g][2]; v.y = acc[t * 8 + g][3];
                *(float2*)&g_O[(size_t)(off_pad + m0 + rl1) * D_DIM + ni] = v;
            }
        }
    }
}

// ---------------- combine ----------------
__global__ void combine_kernel(float* __restrict__ out, int T) {
    int t = blockIdx.x;
    int d4 = blockIdx.y * blockDim.x + threadIdx.x;
    float w0 = g_topk_w[2 * t];
    float w1 = g_topk_w[2 * t + 1];
    int s0 = g_slot_of[2 * t];
    int s1 = g_slot_of[2 * t + 1];
    float4 a = ((const float4*)&g_O[(size_t)s0 * D_DIM])[d4];
    float4 b = ((const float4*)&g_O[(size_t)s1 * D_DIM])[d4];
    float4 r;
    r.x = w0 * a.x + w1 * b.x;
    r.y = w0 * a.y + w1 * b.y;
    r.z = w0 * a.z + w1 * b.z;
    r.w = w0 * a.w + w1 * b.w;
    ((float4*)out)[(size_t)t * (D_DIM / 4) + d4] = r;
}

// ---------------- launch ----------------
extern "C" void kernel_launch(void* const* d_in, const int* in_sizes, int n_in,
                              void* d_out, int out_size) {
    const float* x  = (const float*)d_in[0];
    const float* wr = (const float*)d_in[1];
    const float* wg = (const float*)d_in[2];
    const float* wu = (const float*)d_in[3];
    const float* wd = (const float*)d_in[4];
    int T = in_sizes[0] / D_DIM;  // 2048

    cudaFuncSetAttribute(gemm1_mma, cudaFuncAttributeMaxDynamicSharedMemorySize, SMEM_TOTAL);
    cudaFuncSetAttribute(gemm2_mma, cudaFuncAttributeMaxDynamicSharedMemorySize, SMEM_TOTAL);

    reset_kernel<<<1, 32>>>();
    prefill_kernel<<<(PSLOTS + 255) / 256, 256>>>();

    int nw1 = E_NUM * F_DIM * 256;
    int nw2 = E_NUM * D_DIM * 96;
    convert_w1<<<(nw1 + 255) / 256, 256>>>(wg, 0, nw1);
    convert_w1<<<(nw1 + 255) / 256, 256>>>(wu, 1, nw1);
    convert_w2<<<(nw2 + 255) / 256, 256>>>(wd, nw2);

    router_kernel<<<(T + 7) / 8, 256>>>(x, wr, T);
    offsets_kernel<<<1, 1>>>();
    assign_kernel<<<(2 * T + 255) / 256, 256>>>(T);
    gather_x<<<(PSLOTS * 256) / 256, 256>>>(x);

    dim3 g1(F_DIM / 64, 16, E_NUM);
    gemm1_mma<<<g1, 256, SMEM_TOTAL>>>();

    dim3 g2(D_DIM / 128, 16, E_NUM);
    gemm2_mma<<<g2, 256, SMEM_TOTAL>>>();

    combine_kernel<<<dim3(T, 2), 256>>>((float*)d_out, T);
}

// round 8
// speedup vs baseline: 3.7885x; 1.3046x over previous
#include <cuda_runtime.h>
#include <cuda_bf16.h>
#include <cuda_fp16.h>
#include <cstdint>

#define D_DIM 2048
#define E_NUM 8
#define F_DIM 768
#define T_MAX 2048
#define PSLOTS 5120            // padded slots (each expert padded to 128)
#define NTILES 40              // PSLOTS / 128

#define KT 64
#define NS1 32                 // D_DIM / KT
#define NS2 12                 // F_DIM / KT
#define ABYTES 32768           // A stage block: 128 rows x 256B (hi+lo fp16)
#define BBYTES 16384           // B stage block: 128 rows x 128B (fp16)
#define STG_BYTES 49152
#define NSTG 3
#define SMEM_TOTAL (1024 + NSTG * STG_BYTES)

// ---------------- static device scratch ----------------
__device__ int   g_cnt[E_NUM];
__device__ int   g_cursor[E_NUM];
__device__ int   g_off_pad[E_NUM + 1];
__device__ int   g_topk_idx[2 * T_MAX];
__device__ float g_topk_w[2 * T_MAX];
__device__ int   g_tok_of_slot[PSLOTS];
__device__ int   g_slot_of[2 * T_MAX];

// stage-major packed operands, in-layout swizzled (chunk ^= row&7)
__device__ __align__(16) char g_w1p[(size_t)E_NUM * 12 * NS1 * BBYTES];   // gate+up fp16
__device__ __align__(16) char g_w2p[(size_t)E_NUM * 16 * NS2 * BBYTES];   // down fp16
__device__ __align__(16) char g_xg[(size_t)NTILES * NS1 * ABYTES];        // X fp16 hi/lo
__device__ __align__(16) char g_hp[(size_t)NTILES * NS2 * ABYTES];        // H fp16 hi/lo
__device__ float g_O[(size_t)PSLOTS * D_DIM];

// ---------------- helpers ----------------
__device__ __forceinline__ uint32_t smem_u32(const void* p) {
    uint32_t a;
    asm("{ .reg .u64 t; cvta.to.shared.u64 t, %1; cvt.u32.u64 %0, t; }" : "=r"(a) : "l"(p));
    return a;
}
__device__ __forceinline__ uint32_t swzA(uint32_t row, uint32_t chunk) {  // 256B rows, 16 chunks
    return row * 256u + ((chunk ^ (row & 7u)) << 4);
}
__device__ __forceinline__ uint32_t swzB(uint32_t row, uint32_t chunk) {  // 128B rows, 8 chunks
    return row * 128u + ((chunk ^ (row & 7u)) << 4);
}
__device__ __forceinline__ void ldsm4(uint32_t* r, uint32_t addr) {
    asm volatile("ldmatrix.sync.aligned.m8n8.x4.shared.b16 {%0,%1,%2,%3}, [%4];"
        : "=r"(r[0]), "=r"(r[1]), "=r"(r[2]), "=r"(r[3]) : "r"(addr));
}
__device__ __forceinline__ void bulk_ld(uint32_t dst, const void* src, uint32_t bytes, uint32_t mbar) {
    asm volatile(
        "cp.async.bulk.shared::cluster.global.mbarrier::complete_tx::bytes [%0], [%1], %2, [%3];"
        :: "r"(dst), "l"(src), "r"(bytes), "r"(mbar) : "memory");
}
#define MBARRIER_INIT(addr, cnt) \
    asm volatile("mbarrier.init.shared.b64 [%0], %1;" :: "r"((uint32_t)(addr)), "r"((uint32_t)(cnt)) : "memory")
#define MBARRIER_EXPECT_TX(addr, bytes) \
    asm volatile("mbarrier.arrive.expect_tx.shared.b64 _, [%0], %1;" :: "r"((uint32_t)(addr)), "r"((uint32_t)(bytes)) : "memory")
#define MBARRIER_WAIT_PARITY(mbar_smem_addr, phase_parity) do { \
    uint32_t _mbar = (uint32_t)(mbar_smem_addr); \
    uint32_t _parity = (uint32_t)(phase_parity); \
    uint32_t _done; \
    asm volatile( \
        "{\n\t.reg .pred p;\n\t" \
        "mbarrier.try_wait.parity.acquire.cta.shared::cta.b64 p, [%1], %2;\n\t" \
        "selp.b32 %0, 1, 0, p;\n\t}" \
        : "=r"(_done) : "r"(_mbar), "r"(_parity) : "memory"); \
    if (!_done) { \
        asm volatile( \
            "{\n\t.reg .pred P1;\n\t" \
            "WAIT_LOOP_%=:\n\t" \
            "mbarrier.try_wait.parity.acquire.cta.shared::cta.b64 P1, [%0], %1, 0x989680;\n\t" \
            "@P1 bra.uni WAIT_DONE_%=;\n\t" \
            "bra.uni WAIT_LOOP_%=;\n\t" \
            "WAIT_DONE_%=:\n\t}" \
            :: "r"(_mbar), "r"(_parity) : "memory"); \
    } \
} while (0)

__device__ __forceinline__ void mma_f16(float* c, const uint32_t* a, uint32_t b0, uint32_t b1) {
    asm volatile(
        "mma.sync.aligned.m16n8k16.row.col.f32.f16.f16.f32 "
        "{%0,%1,%2,%3}, {%4,%5,%6,%7}, {%8,%9}, {%0,%1,%2,%3};"
        : "+f"(c[0]), "+f"(c[1]), "+f"(c[2]), "+f"(c[3])
        : "r"(a[0]), "r"(a[1]), "r"(a[2]), "r"(a[3]), "r"(b0), "r"(b1));
}
// fp16 hi/lo split of two fp32 values
__device__ __forceinline__ void split2h(float a, float b, uint32_t& h, uint32_t& l) {
    __half2 hh, ll;
    hh.x = __float2half_rn(a); ll.x = __float2half_rn(a - __half2float(hh.x));
    hh.y = __float2half_rn(b); ll.y = __float2half_rn(b - __half2float(hh.y));
    h = *(uint32_t*)&hh; l = *(uint32_t*)&ll;
}
// fp16 single of two fp32 values
__device__ __forceinline__ uint32_t pack2h(float a, float b) {
    __half2 hh;
    hh.x = __float2half_rn(a);
    hh.y = __float2half_rn(b);
    return *(uint32_t*)&hh;
}

// ---------------- small kernels ----------------
__global__ void reset_kernel() {
    if (threadIdx.x < E_NUM) g_cnt[threadIdx.x] = 0;
}
__global__ void prefill_kernel() {
    int i = blockIdx.x * 256 + threadIdx.x;
    if (i < PSLOTS) g_tok_of_slot[i] = 0;
}

// gate/up weights -> g_w1p  [e][ftile 12][stage 32][row 128][128B swz] (single fp16)
__global__ void convert_w1(const float* __restrict__ src, int isUp, int njobs) {
    int id = blockIdx.x * 256 + threadIdx.x;
    if (id >= njobs) return;
    int e = id / (F_DIM * 256);
    int rem = id - e * (F_DIM * 256);
    int f = rem >> 8;
    int kc = rem & 255;
    const float4* s4 = (const float4*)(src + ((size_t)e * F_DIM + f) * D_DIM + kc * 8);
    float4 v0 = s4[0], v1 = s4[1];
    uint4 h;
    h.x = pack2h(v0.x, v0.y); h.y = pack2h(v0.z, v0.w);
    h.z = pack2h(v1.x, v1.y); h.w = pack2h(v1.z, v1.w);
    int ftile = f >> 6, fl = f & 63;
    int wn = fl >> 5, idx = fl & 31;
    int r = wn * 64 + (isUp ? 32 : 0) + idx;
    int s = kc >> 3, kcs = kc & 7;
    char* base = g_w1p + ((size_t)((e * 12 + ftile) * NS1 + s)) * BBYTES;
    *(uint4*)(base + swzB(r, kcs)) = h;
}

// down weights -> g_w2p  [e][ntile 16][stage 12][row 128][128B swz] (single fp16)
__global__ void convert_w2(const float* __restrict__ src, int njobs) {
    int id = blockIdx.x * 256 + threadIdx.x;
    if (id >= njobs) return;
    int e = id / (D_DIM * 96);
    int rem = id - e * (D_DIM * 96);
    int n = rem / 96;
    int kc = rem - n * 96;
    const float4* s4 = (const float4*)(src + ((size_t)e * D_DIM + n) * F_DIM + kc * 8);
    float4 v0 = s4[0], v1 = s4[1];
    uint4 h;
    h.x = pack2h(v0.x, v0.y); h.y = pack2h(v0.z, v0.w);
    h.z = pack2h(v1.x, v1.y); h.w = pack2h(v1.z, v1.w);
    int ntile = n >> 7, r = n & 127;
    int s = kc >> 3, kcs = kc & 7;
    char* base = g_w2p + ((size_t)((e * 16 + ntile) * NS2 + s)) * BBYTES;
    *(uint4*)(base + swzB(r, kcs)) = h;
}

// gather + fp16 hi/lo split X -> g_xg [tile][stage 32][row 128][256B swz]
__global__ void gather_x(const float* __restrict__ x) {
    int id = blockIdx.x * 256 + threadIdx.x;
    int p = id >> 8;
    int kc = id & 255;
    if (p >= PSLOTS) return;
    int tok = g_tok_of_slot[p];
    const float4* s4 = (const float4*)(x + (size_t)tok * D_DIM + kc * 8);
    float4 v0 = s4[0], v1 = s4[1];
    uint4 h, l;
    split2h(v0.x, v0.y, h.x, l.x); split2h(v0.z, v0.w, h.y, l.y);
    split2h(v1.x, v1.y, h.z, l.z); split2h(v1.z, v1.w, h.w, l.w);
    int tile = p >> 7, r = p & 127;
    int s = kc >> 3, kcs = kc & 7;
    char* base = g_xg + ((size_t)(tile * NS1 + s)) * ABYTES;
    *(uint4*)(base + swzA(r, kcs)) = h;
    *(uint4*)(base + swzA(r, kcs + 8)) = l;
}

__global__ void router_kernel(const float* __restrict__ x,
                              const float* __restrict__ wr, int T) {
    int warp = threadIdx.x >> 5;
    int lane = threadIdx.x & 31;
    int t = blockIdx.x * 8 + warp;
    if (t >= T) return;

    const float4* x4 = (const float4*)(x + (size_t)t * D_DIM);
    const float4* w4 = (const float4*)wr;
    float acc[E_NUM];
#pragma unroll
    for (int e = 0; e < E_NUM; e++) acc[e] = 0.f;
    for (int d4 = lane; d4 < D_DIM / 4; d4 += 32) {
        float4 xv = x4[d4];
#pragma unroll
        for (int e = 0; e < E_NUM; e++) {
            float4 wv = w4[e * (D_DIM / 4) + d4];
            acc[e] += xv.x * wv.x + xv.y * wv.y + xv.z * wv.z + xv.w * wv.w;
        }
    }
#pragma unroll
    for (int e = 0; e < E_NUM; e++) {
#pragma unroll
        for (int o = 16; o > 0; o >>= 1)
            acc[e] += __shfl_xor_sync(0xffffffffu, acc[e], o);
    }
    if (lane == 0) {
        float s0 = -1e30f, s1 = -1e30f;
        int i0 = 0, i1 = 0;
#pragma unroll
        for (int e = 0; e < E_NUM; e++) {
            float v = acc[e];
            if (v > s0) { s1 = s0; i1 = i0; s0 = v; i0 = e; }
            else if (v > s1) { s1 = v; i1 = e; }
        }
        float p1 = expf(s1 - s0);
        float inv = 1.f / (1.f + p1);
        g_topk_idx[2 * t] = i0;
        g_topk_idx[2 * t + 1] = i1;
        g_topk_w[2 * t] = inv;
        g_topk_w[2 * t + 1] = p1 * inv;
        atomicAdd(&g_cnt[i0], 1);
        atomicAdd(&g_cnt[i1], 1);
    }
}

__global__ void offsets_kernel() {
    if (threadIdx.x == 0) {
        int op = 0;
        for (int e = 0; e < E_NUM; e++) {
            g_off_pad[e] = op;
            op += ((g_cnt[e] + 127) >> 7) << 7;
            g_cursor[e] = 0;
        }
        g_off_pad[E_NUM] = op;
    }
}

__global__ void assign_kernel(int T) {
    int i = blockIdx.x * 256 + threadIdx.x;
    if (i >= 2 * T) return;
    int e = g_topk_idx[i];
    int pos = atomicAdd(&g_cursor[e], 1);
    int slot = g_off_pad[e] + pos;
    g_tok_of_slot[slot] = i >> 1;
    g_slot_of[i] = slot;
}

// ---- mainloop compute for one K-stage (KT=64), warp tile 32x64, 2-term fp16 ----
__device__ __forceinline__ void stage_mma(uint32_t stg, int wm, int wn, int lane,
                                          float acc[16][4]) {
    uint32_t rs = (uint32_t)(lane & 7);
    uint32_t rowA0 = (uint32_t)(wm * 32 + (lane & 7) + ((lane >> 3) & 1) * 8);
    uint32_t rowB  = (uint32_t)(wn * 64 + (lane & 7) + ((lane >> 4) & 1) * 8);
    uint32_t cbA = (uint32_t)(lane >> 4);
    uint32_t cbB = (uint32_t)((lane >> 3) & 1);
    uint32_t aA0 = stg + rowA0 * 256;
    uint32_t aA1 = aA0 + 16 * 256;
    uint32_t aB  = stg + (uint32_t)ABYTES + rowB * 128;
#pragma unroll
    for (int ks = 0; ks < 4; ks++) {
        uint32_t chAh = ((cbA + (uint32_t)(ks * 2)) ^ rs) << 4;
        uint32_t chAl = ((cbA + (uint32_t)(ks * 2) + 8u) ^ rs) << 4;
        uint32_t chB  = ((cbB + (uint32_t)(ks * 2)) ^ rs) << 4;
        uint32_t ah[2][4], al[2][4];
        ldsm4(ah[0], aA0 + chAh);
        ldsm4(ah[1], aA1 + chAh);
        ldsm4(al[0], aA0 + chAl);
        ldsm4(al[1], aA1 + chAl);
        uint32_t bh[4][4];
#pragma unroll
        for (int g2 = 0; g2 < 4; g2++)
            ldsm4(bh[g2], aB + (uint32_t)g2 * (16 * 128) + chB);
        // hh: 16 independent MMAs
#pragma unroll
        for (int g2 = 0; g2 < 4; g2++)
#pragma unroll
            for (int t = 0; t < 2; t++) {
                mma_f16(acc[t * 8 + g2 * 2 + 0], ah[t], bh[g2][0], bh[g2][1]);
                mma_f16(acc[t * 8 + g2 * 2 + 1], ah[t], bh[g2][2], bh[g2][3]);
            }
        // lh: 16 more
#pragma unroll
        for (int g2 = 0; g2 < 4; g2++)
#pragma unroll
            for (int t = 0; t < 2; t++) {
                mma_f16(acc[t * 8 + g2 * 2 + 0], al[t], bh[g2][0], bh[g2][1]);
                mma_f16(acc[t * 8 + g2 * 2 + 1], al[t], bh[g2][2], bh[g2][3]);
            }
    }
}

// ================= GEMM1: H = SwiGLU(X Wg^T, X Wu^T) =================
__global__ __launch_bounds__(256, 1) void gemm1_mma() {
    int e = blockIdx.z;
    int cnt = g_cnt[e];
    int m0 = blockIdx.y * 128;
    if (m0 >= cnt) return;
    int off_pad = g_off_pad[e];
    int tile = (off_pad >> 7) + blockIdx.y;
    int f0 = blockIdx.x * 64;

    extern __shared__ __align__(16) char smem[];
    uint32_t sb = smem_u32(smem);
    int tid = threadIdx.x, w = tid >> 5, lane = tid & 31;
    int wm = w >> 1, wn = w & 1;

    const char* aSrc = g_xg + (size_t)tile * NS1 * ABYTES;
    const char* bSrc = g_w1p + (size_t)((e * 12 + blockIdx.x) * NS1) * BBYTES;

    if (tid < NSTG) MBARRIER_INIT(sb + tid * 16, 1);
    __syncthreads();

#pragma unroll
    for (int s = 0; s < NSTG; s++) {
        if (tid == 0) {
            MBARRIER_EXPECT_TX(sb + s * 16, STG_BYTES);
            uint32_t db = sb + 1024 + (uint32_t)s * STG_BYTES;
            bulk_ld(db, aSrc + (size_t)s * ABYTES, ABYTES, sb + s * 16);
            bulk_ld(db + ABYTES, bSrc + (size_t)s * BBYTES, BBYTES, sb + s * 16);
        }
    }

    float acc[16][4];
#pragma unroll
    for (int g = 0; g < 16; g++)
#pragma unroll
        for (int i = 0; i < 4; i++) acc[g][i] = 0.f;

    for (int s = 0; s < NS1; s++) {
        int b = s % NSTG;
        MBARRIER_WAIT_PARITY(sb + b * 16, (s / NSTG) & 1);
        stage_mma(sb + 1024 + (uint32_t)b * STG_BYTES, wm, wn, lane, acc);
        __syncthreads();
        if (s + NSTG < NS1 && tid == 0) {
            MBARRIER_EXPECT_TX(sb + b * 16, STG_BYTES);
            uint32_t db = sb + 1024 + (uint32_t)b * STG_BYTES;
            bulk_ld(db, aSrc + (size_t)(s + NSTG) * ABYTES, ABYTES, sb + b * 16);
            bulk_ld(db + ABYTES, bSrc + (size_t)(s + NSTG) * BBYTES, BBYTES, sb + b * 16);
        }
    }

    // epilogue: SwiGLU + fp16 hi/lo H into g_hp (A layout for GEMM2)
    int q = lane >> 2, t4 = lane & 3;
    char* hBase = g_hp + (size_t)tile * NS2 * ABYTES;
#pragma unroll
    for (int t = 0; t < 2; t++) {
        int rl0 = wm * 32 + t * 16 + q;
        int rl1 = rl0 + 8;
#pragma unroll
        for (int g = 0; g < 4; g++) {
            int f = f0 + wn * 32 + g * 8 + t4 * 2;
            int s2 = f >> 6;
            int fl = f & 63;
            int chunk = fl >> 3;          // (2*fl)>>4
            int inc = (2 * fl) & 15;
            const float* ga = acc[t * 8 + g];
            const float* ua = acc[t * 8 + 4 + g];
            char* sbase = hBase + (size_t)s2 * ABYTES;
            if (m0 + rl0 < cnt) {
                float g0 = ga[0], g1 = ga[1], u0 = ua[0], u1 = ua[1];
                float h0 = g0 / (1.f + __expf(-g0)) * u0;
                float h1 = g1 / (1.f + __expf(-g1)) * u1;
                uint32_t hh, hl;
                split2h(h0, h1, hh, hl);
                *(uint32_t*)(sbase + swzA(rl0, chunk) + inc)     = hh;
                *(uint32_t*)(sbase + swzA(rl0, chunk + 8) + inc) = hl;
            }
            if (m0 + rl1 < cnt) {
                float g0 = ga[2], g1 = ga[3], u0 = ua[2], u1 = ua[3];
                float h0 = g0 / (1.f + __expf(-g0)) * u0;
                float h1 = g1 / (1.f + __expf(-g1)) * u1;
                uint32_t hh, hl;
                split2h(h0, h1, hh, hl);
                *(uint32_t*)(sbase + swzA(rl1, chunk) + inc)     = hh;
                *(uint32_t*)(sbase + swzA(rl1, chunk + 8) + inc) = hl;
            }
        }
    }
}

// ================= GEMM2: O = H Wd^T =================
__global__ __launch_bounds__(256, 1) void gemm2_mma() {
    int e = blockIdx.z;
    int cnt = g_cnt[e];
    int m0 = blockIdx.y * 128;
    if (m0 >= cnt) return;
    int off_pad = g_off_pad[e];
    int tile = (off_pad >> 7) + blockIdx.y;
    int n0 = blockIdx.x * 128;

    extern __shared__ __align__(16) char smem[];
    uint32_t sb = smem_u32(smem);
    int tid = threadIdx.x, w = tid >> 5, lane = tid & 31;
    int wm = w >> 1, wn = w & 1;

    const char* aSrc = g_hp + (size_t)tile * NS2 * ABYTES;
    const char* bSrc = g_w2p + (size_t)((e * 16 + blockIdx.x) * NS2) * BBYTES;

    if (tid < NSTG) MBARRIER_INIT(sb + tid * 16, 1);
    __syncthreads();

#pragma unroll
    for (int s = 0; s < NSTG; s++) {
        if (tid == 0) {
            MBARRIER_EXPECT_TX(sb + s * 16, STG_BYTES);
            uint32_t db = sb + 1024 + (uint32_t)s * STG_BYTES;
            bulk_ld(db, aSrc + (size_t)s * ABYTES, ABYTES, sb + s * 16);
            bulk_ld(db + ABYTES, bSrc + (size_t)s * BBYTES, BBYTES, sb + s * 16);
        }
    }

    float acc[16][4];
#pragma unroll
    for (int g = 0; g < 16; g++)
#pragma unroll
        for (int i = 0; i < 4; i++) acc[g][i] = 0.f;

    for (int s = 0; s < NS2; s++) {
        int b = s % NSTG;
        MBARRIER_WAIT_PARITY(sb + b * 16, (s / NSTG) & 1);
        stage_mma(sb + 1024 + (uint32_t)b * STG_BYTES, wm, wn, lane, acc);
        __syncthreads();
        if (s + NSTG < NS2 && tid == 0) {
            MBARRIER_EXPECT_TX(sb + b * 16, STG_BYTES);
            uint32_t db = sb + 1024 + (uint32_t)b * STG_BYTES;
            bulk_ld(db, aSrc + (size_t)(s + NSTG) * ABYTES, ABYTES, sb + b * 16);
            bulk_ld(db + ABYTES, bSrc + (size_t)(s + NSTG) * BBYTES, BBYTES, sb + b * 16);
        }
    }

    // epilogue: fp32 store to g_O (padded-slot rows)
    int q = lane >> 2, t4 = lane & 3;
#pragma unroll
    for (int t = 0; t < 2; t++) {
        int rl0 = wm * 32 + t * 16 + q;
        int rl1 = rl0 + 8;
#pragma unroll
        for (int g = 0; g < 8; g++) {
            int ni = n0 + wn * 64 + g * 8 + t4 * 2;
            if (m0 + rl0 < cnt) {
                float2 v; v.x = acc[t * 8 + g][0]; v.y = acc[t * 8 + g][1];
                *(float2*)&g_O[(size_t)(off_pad + m0 + rl0) * D_DIM + ni] = v;
            }
            if (m0 + rl1 < cnt) {
                float2 v; v.x = acc[t * 8 + g][2]; v.y = acc[t * 8 + g][3];
                *(float2*)&g_O[(size_t)(off_pad + m0 + rl1) * D_DIM + ni] = v;
            }
        }
    }
}

// ---------------- combine ----------------
__global__ void combine_kernel(float* __restrict__ out, int T) {
    int t = blockIdx.x;
    int d4 = blockIdx.y * blockDim.x + threadIdx.x;
    float w0 = g_topk_w[2 * t];
    float w1 = g_topk_w[2 * t + 1];
    int s0 = g_slot_of[2 * t];
    int s1 = g_slot_of[2 * t + 1];
    float4 a = ((const float4*)&g_O[(size_t)s0 * D_DIM])[d4];
    float4 b = ((const float4*)&g_O[(size_t)s1 * D_DIM])[d4];
    float4 r;
    r.x = w0 * a.x + w1 * b.x;
    r.y = w0 * a.y + w1 * b.y;
    r.z = w0 * a.z + w1 * b.z;
    r.w = w0 * a.w + w1 * b.w;
    ((float4*)out)[(size_t)t * (D_DIM / 4) + d4] = r;
}

// ---------------- launch ----------------
extern "C" void kernel_launch(void* const* d_in, const int* in_sizes, int n_in,
                              void* d_out, int out_size) {
    const float* x  = (const float*)d_in[0];
    const float* wr = (const float*)d_in[1];
    const float* wg = (const float*)d_in[2];
    const float* wu = (const float*)d_in[3];
    const float* wd = (const float*)d_in[4];
    int T = in_sizes[0] / D_DIM;  // 2048

    cudaFuncSetAttribute(gemm1_mma, cudaFuncAttributeMaxDynamicSharedMemorySize, SMEM_TOTAL);
    cudaFuncSetAttribute(gemm2_mma, cudaFuncAttributeMaxDynamicSharedMemorySize, SMEM_TOTAL);

    reset_kernel<<<1, 32>>>();
    prefill_kernel<<<(PSLOTS + 255) / 256, 256>>>();

    int nw1 = E_NUM * F_DIM * 256;
    int nw2 = E_NUM * D_DIM * 96;
    convert_w1<<<(nw1 + 255) / 256, 256>>>(wg, 0, nw1);
    convert_w1<<<(nw1 + 255) / 256, 256>>>(wu, 1, nw1);
    convert_w2<<<(nw2 + 255) / 256, 256>>>(wd, nw2);

    router_kernel<<<(T + 7) / 8, 256>>>(x, wr, T);
    offsets_kernel<<<1, 1>>>();
    assign_kernel<<<(2 * T + 255) / 256, 256>>>(T);
    gather_x<<<(PSLOTS * 256) / 256, 256>>>(x);

    dim3 g1(F_DIM / 64, 16, E_NUM);
    gemm1_mma<<<g1, 256, SMEM_TOTAL>>>();

    dim3 g2(D_DIM / 128, 16, E_NUM);
    gemm2_mma<<<g2, 256, SMEM_TOTAL>>>();

    combine_kernel<<<dim3(T, 2), 256>>>((float*)d_out, T);
}

// round 9
// speedup vs baseline: 3.8704x; 1.0216x over previous
#include <cuda_runtime.h>
#include <cuda_bf16.h>
#include <cuda_fp16.h>
#include <cstdint>

#define D_DIM 2048
#define E_NUM 8
#define F_DIM 768
#define T_MAX 2048
#define PSLOTS 5120            // padded slots (each expert padded to 128)
#define NTILES 40              // PSLOTS / 128

#define KT 128
#define NS1 16                 // D_DIM / KT
#define NS2 6                  // F_DIM / KT
#define ABYTES 65536           // A stage block: 128 rows x 512B (hi 256 | lo 256)
#define BBYTES 32768           // B stage block: 128 rows x 256B (fp16)
#define STG_BYTES 98304
#define NSTG 2
#define SMEM_TOTAL (1024 + NSTG * STG_BYTES)

// ---------------- static device scratch ----------------
__device__ int   g_cnt[E_NUM];
__device__ int   g_cursor[E_NUM];
__device__ int   g_off_pad[E_NUM + 1];
__device__ int   g_topk_idx[2 * T_MAX];
__device__ float g_topk_w[2 * T_MAX];
__device__ int   g_tok_of_slot[PSLOTS];
__device__ int   g_slot_of[2 * T_MAX];

// stage-major packed operands, in-layout swizzled (chunk ^= row&7, low 3 bits)
__device__ __align__(16) char g_w1p[(size_t)E_NUM * 12 * NS1 * BBYTES];   // gate+up fp16
__device__ __align__(16) char g_w2p[(size_t)E_NUM * 16 * NS2 * BBYTES];   // down fp16
__device__ __align__(16) char g_xg[(size_t)NTILES * NS1 * ABYTES];        // X fp16 hi/lo
__device__ __align__(16) char g_hp[(size_t)NTILES * NS2 * ABYTES];        // H fp16 hi/lo
__device__ float g_O[(size_t)PSLOTS * D_DIM];

// ---------------- helpers ----------------
__device__ __forceinline__ uint32_t smem_u32(const void* p) {
    uint32_t a;
    asm("{ .reg .u64 t; cvta.to.shared.u64 t, %1; cvt.u32.u64 %0, t; }" : "=r"(a) : "l"(p));
    return a;
}
// A rows: 512B, 32 chunks of 16B; B rows: 256B, 16 chunks (XOR affects low 3 bits only)
__device__ __forceinline__ uint32_t swzA(uint32_t row, uint32_t chunk) {
    return row * 512u + ((chunk ^ (row & 7u)) << 4);
}
__device__ __forceinline__ uint32_t swzB(uint32_t row, uint32_t chunk) {
    return row * 256u + ((chunk ^ (row & 7u)) << 4);
}
__device__ __forceinline__ void ldsm4(uint32_t* r, uint32_t addr) {
    asm volatile("ldmatrix.sync.aligned.m8n8.x4.shared.b16 {%0,%1,%2,%3}, [%4];"
        : "=r"(r[0]), "=r"(r[1]), "=r"(r[2]), "=r"(r[3]) : "r"(addr));
}
__device__ __forceinline__ void bulk_ld(uint32_t dst, const void* src, uint32_t bytes, uint32_t mbar) {
    asm volatile(
        "cp.async.bulk.shared::cluster.global.mbarrier::complete_tx::bytes [%0], [%1], %2, [%3];"
        :: "r"(dst), "l"(src), "r"(bytes), "r"(mbar) : "memory");
}
#define MBARRIER_INIT(addr, cnt) \
    asm volatile("mbarrier.init.shared.b64 [%0], %1;" :: "r"((uint32_t)(addr)), "r"((uint32_t)(cnt)) : "memory")
#define MBARRIER_EXPECT_TX(addr, bytes) \
    asm volatile("mbarrier.arrive.expect_tx.shared.b64 _, [%0], %1;" :: "r"((uint32_t)(addr)), "r"((uint32_t)(bytes)) : "memory")
#define MBARRIER_WAIT_PARITY(mbar_smem_addr, phase_parity) do { \
    uint32_t _mbar = (uint32_t)(mbar_smem_addr); \
    uint32_t _parity = (uint32_t)(phase_parity); \
    uint32_t _done; \
    asm volatile( \
        "{\n\t.reg .pred p;\n\t" \
        "mbarrier.try_wait.parity.acquire.cta.shared::cta.b64 p, [%1], %2;\n\t" \
        "selp.b32 %0, 1, 0, p;\n\t}" \
        : "=r"(_done) : "r"(_mbar), "r"(_parity) : "memory"); \
    if (!_done) { \
        asm volatile( \
            "{\n\t.reg .pred P1;\n\t" \
            "WAIT_LOOP_%=:\n\t" \
            "mbarrier.try_wait.parity.acquire.cta.shared::cta.b64 P1, [%0], %1, 0x989680;\n\t" \
            "@P1 bra.uni WAIT_DONE_%=;\n\t" \
            "bra.uni WAIT_LOOP_%=;\n\t" \
            "WAIT_DONE_%=:\n\t}" \
            :: "r"(_mbar), "r"(_parity) : "memory"); \
    } \
} while (0)

__device__ __forceinline__ void mma_f16(float* c, const uint32_t* a, uint32_t b0, uint32_t b1) {
    asm volatile(
        "mma.sync.aligned.m16n8k16.row.col.f32.f16.f16.f32 "
        "{%0,%1,%2,%3}, {%4,%5,%6,%7}, {%8,%9}, {%0,%1,%2,%3};"
        : "+f"(c[0]), "+f"(c[1]), "+f"(c[2]), "+f"(c[3])
        : "r"(a[0]), "r"(a[1]), "r"(a[2]), "r"(a[3]), "r"(b0), "r"(b1));
}
__device__ __forceinline__ void split2h(float a, float b, uint32_t& h, uint32_t& l) {
    __half2 hh, ll;
    hh.x = __float2half_rn(a); ll.x = __float2half_rn(a - __half2float(hh.x));
    hh.y = __float2half_rn(b); ll.y = __float2half_rn(b - __half2float(hh.y));
    h = *(uint32_t*)&hh; l = *(uint32_t*)&ll;
}
__device__ __forceinline__ uint32_t pack2h(float a, float b) {
    __half2 hh;
    hh.x = __float2half_rn(a);
    hh.y = __float2half_rn(b);
    return *(uint32_t*)&hh;
}

// ---------------- small kernels ----------------
__global__ void reset_kernel() {
    if (threadIdx.x < E_NUM) g_cnt[threadIdx.x] = 0;
}
__global__ void prefill_kernel() {
    int i = blockIdx.x * 256 + threadIdx.x;
    if (i < PSLOTS) g_tok_of_slot[i] = 0;
}

// gate/up weights -> g_w1p  [e][ftile 12][stage 16][row 128][256B swz] (fp16)
__global__ void convert_w1(const float* __restrict__ src, int isUp, int njobs) {
    int id = blockIdx.x * 256 + threadIdx.x;
    if (id >= njobs) return;
    int e = id / (F_DIM * 256);
    int rem = id - e * (F_DIM * 256);
    int f = rem >> 8;
    int kc = rem & 255;          // 16B chunk over D (8 fp32 -> 8 fp16... wait: 8 fp16=16B from 8 fp32)
    const float4* s4 = (const float4*)(src + ((size_t)e * F_DIM + f) * D_DIM + kc * 8);
    float4 v0 = s4[0], v1 = s4[1];
    uint4 h;
    h.x = pack2h(v0.x, v0.y); h.y = pack2h(v0.z, v0.w);
    h.z = pack2h(v1.x, v1.y); h.w = pack2h(v1.z, v1.w);
    int ftile = f >> 6, fl = f & 63;
    int wn = fl >> 5, idx = fl & 31;
    int r = wn * 64 + (isUp ? 32 : 0) + idx;
    int s = kc >> 4, kcs = kc & 15;
    char* base = g_w1p + ((size_t)((e * 12 + ftile) * NS1 + s)) * BBYTES;
    *(uint4*)(base + swzB(r, kcs)) = h;
}

// down weights -> g_w2p  [e][ntile 16][stage 6][row 128][256B swz] (fp16)
__global__ void convert_w2(const float* __restrict__ src, int njobs) {
    int id = blockIdx.x * 256 + threadIdx.x;
    if (id >= njobs) return;
    int e = id / (D_DIM * 96);
    int rem = id - e * (D_DIM * 96);
    int n = rem / 96;
    int kc = rem - n * 96;
    const float4* s4 = (const float4*)(src + ((size_t)e * D_DIM + n) * F_DIM + kc * 8);
    float4 v0 = s4[0], v1 = s4[1];
    uint4 h;
    h.x = pack2h(v0.x, v0.y); h.y = pack2h(v0.z, v0.w);
    h.z = pack2h(v1.x, v1.y); h.w = pack2h(v1.z, v1.w);
    int ntile = n >> 7, r = n & 127;
    int s = kc >> 4, kcs = kc & 15;
    char* base = g_w2p + ((size_t)((e * 16 + ntile) * NS2 + s)) * BBYTES;
    *(uint4*)(base + swzB(r, kcs)) = h;
}

// gather + fp16 hi/lo split X -> g_xg [tile][stage 16][row 128][512B swz]
__global__ void gather_x(const float* __restrict__ x) {
    int id = blockIdx.x * 256 + threadIdx.x;
    int p = id >> 8;
    int kc = id & 255;
    if (p >= PSLOTS) return;
    int tok = g_tok_of_slot[p];
    const float4* s4 = (const float4*)(x + (size_t)tok * D_DIM + kc * 8);
    float4 v0 = s4[0], v1 = s4[1];
    uint4 h, l;
    split2h(v0.x, v0.y, h.x, l.x); split2h(v0.z, v0.w, h.y, l.y);
    split2h(v1.x, v1.y, h.z, l.z); split2h(v1.z, v1.w, h.w, l.w);
    int tile = p >> 7, r = p & 127;
    int s = kc >> 4, kcs = kc & 15;
    char* base = g_xg + ((size_t)(tile * NS1 + s)) * ABYTES;
    uint32_t oh = swzA(r, kcs);
    *(uint4*)(base + oh)       = h;   // hi chunks 0..15
    *(uint4*)(base + oh + 256) = l;   // lo chunks 16..31 (same XOR, +256B)
}

__global__ void router_kernel(const float* __restrict__ x,
                              const float* __restrict__ wr, int T) {
    int warp = threadIdx.x >> 5;
    int lane = threadIdx.x & 31;
    int t = blockIdx.x * 8 + warp;
    if (t >= T) return;

    const float4* x4 = (const float4*)(x + (size_t)t * D_DIM);
    const float4* w4 = (const float4*)wr;
    float acc[E_NUM];
#pragma unroll
    for (int e = 0; e < E_NUM; e++) acc[e] = 0.f;
    for (int d4 = lane; d4 < D_DIM / 4; d4 += 32) {
        float4 xv = x4[d4];
#pragma unroll
        for (int e = 0; e < E_NUM; e++) {
            float4 wv = w4[e * (D_DIM / 4) + d4];
            acc[e] += xv.x * wv.x + xv.y * wv.y + xv.z * wv.z + xv.w * wv.w;
        }
    }
#pragma unroll
    for (int e = 0; e < E_NUM; e++) {
#pragma unroll
        for (int o = 16; o > 0; o >>= 1)
            acc[e] += __shfl_xor_sync(0xffffffffu, acc[e], o);
    }
    if (lane == 0) {
        float s0 = -1e30f, s1 = -1e30f;
        int i0 = 0, i1 = 0;
#pragma unroll
        for (int e = 0; e < E_NUM; e++) {
            float v = acc[e];
            if (v > s0) { s1 = s0; i1 = i0; s0 = v; i0 = e; }
            else if (v > s1) { s1 = v; i1 = e; }
        }
        float p1 = expf(s1 - s0);
        float inv = 1.f / (1.f + p1);
        g_topk_idx[2 * t] = i0;
        g_topk_idx[2 * t + 1] = i1;
        g_topk_w[2 * t] = inv;
        g_topk_w[2 * t + 1] = p1 * inv;
        atomicAdd(&g_cnt[i0], 1);
        atomicAdd(&g_cnt[i1], 1);
    }
}

__global__ void offsets_kernel() {
    if (threadIdx.x == 0) {
        int op = 0;
        for (int e = 0; e < E_NUM; e++) {
            g_off_pad[e] = op;
            op += ((g_cnt[e] + 127) >> 7) << 7;
            g_cursor[e] = 0;
        }
        g_off_pad[E_NUM] = op;
    }
}

__global__ void assign_kernel(int T) {
    int i = blockIdx.x * 256 + threadIdx.x;
    if (i >= 2 * T) return;
    int e = g_topk_idx[i];
    int pos = atomicAdd(&g_cursor[e], 1);
    int slot = g_off_pad[e] + pos;
    g_tok_of_slot[slot] = i >> 1;
    g_slot_of[i] = slot;
}

// ---- mainloop compute for one K-stage (KT=128), warp tile 32x64, 2-term fp16 ----
__device__ __forceinline__ void stage_mma(uint32_t stg, int wm, int wn, int lane,
                                          float acc[16][4]) {
    uint32_t rs = (uint32_t)(lane & 7);
    uint32_t rowA0 = (uint32_t)(wm * 32 + (lane & 7) + ((lane >> 3) & 1) * 8);
    uint32_t rowB  = (uint32_t)(wn * 64 + (lane & 7) + ((lane >> 4) & 1) * 8);
    uint32_t cbA = (uint32_t)(lane >> 4);
    uint32_t cbB = (uint32_t)((lane >> 3) & 1);
    uint32_t aA0 = stg + rowA0 * 512;
    uint32_t aA1 = aA0 + 16 * 512;
    uint32_t aB  = stg + (uint32_t)ABYTES + rowB * 256;
#pragma unroll
    for (int ks = 0; ks < 8; ks++) {
        uint32_t chAh = ((cbA + (uint32_t)(ks * 2)) ^ rs) << 4;          // hi chunks 0..15
        uint32_t chAl = chAh + 256u;                                      // lo chunks (+256B)
        uint32_t chB  = ((cbB + (uint32_t)(ks * 2)) ^ rs) << 4;
        uint32_t ah[2][4], al[2][4];
        ldsm4(ah[0], aA0 + chAh);
        ldsm4(ah[1], aA1 + chAh);
        ldsm4(al[0], aA0 + chAl);
        ldsm4(al[1], aA1 + chAl);
        uint32_t bh[4][4];
#pragma unroll
        for (int g2 = 0; g2 < 4; g2++)
            ldsm4(bh[g2], aB + (uint32_t)g2 * (16 * 256) + chB);
        // hh: 16 independent MMAs
#pragma unroll
        for (int g2 = 0; g2 < 4; g2++)
#pragma unroll
            for (int t = 0; t < 2; t++) {
                mma_f16(acc[t * 8 + g2 * 2 + 0], ah[t], bh[g2][0], bh[g2][1]);
                mma_f16(acc[t * 8 + g2 * 2 + 1], ah[t], bh[g2][2], bh[g2][3]);
            }
        // lh: 16 more
#pragma unroll
        for (int g2 = 0; g2 < 4; g2++)
#pragma unroll
            for (int t = 0; t < 2; t++) {
                mma_f16(acc[t * 8 + g2 * 2 + 0], al[t], bh[g2][0], bh[g2][1]);
                mma_f16(acc[t * 8 + g2 * 2 + 1], al[t], bh[g2][2], bh[g2][3]);
            }
    }
}

// ================= GEMM1: H = SwiGLU(X Wg^T, X Wu^T) =================
__global__ __launch_bounds__(256, 1) void gemm1_mma() {
    int e = blockIdx.z;
    int cnt = g_cnt[e];
    int m0 = blockIdx.y * 128;
    if (m0 >= cnt) return;
    int off_pad = g_off_pad[e];
    int tile = (off_pad >> 7) + blockIdx.y;
    int f0 = blockIdx.x * 64;

    extern __shared__ __align__(16) char smem[];
    uint32_t sb = smem_u32(smem);
    int tid = threadIdx.x, w = tid >> 5, lane = tid & 31;
    int wm = w >> 1, wn = w & 1;

    const char* aSrc = g_xg + (size_t)tile * NS1 * ABYTES;
    const char* bSrc = g_w1p + (size_t)((e * 12 + blockIdx.x) * NS1) * BBYTES;

    if (tid < NSTG) MBARRIER_INIT(sb + tid * 16, 1);
    __syncthreads();

#pragma unroll
    for (int s = 0; s < NSTG; s++) {
        if (tid == 0) {
            MBARRIER_EXPECT_TX(sb + s * 16, STG_BYTES);
            uint32_t db = sb + 1024 + (uint32_t)s * STG_BYTES;
            bulk_ld(db, aSrc + (size_t)s * ABYTES, ABYTES, sb + s * 16);
            bulk_ld(db + ABYTES, bSrc + (size_t)s * BBYTES, BBYTES, sb + s * 16);
        }
    }

    float acc[16][4];
#pragma unroll
    for (int g = 0; g < 16; g++)
#pragma unroll
        for (int i = 0; i < 4; i++) acc[g][i] = 0.f;

    for (int s = 0; s < NS1; s++) {
        int b = s % NSTG;
        MBARRIER_WAIT_PARITY(sb + b * 16, (s / NSTG) & 1);
        stage_mma(sb + 1024 + (uint32_t)b * STG_BYTES, wm, wn, lane, acc);
        __syncthreads();
        if (s + NSTG < NS1 && tid == 0) {
            MBARRIER_EXPECT_TX(sb + b * 16, STG_BYTES);
            uint32_t db = sb + 1024 + (uint32_t)b * STG_BYTES;
            bulk_ld(db, aSrc + (size_t)(s + NSTG) * ABYTES, ABYTES, sb + b * 16);
            bulk_ld(db + ABYTES, bSrc + (size_t)(s + NSTG) * BBYTES, BBYTES, sb + b * 16);
        }
    }

    // epilogue: SwiGLU + fp16 hi/lo H into g_hp (A layout for GEMM2, KT=128 stages)
    int q = lane >> 2, t4 = lane & 3;
    char* hBase = g_hp + (size_t)tile * NS2 * ABYTES;
#pragma unroll
    for (int t = 0; t < 2; t++) {
        int rl0 = wm * 32 + t * 16 + q;
        int rl1 = rl0 + 8;
#pragma unroll
        for (int g = 0; g < 4; g++) {
            int f = f0 + wn * 32 + g * 8 + t4 * 2;
            int s2 = f >> 7;
            int fl = f & 127;
            int chunk = fl >> 3;           // (2*fl)>>4, in 0..15
            int inc = (2 * fl) & 15;
            const float* ga = acc[t * 8 + g];
            const float* ua = acc[t * 8 + 4 + g];
            char* sbase = hBase + (size_t)s2 * ABYTES;
            if (m0 + rl0 < cnt) {
                float g0 = ga[0], g1 = ga[1], u0 = ua[0], u1 = ua[1];
                float h0 = g0 / (1.f + __expf(-g0)) * u0;
                float h1 = g1 / (1.f + __expf(-g1)) * u1;
                uint32_t hh, hl;
                split2h(h0, h1, hh, hl);
                uint32_t oh = swzA(rl0, chunk) + inc;
                *(uint32_t*)(sbase + oh)       = hh;
                *(uint32_t*)(sbase + oh + 256) = hl;
            }
            if (m0 + rl1 < cnt) {
                float g0 = ga[2], g1 = ga[3], u0 = ua[2], u1 = ua[3];
                float h0 = g0 / (1.f + __expf(-g0)) * u0;
                float h1 = g1 / (1.f + __expf(-g1)) * u1;
                uint32_t hh, hl;
                split2h(h0, h1, hh, hl);
                uint32_t oh = swzA(rl1, chunk) + inc;
                *(uint32_t*)(sbase + oh)       = hh;
                *(uint32_t*)(sbase + oh + 256) = hl;
            }
        }
    }
}

// ================= GEMM2: O = H Wd^T =================
__global__ __launch_bounds__(256, 1) void gemm2_mma() {
    int e = blockIdx.z;
    int cnt = g_cnt[e];
    int m0 = blockIdx.y * 128;
    if (m0 >= cnt) return;
    int off_pad = g_off_pad[e];
    int tile = (off_pad >> 7) + blockIdx.y;
    int n0 = blockIdx.x * 128;

    extern __shared__ __align__(16) char smem[];
    uint32_t sb = smem_u32(smem);
    int tid = threadIdx.x, w = tid >> 5, lane = tid & 31;
    int wm = w >> 1, wn = w & 1;

    const char* aSrc = g_hp + (size_t)tile * NS2 * ABYTES;
    const char* bSrc = g_w2p + (size_t)((e * 16 + blockIdx.x) * NS2) * BBYTES;

    if (tid < NSTG) MBARRIER_INIT(sb + tid * 16, 1);
    __syncthreads();

#pragma unroll
    for (int s = 0; s < NSTG; s++) {
        if (tid == 0) {
            MBARRIER_EXPECT_TX(sb + s * 16, STG_BYTES);
            uint32_t db = sb + 1024 + (uint32_t)s * STG_BYTES;
            bulk_ld(db, aSrc + (size_t)s * ABYTES, ABYTES, sb + s * 16);
            bulk_ld(db + ABYTES, bSrc + (size_t)s * BBYTES, BBYTES, sb + s * 16);
        }
    }

    float acc[16][4];
#pragma unroll
    for (int g = 0; g < 16; g++)
#pragma unroll
        for (int i = 0; i < 4; i++) acc[g][i] = 0.f;

    for (int s = 0; s < NS2; s++) {
        int b = s % NSTG;
        MBARRIER_WAIT_PARITY(sb + b * 16, (s / NSTG) & 1);
        stage_mma(sb + 1024 + (uint32_t)b * STG_BYTES, wm, wn, lane, acc);
        __syncthreads();
        if (s + NSTG < NS2 && tid == 0) {
            MBARRIER_EXPECT_TX(sb + b * 16, STG_BYTES);
            uint32_t db = sb + 1024 + (uint32_t)b * STG_BYTES;
            bulk_ld(db, aSrc + (size_t)(s + NSTG) * ABYTES, ABYTES, sb + b * 16);
            bulk_ld(db + ABYTES, bSrc + (size_t)(s + NSTG) * BBYTES, BBYTES, sb + b * 16);
        }
    }

    // epilogue: fp32 store to g_O (padded-slot rows)
    int q = lane >> 2, t4 = lane & 3;
#pragma unroll
    for (int t = 0; t < 2; t++) {
        int rl0 = wm * 32 + t * 16 + q;
        int rl1 = rl0 + 8;
#pragma unroll
        for (int g = 0; g < 8; g++) {
            int ni = n0 + wn * 64 + g * 8 + t4 * 2;
            if (m0 + rl0 < cnt) {
                float2 v; v.x = acc[t * 8 + g][0]; v.y = acc[t * 8 + g][1];
                *(float2*)&g_O[(size_t)(off_pad + m0 + rl0) * D_DIM + ni] = v;
            }
            if (m0 + rl1 < cnt) {
                float2 v; v.x = acc[t * 8 + g][2]; v.y = acc[t * 8 + g][3];
                *(float2*)&g_O[(size_t)(off_pad + m0 + rl1) * D_DIM + ni] = v;
            }
        }
    }
}

// ---------------- combine ----------------
__global__ void combine_kernel(float* __restrict__ out, int T) {
    int t = blockIdx.x;
    int d4 = blockIdx.y * blockDim.x + threadIdx.x;
    float w0 = g_topk_w[2 * t];
    float w1 = g_topk_w[2 * t + 1];
    int s0 = g_slot_of[2 * t];
    int s1 = g_slot_of[2 * t + 1];
    float4 a = ((const float4*)&g_O[(size_t)s0 * D_DIM])[d4];
    float4 b = ((const float4*)&g_O[(size_t)s1 * D_DIM])[d4];
    float4 r;
    r.x = w0 * a.x + w1 * b.x;
    r.y = w0 * a.y + w1 * b.y;
    r.z = w0 * a.z + w1 * b.z;
    r.w = w0 * a.w + w1 * b.w;
    ((float4*)out)[(size_t)t * (D_DIM / 4) + d4] = r;
}

// ---------------- launch ----------------
extern "C" void kernel_launch(void* const* d_in, const int* in_sizes, int n_in,
                              void* d_out, int out_size) {
    const float* x  = (const float*)d_in[0];
    const float* wr = (const float*)d_in[1];
    const float* wg = (const float*)d_in[2];
    const float* wu = (const float*)d_in[3];
    const float* wd = (const float*)d_in[4];
    int T = in_sizes[0] / D_DIM;  // 2048

    cudaFuncSetAttribute(gemm1_mma, cudaFuncAttributeMaxDynamicSharedMemorySize, SMEM_TOTAL);
    cudaFuncSetAttribute(gemm2_mma, cudaFuncAttributeMaxDynamicSharedMemorySize, SMEM_TOTAL);

    reset_kernel<<<1, 32>>>();
    prefill_kernel<<<(PSLOTS + 255) / 256, 256>>>();

    int nw1 = E_NUM * F_DIM * 256;
    int nw2 = E_NUM * D_DIM * 96;
    convert_w1<<<(nw1 + 255) / 256, 256>>>(wg, 0, nw1);
    convert_w1<<<(nw1 + 255) / 256, 256>>>(wu, 1, nw1);
    convert_w2<<<(nw2 + 255) / 256, 256>>>(wd, nw2);

    router_kernel<<<(T + 7) / 8, 256>>>(x, wr, T);
    offsets_kernel<<<1, 1>>>();
    assign_kernel<<<(2 * T + 255) / 256, 256>>>(T);
    gather_x<<<(PSLOTS * 256) / 256, 256>>>(x);

    dim3 g1(F_DIM / 64, 16, E_NUM);
    gemm1_mma<<<g1, 256, SMEM_TOTAL>>>();

    dim3 g2(D_DIM / 128, 16, E_NUM);
    gemm2_mma<<<g2, 256, SMEM_TOTAL>>>();

    combine_kernel<<<dim3(T, 2), 256>>>((float*)d_out, T);
}

// round 10
// speedup vs baseline: 5.3494x; 1.3821x over previous
#include <cuda_runtime.h>
#include <cuda_bf16.h>
#include <cuda_fp16.h>
#include <cstdint>

#define D_DIM 2048
#define E_NUM 8
#define F_DIM 768
#define T_MAX 2048
#define PSLOTS 5120            // padded slots (each expert padded to 128)
#define NTILES 40              // PSLOTS / 128

#define KT 128
#define NS1 16                 // D_DIM / KT
#define NS2 6                  // F_DIM / KT
#define ABYTES 32768           // A stage block: 128 rows x 256B (fp16)
#define BBYTES 32768           // B stage block: 128 rows x 256B (fp16)
#define STG_BYTES 65536
#define NSTG 3
#define SMEM_TOTAL (1024 + NSTG * STG_BYTES)

// ---------------- static device scratch ----------------
__device__ int   g_cnt[E_NUM];
__device__ int   g_cursor[E_NUM];
__device__ int   g_off_pad[E_NUM + 1];
__device__ int   g_topk_idx[2 * T_MAX];
__device__ float g_topk_w[2 * T_MAX];
__device__ int   g_tok_of_slot[PSLOTS];
__device__ int   g_slot_of[2 * T_MAX];

// stage-major packed operands, in-layout swizzled (chunk ^= row&7, low 3 bits)
__device__ __align__(16) char g_w1p[(size_t)E_NUM * 12 * NS1 * BBYTES];   // gate+up fp16
__device__ __align__(16) char g_w2p[(size_t)E_NUM * 16 * NS2 * BBYTES];   // down fp16
__device__ __align__(16) char g_xg[(size_t)NTILES * NS1 * ABYTES];        // X fp16
__device__ __align__(16) char g_hp[(size_t)NTILES * NS2 * ABYTES];        // H fp16
__device__ float g_O[(size_t)PSLOTS * D_DIM];

// ---------------- helpers ----------------
__device__ __forceinline__ uint32_t smem_u32(const void* p) {
    uint32_t a;
    asm("{ .reg .u64 t; cvta.to.shared.u64 t, %1; cvt.u32.u64 %0, t; }" : "=r"(a) : "l"(p));
    return a;
}
// rows: 256B, 16 chunks of 16B (XOR affects low 3 bits of chunk index)
__device__ __forceinline__ uint32_t swz(uint32_t row, uint32_t chunk) {
    return row * 256u + ((chunk ^ (row & 7u)) << 4);
}
__device__ __forceinline__ void ldsm4(uint32_t* r, uint32_t addr) {
    asm volatile("ldmatrix.sync.aligned.m8n8.x4.shared.b16 {%0,%1,%2,%3}, [%4];"
        : "=r"(r[0]), "=r"(r[1]), "=r"(r[2]), "=r"(r[3]) : "r"(addr));
}
__device__ __forceinline__ void bulk_ld(uint32_t dst, const void* src, uint32_t bytes, uint32_t mbar) {
    asm volatile(
        "cp.async.bulk.shared::cluster.global.mbarrier::complete_tx::bytes [%0], [%1], %2, [%3];"
        :: "r"(dst), "l"(src), "r"(bytes), "r"(mbar) : "memory");
}
#define MBARRIER_INIT(addr, cnt) \
    asm volatile("mbarrier.init.shared.b64 [%0], %1;" :: "r"((uint32_t)(addr)), "r"((uint32_t)(cnt)) : "memory")
#define MBARRIER_EXPECT_TX(addr, bytes) \
    asm volatile("mbarrier.arrive.expect_tx.shared.b64 _, [%0], %1;" :: "r"((uint32_t)(addr)), "r"((uint32_t)(bytes)) : "memory")
#define MBARRIER_WAIT_PARITY(mbar_smem_addr, phase_parity) do { \
    uint32_t _mbar = (uint32_t)(mbar_smem_addr); \
    uint32_t _parity = (uint32_t)(phase_parity); \
    uint32_t _done; \
    asm volatile( \
        "{\n\t.reg .pred p;\n\t" \
        "mbarrier.try_wait.parity.acquire.cta.shared::cta.b64 p, [%1], %2;\n\t" \
        "selp.b32 %0, 1, 0, p;\n\t}" \
        : "=r"(_done) : "r"(_mbar), "r"(_parity) : "memory"); \
    if (!_done) { \
        asm volatile( \
            "{\n\t.reg .pred P1;\n\t" \
            "WAIT_LOOP_%=:\n\t" \
            "mbarrier.try_wait.parity.acquire.cta.shared::cta.b64 P1, [%0], %1, 0x989680;\n\t" \
            "@P1 bra.uni WAIT_DONE_%=;\n\t" \
            "bra.uni WAIT_LOOP_%=;\n\t" \
            "WAIT_DONE_%=:\n\t}" \
            :: "r"(_mbar), "r"(_parity) : "memory"); \
    } \
} while (0)

__device__ __forceinline__ void mma_f16(float* c, const uint32_t* a, uint32_t b0, uint32_t b1) {
    asm volatile(
        "mma.sync.aligned.m16n8k16.row.col.f32.f16.f16.f32 "
        "{%0,%1,%2,%3}, {%4,%5,%6,%7}, {%8,%9}, {%0,%1,%2,%3};"
        : "+f"(c[0]), "+f"(c[1]), "+f"(c[2]), "+f"(c[3])
        : "r"(a[0]), "r"(a[1]), "r"(a[2]), "r"(a[3]), "r"(b0), "r"(b1));
}
__device__ __forceinline__ uint32_t pack2h(float a, float b) {
    __half2 hh;
    hh.x = __float2half_rn(a);
    hh.y = __float2half_rn(b);
    return *(uint32_t*)&hh;
}

// ---------------- small kernels ----------------
__global__ void reset_kernel() {
    if (threadIdx.x < E_NUM) g_cnt[threadIdx.x] = 0;
}
__global__ void prefill_kernel() {
    int i = blockIdx.x * 256 + threadIdx.x;
    if (i < PSLOTS) g_tok_of_slot[i] = 0;
}

// gate/up weights -> g_w1p  [e][ftile 12][stage 16][row 128][256B swz] (fp16)
__global__ void convert_w1(const float* __restrict__ src, int isUp, int njobs) {
    int id = blockIdx.x * 256 + threadIdx.x;
    if (id >= njobs) return;
    int e = id / (F_DIM * 256);
    int rem = id - e * (F_DIM * 256);
    int f = rem >> 8;
    int kc = rem & 255;
    const float4* s4 = (const float4*)(src + ((size_t)e * F_DIM + f) * D_DIM + kc * 8);
    float4 v0 = s4[0], v1 = s4[1];
    uint4 h;
    h.x = pack2h(v0.x, v0.y); h.y = pack2h(v0.z, v0.w);
    h.z = pack2h(v1.x, v1.y); h.w = pack2h(v1.z, v1.w);
    int ftile = f >> 6, fl = f & 63;
    int wn = fl >> 5, idx = fl & 31;
    int r = wn * 64 + (isUp ? 32 : 0) + idx;
    int s = kc >> 4, kcs = kc & 15;
    char* base = g_w1p + ((size_t)((e * 12 + ftile) * NS1 + s)) * BBYTES;
    *(uint4*)(base + swz(r, kcs)) = h;
}

// down weights -> g_w2p  [e][ntile 16][stage 6][row 128][256B swz] (fp16)
__global__ void convert_w2(const float* __restrict__ src, int njobs) {
    int id = blockIdx.x * 256 + threadIdx.x;
    if (id >= njobs) return;
    int e = id / (D_DIM * 96);
    int rem = id - e * (D_DIM * 96);
    int n = rem / 96;
    int kc = rem - n * 96;
    const float4* s4 = (const float4*)(src + ((size_t)e * D_DIM + n) * F_DIM + kc * 8);
    float4 v0 = s4[0], v1 = s4[1];
    uint4 h;
    h.x = pack2h(v0.x, v0.y); h.y = pack2h(v0.z, v0.w);
    h.z = pack2h(v1.x, v1.y); h.w = pack2h(v1.z, v1.w);
    int ntile = n >> 7, r = n & 127;
    int s = kc >> 4, kcs = kc & 15;
    char* base = g_w2p + ((size_t)((e * 16 + ntile) * NS2 + s)) * BBYTES;
    *(uint4*)(base + swz(r, kcs)) = h;
}

// gather + fp16 X -> g_xg [tile][stage 16][row 128][256B swz]
__global__ void gather_x(const float* __restrict__ x) {
    int id = blockIdx.x * 256 + threadIdx.x;
    int p = id >> 8;
    int kc = id & 255;
    if (p >= PSLOTS) return;
    int tok = g_tok_of_slot[p];
    const float4* s4 = (const float4*)(x + (size_t)tok * D_DIM + kc * 8);
    float4 v0 = s4[0], v1 = s4[1];
    uint4 h;
    h.x = pack2h(v0.x, v0.y); h.y = pack2h(v0.z, v0.w);
    h.z = pack2h(v1.x, v1.y); h.w = pack2h(v1.z, v1.w);
    int tile = p >> 7, r = p & 127;
    int s = kc >> 4, kcs = kc & 15;
    char* base = g_xg + ((size_t)(tile * NS1 + s)) * ABYTES;
    *(uint4*)(base + swz(r, kcs)) = h;
}

__global__ void router_kernel(const float* __restrict__ x,
                              const float* __restrict__ wr, int T) {
    int warp = threadIdx.x >> 5;
    int lane = threadIdx.x & 31;
    int t = blockIdx.x * 8 + warp;
    if (t >= T) return;

    const float4* x4 = (const float4*)(x + (size_t)t * D_DIM);
    const float4* w4 = (const float4*)wr;
    float acc[E_NUM];
#pragma unroll
    for (int e = 0; e < E_NUM; e++) acc[e] = 0.f;
    for (int d4 = lane; d4 < D_DIM / 4; d4 += 32) {
        float4 xv = x4[d4];
#pragma unroll
        for (int e = 0; e < E_NUM; e++) {
            float4 wv = w4[e * (D_DIM / 4) + d4];
            acc[e] += xv.x * wv.x + xv.y * wv.y + xv.z * wv.z + xv.w * wv.w;
        }
    }
#pragma unroll
    for (int e = 0; e < E_NUM; e++) {
#pragma unroll
        for (int o = 16; o > 0; o >>= 1)
            acc[e] += __shfl_xor_sync(0xffffffffu, acc[e], o);
    }
    if (lane == 0) {
        float s0 = -1e30f, s1 = -1e30f;
        int i0 = 0, i1 = 0;
#pragma unroll
        for (int e = 0; e < E_NUM; e++) {
            float v = acc[e];
            if (v > s0) { s1 = s0; i1 = i0; s0 = v; i0 = e; }
            else if (v > s1) { s1 = v; i1 = e; }
        }
        float p1 = expf(s1 - s0);
        float inv = 1.f / (1.f + p1);
        g_topk_idx[2 * t] = i0;
        g_topk_idx[2 * t + 1] = i1;
        g_topk_w[2 * t] = inv;
        g_topk_w[2 * t + 1] = p1 * inv;
        atomicAdd(&g_cnt[i0], 1);
        atomicAdd(&g_cnt[i1], 1);
    }
}

__global__ void offsets_kernel() {
    if (threadIdx.x == 0) {
        int op = 0;
        for (int e = 0; e < E_NUM; e++) {
            g_off_pad[e] = op;
            op += ((g_cnt[e] + 127) >> 7) << 7;
            g_cursor[e] = 0;
        }
        g_off_pad[E_NUM] = op;
    }
}

__global__ void assign_kernel(int T) {
    int i = blockIdx.x * 256 + threadIdx.x;
    if (i >= 2 * T) return;
    int e = g_topk_idx[i];
    int pos = atomicAdd(&g_cursor[e], 1);
    int slot = g_off_pad[e] + pos;
    g_tok_of_slot[slot] = i >> 1;
    g_slot_of[i] = slot;
}

// ---- mainloop compute for one K-stage (KT=128), warp tile 32x64, single fp16 ----
__device__ __forceinline__ void stage_mma(uint32_t stg, int wm, int wn, int lane,
                                          float acc[16][4]) {
    uint32_t rs = (uint32_t)(lane & 7);
    uint32_t rowA0 = (uint32_t)(wm * 32 + (lane & 7) + ((lane >> 3) & 1) * 8);
    uint32_t rowB  = (uint32_t)(wn * 64 + (lane & 7) + ((lane >> 4) & 1) * 8);
    uint32_t cbA = (uint32_t)(lane >> 4);
    uint32_t cbB = (uint32_t)((lane >> 3) & 1);
    uint32_t aA0 = stg + rowA0 * 256;
    uint32_t aA1 = aA0 + 16 * 256;
    uint32_t aB  = stg + (uint32_t)ABYTES + rowB * 256;
#pragma unroll
    for (int ks = 0; ks < 8; ks++) {
        uint32_t chA = ((cbA + (uint32_t)(ks * 2)) ^ rs) << 4;
        uint32_t chB = ((cbB + (uint32_t)(ks * 2)) ^ rs) << 4;
        uint32_t ah[2][4];
        ldsm4(ah[0], aA0 + chA);
        ldsm4(ah[1], aA1 + chA);
        uint32_t bh[4][4];
#pragma unroll
        for (int g2 = 0; g2 < 4; g2++)
            ldsm4(bh[g2], aB + (uint32_t)g2 * (16 * 256) + chB);
        // 16 independent MMAs
#pragma unroll
        for (int g2 = 0; g2 < 4; g2++)
#pragma unroll
            for (int t = 0; t < 2; t++) {
                mma_f16(acc[t * 8 + g2 * 2 + 0], ah[t], bh[g2][0], bh[g2][1]);
                mma_f16(acc[t * 8 + g2 * 2 + 1], ah[t], bh[g2][2], bh[g2][3]);
            }
    }
}

// ================= GEMM1: H = SwiGLU(X Wg^T, X Wu^T) =================
__global__ __launch_bounds__(256, 1) void gemm1_mma() {
    int e = blockIdx.z;
    int cnt = g_cnt[e];
    int m0 = blockIdx.y * 128;
    if (m0 >= cnt) return;
    int off_pad = g_off_pad[e];
    int tile = (off_pad >> 7) + blockIdx.y;
    int f0 = blockIdx.x * 64;

    extern __shared__ __align__(16) char smem[];
    uint32_t sb = smem_u32(smem);
    int tid = threadIdx.x, w = tid >> 5, lane = tid & 31;
    int wm = w >> 1, wn = w & 1;

    const char* aSrc = g_xg + (size_t)tile * NS1 * ABYTES;
    const char* bSrc = g_w1p + (size_t)((e * 12 + blockIdx.x) * NS1) * BBYTES;

    if (tid < NSTG) MBARRIER_INIT(sb + tid * 16, 1);
    __syncthreads();

#pragma unroll
    for (int s = 0; s < NSTG; s++) {
        if (tid == 0) {
            MBARRIER_EXPECT_TX(sb + s * 16, STG_BYTES);
            uint32_t db = sb + 1024 + (uint32_t)s * STG_BYTES;
            bulk_ld(db, aSrc + (size_t)s * ABYTES, ABYTES, sb + s * 16);
            bulk_ld(db + ABYTES, bSrc + (size_t)s * BBYTES, BBYTES, sb + s * 16);
        }
    }

    float acc[16][4];
#pragma unroll
    for (int g = 0; g < 16; g++)
#pragma unroll
        for (int i = 0; i < 4; i++) acc[g][i] = 0.f;

    for (int s = 0; s < NS1; s++) {
        int b = s % NSTG;
        MBARRIER_WAIT_PARITY(sb + b * 16, (s / NSTG) & 1);
        stage_mma(sb + 1024 + (uint32_t)b * STG_BYTES, wm, wn, lane, acc);
        __syncthreads();
        if (s + NSTG < NS1 && tid == 0) {
            MBARRIER_EXPECT_TX(sb + b * 16, STG_BYTES);
            uint32_t db = sb + 1024 + (uint32_t)b * STG_BYTES;
            bulk_ld(db, aSrc + (size_t)(s + NSTG) * ABYTES, ABYTES, sb + b * 16);
            bulk_ld(db + ABYTES, bSrc + (size_t)(s + NSTG) * BBYTES, BBYTES, sb + b * 16);
        }
    }

    // epilogue: SwiGLU + fp16 H into g_hp (A layout for GEMM2, KT=128 stages)
    int q = lane >> 2, t4 = lane & 3;
    char* hBase = g_hp + (size_t)tile * NS2 * ABYTES;
#pragma unroll
    for (int t = 0; t < 2; t++) {
        int rl0 = wm * 32 + t * 16 + q;
        int rl1 = rl0 + 8;
#pragma unroll
        for (int g = 0; g < 4; g++) {
            int f = f0 + wn * 32 + g * 8 + t4 * 2;
            int s2 = f >> 7;
            int fl = f & 127;
            int chunk = fl >> 3;
            int inc = (2 * fl) & 15;
            const float* ga = acc[t * 8 + g];
            const float* ua = acc[t * 8 + 4 + g];
            char* sbase = hBase + (size_t)s2 * ABYTES;
            if (m0 + rl0 < cnt) {
                float g0 = ga[0], g1 = ga[1], u0 = ua[0], u1 = ua[1];
                float h0 = g0 / (1.f + __expf(-g0)) * u0;
                float h1 = g1 / (1.f + __expf(-g1)) * u1;
                *(uint32_t*)(sbase + swz(rl0, chunk) + inc) = pack2h(h0, h1);
            }
            if (m0 + rl1 < cnt) {
                float g0 = ga[2], g1 = ga[3], u0 = ua[2], u1 = ua[3];
                float h0 = g0 / (1.f + __expf(-g0)) * u0;
                float h1 = g1 / (1.f + __expf(-g1)) * u1;
                *(uint32_t*)(sbase + swz(rl1, chunk) + inc) = pack2h(h0, h1);
            }
        }
    }
}

// ================= GEMM2: O = H Wd^T =================
__global__ __launch_bounds__(256, 1) void gemm2_mma() {
    int e = blockIdx.z;
    int cnt = g_cnt[e];
    int m0 = blockIdx.y * 128;
    if (m0 >= cnt) return;
    int off_pad = g_off_pad[e];
    int tile = (off_pad >> 7) + blockIdx.y;
    int n0 = blockIdx.x * 128;

    extern __shared__ __align__(16) char smem[];
    uint32_t sb = smem_u32(smem);
    int tid = threadIdx.x, w = tid >> 5, lane = tid & 31;
    int wm = w >> 1, wn = w & 1;

    const char* aSrc = g_hp + (size_t)tile * NS2 * ABYTES;
    const char* bSrc = g_w2p + (size_t)((e * 16 + blockIdx.x) * NS2) * BBYTES;

    if (tid < NSTG) MBARRIER_INIT(sb + tid * 16, 1);
    __syncthreads();

#pragma unroll
    for (int s = 0; s < NSTG; s++) {
        if (tid == 0) {
            MBARRIER_EXPECT_TX(sb + s * 16, STG_BYTES);
            uint32_t db = sb + 1024 + (uint32_t)s * STG_BYTES;
            bulk_ld(db, aSrc + (size_t)s * ABYTES, ABYTES, sb + s * 16);
            bulk_ld(db + ABYTES, bSrc + (size_t)s * BBYTES, BBYTES, sb + s * 16);
        }
    }

    float acc[16][4];
#pragma unroll
    for (int g = 0; g < 16; g++)
#pragma unroll
        for (int i = 0; i < 4; i++) acc[g][i] = 0.f;

    for (int s = 0; s < NS2; s++) {
        int b = s % NSTG;
        MBARRIER_WAIT_PARITY(sb + b * 16, (s / NSTG) & 1);
        stage_mma(sb + 1024 + (uint32_t)b * STG_BYTES, wm, wn, lane, acc);
        __syncthreads();
        if (s + NSTG < NS2 && tid == 0) {
            MBARRIER_EXPECT_TX(sb + b * 16, STG_BYTES);
            uint32_t db = sb + 1024 + (uint32_t)b * STG_BYTES;
            bulk_ld(db, aSrc + (size_t)(s + NSTG) * ABYTES, ABYTES, sb + b * 16);
            bulk_ld(db + ABYTES, bSrc + (size_t)(s + NSTG) * BBYTES, BBYTES, sb + b * 16);
        }
    }

    // epilogue: fp32 store to g_O (padded-slot rows)
    int q = lane >> 2, t4 = lane & 3;
#pragma unroll
    for (int t = 0; t < 2; t++) {
        int rl0 = wm * 32 + t * 16 + q;
        int rl1 = rl0 + 8;
#pragma unroll
        for (int g = 0; g < 8; g++) {
            int ni = n0 + wn * 64 + g * 8 + t4 * 2;
            if (m0 + rl0 < cnt) {
                float2 v; v.x = acc[t * 8 + g][0]; v.y = acc[t * 8 + g][1];
                *(float2*)&g_O[(size_t)(off_pad + m0 + rl0) * D_DIM + ni] = v;
            }
            if (m0 + rl1 < cnt) {
                float2 v; v.x = acc[t * 8 + g][2]; v.y = acc[t * 8 + g][3];
                *(float2*)&g_O[(size_t)(off_pad + m0 + rl1) * D_DIM + ni] = v;
            }
        }
    }
}

// ---------------- combine ----------------
__global__ void combine_kernel(float* __restrict__ out, int T) {
    int t = blockIdx.x;
    int d4 = blockIdx.y * blockDim.x + threadIdx.x;
    float w0 = g_topk_w[2 * t];
    float w1 = g_topk_w[2 * t + 1];
    int s0 = g_slot_of[2 * t];
    int s1 = g_slot_of[2 * t + 1];
    float4 a = ((const float4*)&g_O[(size_t)s0 * D_DIM])[d4];
    float4 b = ((const float4*)&g_O[(size_t)s1 * D_DIM])[d4];
    float4 r;
    r.x = w0 * a.x + w1 * b.x;
    r.y = w0 * a.y + w1 * b.y;
    r.z = w0 * a.z + w1 * b.z;
    r.w = w0 * a.w + w1 * b.w;
    ((float4*)out)[(size_t)t * (D_DIM / 4) + d4] = r;
}

// ---------------- launch ----------------
extern "C" void kernel_launch(void* const* d_in, const int* in_sizes, int n_in,
                              void* d_out, int out_size) {
    const float* x  = (const float*)d_in[0];
    const float* wr = (const float*)d_in[1];
    const float* wg = (const float*)d_in[2];
    const float* wu = (const float*)d_in[3];
    const float* wd = (const float*)d_in[4];
    int T = in_sizes[0] / D_DIM;  // 2048

    cudaFuncSetAttribute(gemm1_mma, cudaFuncAttributeMaxDynamicSharedMemorySize, SMEM_TOTAL);
    cudaFuncSetAttribute(gemm2_mma, cudaFuncAttributeMaxDynamicSharedMemorySize, SMEM_TOTAL);

    reset_kernel<<<1, 32>>>();
    prefill_kernel<<<(PSLOTS + 255) / 256, 256>>>();

    int nw1 = E_NUM * F_DIM * 256;
    int nw2 = E_NUM * D_DIM * 96;
    convert_w1<<<(nw1 + 255) / 256, 256>>>(wg, 0, nw1);
    convert_w1<<<(nw1 + 255) / 256, 256>>>(wu, 1, nw1);
    convert_w2<<<(nw2 + 255) / 256, 256>>>(wd, nw2);

    router_kernel<<<(T + 7) / 8, 256>>>(x, wr, T);
    offsets_kernel<<<1, 1>>>();
    assign_kernel<<<(2 * T + 255) / 256, 256>>>(T);
    gather_x<<<(PSLOTS * 256) / 256, 256>>>(x);

    dim3 g1(F_DIM / 64, 16, E_NUM);
    gemm1_mma<<<g1, 256, SMEM_TOTAL>>>();

    dim3 g2(D_DIM / 128, 16, E_NUM);
    gemm2_mma<<<g2, 256, SMEM_TOTAL>>>();

    combine_kernel<<<dim3(T, 2), 256>>>((float*)d_out, T);
}

// round 11
// speedup vs baseline: 5.5080x; 1.0296x over previous
#include <cuda_runtime.h>
#include <cuda_bf16.h>
#include <cuda_fp16.h>
#include <cstdint>

#define D_DIM 2048
#define E_NUM 8
#define F_DIM 768
#define T_MAX 2048
#define PSLOTS 5120            // padded slots (each expert padded to 128)
#define NTILES 40              // PSLOTS / 128

#define KT 64
#define NS1 32                 // D_DIM / KT
#define NS2 12                 // F_DIM / KT
#define ABYTES 16384           // A stage block: 128 rows x 128B (fp16)
#define BBYTES 16384           // B stage block: 128 rows x 128B (fp16)
#define STG_BYTES 32768
#define NSTG 3
#define SMEM_TOTAL (1024 + NSTG * STG_BYTES)   // 99328 -> 2 CTAs/SM

// ---------------- static device scratch ----------------
__device__ int   g_cnt[E_NUM];
__device__ int   g_cursor[E_NUM];
__device__ int   g_off_pad[E_NUM + 1];
__device__ int   g_topk_idx[2 * T_MAX];
__device__ float g_topk_w[2 * T_MAX];
__device__ int   g_tok_of_slot[PSLOTS];
__device__ int   g_slot_of[2 * T_MAX];

// stage-major packed operands, in-layout swizzled (chunk ^= row&7)
__device__ __align__(16) char g_w1p[(size_t)E_NUM * 12 * NS1 * BBYTES];   // gate+up fp16
__device__ __align__(16) char g_w2p[(size_t)E_NUM * 16 * NS2 * BBYTES];   // down fp16
__device__ __align__(16) char g_xg[(size_t)NTILES * NS1 * ABYTES];        // X fp16
__device__ __align__(16) char g_hp[(size_t)NTILES * NS2 * ABYTES];        // H fp16
__device__ float g_O[(size_t)PSLOTS * D_DIM];

// ---------------- helpers ----------------
__device__ __forceinline__ uint32_t smem_u32(const void* p) {
    uint32_t a;
    asm("{ .reg .u64 t; cvta.to.shared.u64 t, %1; cvt.u32.u64 %0, t; }" : "=r"(a) : "l"(p));
    return a;
}
// rows: 128B, 8 chunks of 16B (XOR over all 3 chunk bits)
__device__ __forceinline__ uint32_t swz(uint32_t row, uint32_t chunk) {
    return row * 128u + ((chunk ^ (row & 7u)) << 4);
}
__device__ __forceinline__ void ldsm4(uint32_t* r, uint32_t addr) {
    asm volatile("ldmatrix.sync.aligned.m8n8.x4.shared.b16 {%0,%1,%2,%3}, [%4];"
        : "=r"(r[0]), "=r"(r[1]), "=r"(r[2]), "=r"(r[3]) : "r"(addr));
}
__device__ __forceinline__ void bulk_ld(uint32_t dst, const void* src, uint32_t bytes, uint32_t mbar) {
    asm volatile(
        "cp.async.bulk.shared::cluster.global.mbarrier::complete_tx::bytes [%0], [%1], %2, [%3];"
        :: "r"(dst), "l"(src), "r"(bytes), "r"(mbar) : "memory");
}
#define MBARRIER_INIT(addr, cnt) \
    asm volatile("mbarrier.init.shared.b64 [%0], %1;" :: "r"((uint32_t)(addr)), "r"((uint32_t)(cnt)) : "memory")
#define MBARRIER_EXPECT_TX(addr, bytes) \
    asm volatile("mbarrier.arrive.expect_tx.shared.b64 _, [%0], %1;" :: "r"((uint32_t)(addr)), "r"((uint32_t)(bytes)) : "memory")
#define MBARRIER_WAIT_PARITY(mbar_smem_addr, phase_parity) do { \
    uint32_t _mbar = (uint32_t)(mbar_smem_addr); \
    uint32_t _parity = (uint32_t)(phase_parity); \
    uint32_t _done; \
    asm volatile( \
        "{\n\t.reg .pred p;\n\t" \
        "mbarrier.try_wait.parity.acquire.cta.shared::cta.b64 p, [%1], %2;\n\t" \
        "selp.b32 %0, 1, 0, p;\n\t}" \
        : "=r"(_done) : "r"(_mbar), "r"(_parity) : "memory"); \
    if (!_done) { \
        asm volatile( \
            "{\n\t.reg .pred P1;\n\t" \
            "WAIT_LOOP_%=:\n\t" \
            "mbarrier.try_wait.parity.acquire.cta.shared::cta.b64 P1, [%0], %1, 0x989680;\n\t" \
            "@P1 bra.uni WAIT_DONE_%=;\n\t" \
            "bra.uni WAIT_LOOP_%=;\n\t" \
            "WAIT_DONE_%=:\n\t}" \
            :: "r"(_mbar), "r"(_parity) : "memory"); \
    } \
} while (0)

__device__ __forceinline__ void mma_f16(float* c, const uint32_t* a, uint32_t b0, uint32_t b1) {
    asm volatile(
        "mma.sync.aligned.m16n8k16.row.col.f32.f16.f16.f32 "
        "{%0,%1,%2,%3}, {%4,%5,%6,%7}, {%8,%9}, {%0,%1,%2,%3};"
        : "+f"(c[0]), "+f"(c[1]), "+f"(c[2]), "+f"(c[3])
        : "r"(a[0]), "r"(a[1]), "r"(a[2]), "r"(a[3]), "r"(b0), "r"(b1));
}
__device__ __forceinline__ uint32_t pack2h(float a, float b) {
    __half2 hh;
    hh.x = __float2half_rn(a);
    hh.y = __float2half_rn(b);
    return *(uint32_t*)&hh;
}

// ---------------- small kernels ----------------
__global__ void reset_kernel() {
    if (threadIdx.x < E_NUM) g_cnt[threadIdx.x] = 0;
}
__global__ void prefill_kernel() {
    int i = blockIdx.x * 256 + threadIdx.x;
    if (i < PSLOTS) g_tok_of_slot[i] = 0;
}

// gate/up weights -> g_w1p  [e][ftile 12][stage 32][row 128][128B swz] (fp16)
__global__ void convert_w1(const float* __restrict__ src, int isUp, int njobs) {
    int id = blockIdx.x * 256 + threadIdx.x;
    if (id >= njobs) return;
    int e = id / (F_DIM * 256);
    int rem = id - e * (F_DIM * 256);
    int f = rem >> 8;
    int kc = rem & 255;
    const float4* s4 = (const float4*)(src + ((size_t)e * F_DIM + f) * D_DIM + kc * 8);
    float4 v0 = s4[0], v1 = s4[1];
    uint4 h;
    h.x = pack2h(v0.x, v0.y); h.y = pack2h(v0.z, v0.w);
    h.z = pack2h(v1.x, v1.y); h.w = pack2h(v1.z, v1.w);
    int ftile = f >> 6, fl = f & 63;
    int wn = fl >> 5, idx = fl & 31;
    int r = wn * 64 + (isUp ? 32 : 0) + idx;
    int s = kc >> 3, kcs = kc & 7;
    char* base = g_w1p + ((size_t)((e * 12 + ftile) * NS1 + s)) * BBYTES;
    *(uint4*)(base + swz(r, kcs)) = h;
}

// down weights -> g_w2p  [e][ntile 16][stage 12][row 128][128B swz] (fp16)
__global__ void convert_w2(const float* __restrict__ src, int njobs) {
    int id = blockIdx.x * 256 + threadIdx.x;
    if (id >= njobs) return;
    int e = id / (D_DIM * 96);
    int rem = id - e * (D_DIM * 96);
    int n = rem / 96;
    int kc = rem - n * 96;
    const float4* s4 = (const float4*)(src + ((size_t)e * D_DIM + n) * F_DIM + kc * 8);
    float4 v0 = s4[0], v1 = s4[1];
    uint4 h;
    h.x = pack2h(v0.x, v0.y); h.y = pack2h(v0.z, v0.w);
    h.z = pack2h(v1.x, v1.y); h.w = pack2h(v1.z, v1.w);
    int ntile = n >> 7, r = n & 127;
    int s = kc >> 3, kcs = kc & 7;
    char* base = g_w2p + ((size_t)((e * 16 + ntile) * NS2 + s)) * BBYTES;
    *(uint4*)(base + swz(r, kcs)) = h;
}

// gather + fp16 X -> g_xg [tile][stage 32][row 128][128B swz]
__global__ void gather_x(const float* __restrict__ x) {
    int id = blockIdx.x * 256 + threadIdx.x;
    int p = id >> 8;
    int kc = id & 255;
    if (p >= PSLOTS) return;
    int tok = g_tok_of_slot[p];
    const float4* s4 = (const float4*)(x + (size_t)tok * D_DIM + kc * 8);
    float4 v0 = s4[0], v1 = s4[1];
    uint4 h;
    h.x = pack2h(v0.x, v0.y); h.y = pack2h(v0.z, v0.w);
    h.z = pack2h(v1.x, v1.y); h.w = pack2h(v1.z, v1.w);
    int tile = p >> 7, r = p & 127;
    int s = kc >> 3, kcs = kc & 7;
    char* base = g_xg + ((size_t)(tile * NS1 + s)) * ABYTES;
    *(uint4*)(base + swz(r, kcs)) = h;
}

__global__ void router_kernel(const float* __restrict__ x,
                              const float* __restrict__ wr, int T) {
    int warp = threadIdx.x >> 5;
    int lane = threadIdx.x & 31;
    int t = blockIdx.x * 8 + warp;
    if (t >= T) return;

    const float4* x4 = (const float4*)(x + (size_t)t * D_DIM);
    const float4* w4 = (const float4*)wr;
    float acc[E_NUM];
#pragma unroll
    for (int e = 0; e < E_NUM; e++) acc[e] = 0.f;
    for (int d4 = lane; d4 < D_DIM / 4; d4 += 32) {
        float4 xv = x4[d4];
#pragma unroll
        for (int e = 0; e < E_NUM; e++) {
            float4 wv = w4[e * (D_DIM / 4) + d4];
            acc[e] += xv.x * wv.x + xv.y * wv.y + xv.z * wv.z + xv.w * wv.w;
        }
    }
#pragma unroll
    for (int e = 0; e < E_NUM; e++) {
#pragma unroll
        for (int o = 16; o > 0; o >>= 1)
            acc[e] += __shfl_xor_sync(0xffffffffu, acc[e], o);
    }
    if (lane == 0) {
        float s0 = -1e30f, s1 = -1e30f;
        int i0 = 0, i1 = 0;
#pragma unroll
        for (int e = 0; e < E_NUM; e++) {
            float v = acc[e];
            if (v > s0) { s1 = s0; i1 = i0; s0 = v; i0 = e; }
            else if (v > s1) { s1 = v; i1 = e; }
        }
        float p1 = expf(s1 - s0);
        float inv = 1.f / (1.f + p1);
        g_topk_idx[2 * t] = i0;
        g_topk_idx[2 * t + 1] = i1;
        g_topk_w[2 * t] = inv;
        g_topk_w[2 * t + 1] = p1 * inv;
        atomicAdd(&g_cnt[i0], 1);
        atomicAdd(&g_cnt[i1], 1);
    }
}

__global__ void offsets_kernel() {
    if (threadIdx.x == 0) {
        int op = 0;
        for (int e = 0; e < E_NUM; e++) {
            g_off_pad[e] = op;
            op += ((g_cnt[e] + 127) >> 7) << 7;
            g_cursor[e] = 0;
        }
        g_off_pad[E_NUM] = op;
    }
}

__global__ void assign_kernel(int T) {
    int i = blockIdx.x * 256 + threadIdx.x;
    if (i >= 2 * T) return;
    int e = g_topk_idx[i];
    int pos = atomicAdd(&g_cursor[e], 1);
    int slot = g_off_pad[e] + pos;
    g_tok_of_slot[slot] = i >> 1;
    g_slot_of[i] = slot;
}

// ---- mainloop compute for one K-stage (KT=64), warp tile 32x64, single fp16 ----
__device__ __forceinline__ void stage_mma(uint32_t stg, int wm, int wn, int lane,
                                          float acc[16][4]) {
    uint32_t rs = (uint32_t)(lane & 7);
    uint32_t rowA0 = (uint32_t)(wm * 32 + (lane & 7) + ((lane >> 3) & 1) * 8);
    uint32_t rowB  = (uint32_t)(wn * 64 + (lane & 7) + ((lane >> 4) & 1) * 8);
    uint32_t cbA = (uint32_t)(lane >> 4);
    uint32_t cbB = (uint32_t)((lane >> 3) & 1);
    uint32_t aA0 = stg + rowA0 * 128;
    uint32_t aA1 = aA0 + 16 * 128;
    uint32_t aB  = stg + (uint32_t)ABYTES + rowB * 128;
#pragma unroll
    for (int ks = 0; ks < 4; ks++) {
        uint32_t chA = ((cbA + (uint32_t)(ks * 2)) ^ rs) << 4;
        uint32_t chB = ((cbB + (uint32_t)(ks * 2)) ^ rs) << 4;
        uint32_t ah[2][4];
        ldsm4(ah[0], aA0 + chA);
        ldsm4(ah[1], aA1 + chA);
        uint32_t bh[4][4];
#pragma unroll
        for (int g2 = 0; g2 < 4; g2++)
            ldsm4(bh[g2], aB + (uint32_t)g2 * (16 * 128) + chB);
        // 16 independent MMAs
#pragma unroll
        for (int g2 = 0; g2 < 4; g2++)
#pragma unroll
            for (int t = 0; t < 2; t++) {
                mma_f16(acc[t * 8 + g2 * 2 + 0], ah[t], bh[g2][0], bh[g2][1]);
                mma_f16(acc[t * 8 + g2 * 2 + 1], ah[t], bh[g2][2], bh[g2][3]);
            }
    }
}

// ================= GEMM1: H = SwiGLU(X Wg^T, X Wu^T) =================
__global__ __launch_bounds__(256, 2) void gemm1_mma() {
    int e = blockIdx.z;
    int cnt = g_cnt[e];
    int m0 = blockIdx.y * 128;
    if (m0 >= cnt) return;
    int off_pad = g_off_pad[e];
    int tile = (off_pad >> 7) + blockIdx.y;
    int f0 = blockIdx.x * 64;

    extern __shared__ __align__(16) char smem[];
    uint32_t sb = smem_u32(smem);
    int tid = threadIdx.x, w = tid >> 5, lane = tid & 31;
    int wm = w >> 1, wn = w & 1;

    const char* aSrc = g_xg + (size_t)tile * NS1 * ABYTES;
    const char* bSrc = g_w1p + (size_t)((e * 12 + blockIdx.x) * NS1) * BBYTES;

    if (tid < NSTG) MBARRIER_INIT(sb + tid * 16, 1);
    __syncthreads();

#pragma unroll
    for (int s = 0; s < NSTG; s++) {
        if (tid == 0) {
            MBARRIER_EXPECT_TX(sb + s * 16, STG_BYTES);
            uint32_t db = sb + 1024 + (uint32_t)s * STG_BYTES;
            bulk_ld(db, aSrc + (size_t)s * ABYTES, ABYTES, sb + s * 16);
            bulk_ld(db + ABYTES, bSrc + (size_t)s * BBYTES, BBYTES, sb + s * 16);
        }
    }

    float acc[16][4];
#pragma unroll
    for (int g = 0; g < 16; g++)
#pragma unroll
        for (int i = 0; i < 4; i++) acc[g][i] = 0.f;

    for (int s = 0; s < NS1; s++) {
        int b = s % NSTG;
        MBARRIER_WAIT_PARITY(sb + b * 16, (s / NSTG) & 1);
        stage_mma(sb + 1024 + (uint32_t)b * STG_BYTES, wm, wn, lane, acc);
        __syncthreads();
        if (s + NSTG < NS1 && tid == 0) {
            MBARRIER_EXPECT_TX(sb + b * 16, STG_BYTES);
            uint32_t db = sb + 1024 + (uint32_t)b * STG_BYTES;
            bulk_ld(db, aSrc + (size_t)(s + NSTG) * ABYTES, ABYTES, sb + b * 16);
            bulk_ld(db + ABYTES, bSrc + (size_t)(s + NSTG) * BBYTES, BBYTES, sb + b * 16);
        }
    }

    // epilogue: SwiGLU + fp16 H into g_hp (A layout for GEMM2, KT=64 stages)
    int q = lane >> 2, t4 = lane & 3;
    char* hBase = g_hp + (size_t)tile * NS2 * ABYTES;
#pragma unroll
    for (int t = 0; t < 2; t++) {
        int rl0 = wm * 32 + t * 16 + q;
        int rl1 = rl0 + 8;
#pragma unroll
        for (int g = 0; g < 4; g++) {
            int f = f0 + wn * 32 + g * 8 + t4 * 2;
            int s2 = f >> 6;
            int fl = f & 63;
            int chunk = fl >> 3;          // (2*fl)>>4, in 0..7
            int inc = (2 * fl) & 15;
            const float* ga = acc[t * 8 + g];
            const float* ua = acc[t * 8 + 4 + g];
            char* sbase = hBase + (size_t)s2 * ABYTES;
            if (m0 + rl0 < cnt) {
                float g0 = ga[0], g1 = ga[1], u0 = ua[0], u1 = ua[1];
                float h0 = g0 / (1.f + __expf(-g0)) * u0;
                float h1 = g1 / (1.f + __expf(-g1)) * u1;
                *(uint32_t*)(sbase + swz(rl0, chunk) + inc) = pack2h(h0, h1);
            }
            if (m0 + rl1 < cnt) {
                float g0 = ga[2], g1 = ga[3], u0 = ua[2], u1 = ua[3];
                float h0 = g0 / (1.f + __expf(-g0)) * u0;
                float h1 = g1 / (1.f + __expf(-g1)) * u1;
                *(uint32_t*)(sbase + swz(rl1, chunk) + inc) = pack2h(h0, h1);
            }
        }
    }
}

// ================= GEMM2: O = H Wd^T =================
__global__ __launch_bounds__(256, 2) void gemm2_mma() {
    int e = blockIdx.z;
    int cnt = g_cnt[e];
    int m0 = blockIdx.y * 128;
    if (m0 >= cnt) return;
    int off_pad = g_off_pad[e];
    int tile = (off_pad >> 7) + blockIdx.y;
    int n0 = blockIdx.x * 128;

    extern __shared__ __align__(16) char smem[];
    uint32_t sb = smem_u32(smem);
    int tid = threadIdx.x, w = tid >> 5, lane = tid & 31;
    int wm = w >> 1, wn = w & 1;

    const char* aSrc = g_hp + (size_t)tile * NS2 * ABYTES;
    const char* bSrc = g_w2p + (size_t)((e * 16 + blockIdx.x) * NS2) * BBYTES;

    if (tid < NSTG) MBARRIER_INIT(sb + tid * 16, 1);
    __syncthreads();

#pragma unroll
    for (int s = 0; s < NSTG; s++) {
        if (tid == 0) {
            MBARRIER_EXPECT_TX(sb + s * 16, STG_BYTES);
            uint32_t db = sb + 1024 + (uint32_t)s * STG_BYTES;
            bulk_ld(db, aSrc + (size_t)s * ABYTES, ABYTES, sb + s * 16);
            bulk_ld(db + ABYTES, bSrc + (size_t)s * BBYTES, BBYTES, sb + s * 16);
        }
    }

    float acc[16][4];
#pragma unroll
    for (int g = 0; g < 16; g++)
#pragma unroll
        for (int i = 0; i < 4; i++) acc[g][i] = 0.f;

    for (int s = 0; s < NS2; s++) {
        int b = s % NSTG;
        MBARRIER_WAIT_PARITY(sb + b * 16, (s / NSTG) & 1);
        stage_mma(sb + 1024 + (uint32_t)b * STG_BYTES, wm, wn, lane, acc);
        __syncthreads();
        if (s + NSTG < NS2 && tid == 0) {
            MBARRIER_EXPECT_TX(sb + b * 16, STG_BYTES);
            uint32_t db = sb + 1024 + (uint32_t)b * STG_BYTES;
            bulk_ld(db, aSrc + (size_t)(s + NSTG) * ABYTES, ABYTES, sb + b * 16);
            bulk_ld(db + ABYTES, bSrc + (size_t)(s + NSTG) * BBYTES, BBYTES, sb + b * 16);
        }
    }

    // epilogue: fp32 store to g_O (padded-slot rows)
    int q = lane >> 2, t4 = lane & 3;
#pragma unroll
    for (int t = 0; t < 2; t++) {
        int rl0 = wm * 32 + t * 16 + q;
        int rl1 = rl0 + 8;
#pragma unroll
        for (int g = 0; g < 8; g++) {
            int ni = n0 + wn * 64 + g * 8 + t4 * 2;
            if (m0 + rl0 < cnt) {
                float2 v; v.x = acc[t * 8 + g][0]; v.y = acc[t * 8 + g][1];
                *(float2*)&g_O[(size_t)(off_pad + m0 + rl0) * D_DIM + ni] = v;
            }
            if (m0 + rl1 < cnt) {
                float2 v; v.x = acc[t * 8 + g][2]; v.y = acc[t * 8 + g][3];
                *(float2*)&g_O[(size_t)(off_pad + m0 + rl1) * D_DIM + ni] = v;
            }
        }
    }
}

// ---------------- combine ----------------
__global__ void combine_kernel(float* __restrict__ out, int T) {
    int t = blockIdx.x;
    int d4 = blockIdx.y * blockDim.x + threadIdx.x;
    float w0 = g_topk_w[2 * t];
    float w1 = g_topk_w[2 * t + 1];
    int s0 = g_slot_of[2 * t];
    int s1 = g_slot_of[2 * t + 1];
    float4 a = ((const float4*)&g_O[(size_t)s0 * D_DIM])[d4];
    float4 b = ((const float4*)&g_O[(size_t)s1 * D_DIM])[d4];
    float4 r;
    r.x = w0 * a.x + w1 * b.x;
    r.y = w0 * a.y + w1 * b.y;
    r.z = w0 * a.z + w1 * b.z;
    r.w = w0 * a.w + w1 * b.w;
    ((float4*)out)[(size_t)t * (D_DIM / 4) + d4] = r;
}

// ---------------- launch ----------------
extern "C" void kernel_launch(void* const* d_in, const int* in_sizes, int n_in,
                              void* d_out, int out_size) {
    const float* x  = (const float*)d_in[0];
    const float* wr = (const float*)d_in[1];
    const float* wg = (const float*)d_in[2];
    const float* wu = (const float*)d_in[3];
    const float* wd = (const float*)d_in[4];
    int T = in_sizes[0] / D_DIM;  // 2048

    cudaFuncSetAttribute(gemm1_mma, cudaFuncAttributeMaxDynamicSharedMemorySize, SMEM_TOTAL);
    cudaFuncSetAttribute(gemm2_mma, cudaFuncAttributeMaxDynamicSharedMemorySize, SMEM_TOTAL);

    reset_kernel<<<1, 32>>>();
    prefill_kernel<<<(PSLOTS + 255) / 256, 256>>>();

    int nw1 = E_NUM * F_DIM * 256;
    int nw2 = E_NUM * D_DIM * 96;
    convert_w1<<<(nw1 + 255) / 256, 256>>>(wg, 0, nw1);
    convert_w1<<<(nw1 + 255) / 256, 256>>>(wu, 1, nw1);
    convert_w2<<<(nw2 + 255) / 256, 256>>>(wd, nw2);

    router_kernel<<<(T + 7) / 8, 256>>>(x, wr, T);
    offsets_kernel<<<1, 1>>>();
    assign_kernel<<<(2 * T + 255) / 256, 256>>>(T);
    gather_x<<<(PSLOTS * 256) / 256, 256>>>(x);

    dim3 g1(F_DIM / 64, 16, E_NUM);
    gemm1_mma<<<g1, 256, SMEM_TOTAL>>>();

    dim3 g2(D_DIM / 128, 16, E_NUM);
    gemm2_mma<<<g2, 256, SMEM_TOTAL>>>();

    combine_kernel<<<dim3(T, 2), 256>>>((float*)d_out, T);
}

// round 13
// speedup vs baseline: 5.8490x; 1.0619x over previous
#include <cuda_runtime.h>
#include <cuda_bf16.h>
#include <cuda_fp16.h>
#include <cstdint>

#define D_DIM 2048
#define E_NUM 8
#define F_DIM 768
#define T_MAX 2048
#define PSLOTS 5120
#define NTILES_MAX 40

#define KT 64
#define NS1 32                 // D_DIM / KT
#define NS2 12                 // F_DIM / KT
#define ABYTES 16384           // 128 rows x 128B fp16
#define BBYTES 16384
#define STG_BYTES 32768
#define NSTG 3
#define SMEM_TOTAL (1024 + NSTG * STG_BYTES)   // ~99KB -> 2 CTAs/SM
#define NWORKERS 304

// ---------------- static device scratch ----------------
__device__ int   g_cnt[E_NUM];
__device__ int   g_cursor[E_NUM];
__device__ int   g_off_pad[E_NUM + 1];
__device__ int   g_topk_idx[2 * T_MAX];
__device__ float g_topk_w[2 * T_MAX];
__device__ int   g_tok_of_slot[PSLOTS];
__device__ int   g_slot_of[2 * T_MAX];
__device__ int   g_work;
__device__ int   g_done[NTILES_MAX];

__device__ __align__(16) char g_w1p[(size_t)E_NUM * 12 * NS1 * BBYTES];
__device__ __align__(16) char g_w2p[(size_t)E_NUM * 16 * NS2 * BBYTES];
__device__ __align__(16) char g_xg[(size_t)NTILES_MAX * NS1 * ABYTES];
__device__ __align__(16) char g_hp[(size_t)NTILES_MAX * NS2 * ABYTES];
__device__ float g_O[(size_t)PSLOTS * D_DIM];

// ---------------- helpers ----------------
__device__ __forceinline__ uint32_t smem_u32(const void* p) {
    uint32_t a;
    asm("{ .reg .u64 t; cvta.to.shared.u64 t, %1; cvt.u32.u64 %0, t; }" : "=r"(a) : "l"(p));
    return a;
}
__device__ __forceinline__ uint32_t swz(uint32_t row, uint32_t chunk) {
    return row * 128u + ((chunk ^ (row & 7u)) << 4);
}
__device__ __forceinline__ void ldsm4(uint32_t* r, uint32_t addr) {
    asm volatile("ldmatrix.sync.aligned.m8n8.x4.shared.b16 {%0,%1,%2,%3}, [%4];"
        : "=r"(r[0]), "=r"(r[1]), "=r"(r[2]), "=r"(r[3]) : "r"(addr));
}
__device__ __forceinline__ void bulk_ld(uint32_t dst, const void* src, uint32_t bytes, uint32_t mbar) {
    asm volatile(
        "cp.async.bulk.shared::cluster.global.mbarrier::complete_tx::bytes [%0], [%1], %2, [%3];"
        :: "r"(dst), "l"(src), "r"(bytes), "r"(mbar) : "memory");
}
#define MBARRIER_INIT(addr, cnt) \
    asm volatile("mbarrier.init.shared.b64 [%0], %1;" :: "r"((uint32_t)(addr)), "r"((uint32_t)(cnt)) : "memory")
#define MBARRIER_EXPECT_TX(addr, bytes) \
    asm volatile("mbarrier.arrive.expect_tx.shared.b64 _, [%0], %1;" :: "r"((uint32_t)(addr)), "r"((uint32_t)(bytes)) : "memory")
#define MBARRIER_WAIT_PARITY(mbar_smem_addr, phase_parity) do { \
    uint32_t _mbar = (uint32_t)(mbar_smem_addr); \
    uint32_t _parity = (uint32_t)(phase_parity); \
    uint32_t _done; \
    asm volatile( \
        "{\n\t.reg .pred p;\n\t" \
        "mbarrier.try_wait.parity.acquire.cta.shared::cta.b64 p, [%1], %2;\n\t" \
        "selp.b32 %0, 1, 0, p;\n\t}" \
        : "=r"(_done) : "r"(_mbar), "r"(_parity) : "memory"); \
    if (!_done) { \
        asm volatile( \
            "{\n\t.reg .pred P1;\n\t" \
            "WAIT_LOOP_%=:\n\t" \
            "mbarrier.try_wait.parity.acquire.cta.shared::cta.b64 P1, [%0], %1, 0x989680;\n\t" \
            "@P1 bra.uni WAIT_DONE_%=;\n\t" \
            "bra.uni WAIT_LOOP_%=;\n\t" \
            "WAIT_DONE_%=:\n\t}" \
            :: "r"(_mbar), "r"(_parity) : "memory"); \
    } \
} while (0)

__device__ __forceinline__ void mma_f16(float* c, const uint32_t* a, uint32_t b0, uint32_t b1) {
    asm volatile(
        "mma.sync.aligned.m16n8k16.row.col.f32.f16.f16.f32 "
        "{%0,%1,%2,%3}, {%4,%5,%6,%7}, {%8,%9}, {%0,%1,%2,%3};"
        : "+f"(c[0]), "+f"(c[1]), "+f"(c[2]), "+f"(c[3])
        : "r"(a[0]), "r"(a[1]), "r"(a[2]), "r"(a[3]), "r"(b0), "r"(b1));
}
__device__ __forceinline__ uint32_t pack2h(float a, float b) {
    __half2 hh;
    hh.x = __float2half_rn(a);
    hh.y = __float2half_rn(b);
    return *(uint32_t*)&hh;
}

// ---------------- small kernels ----------------
__global__ void reset_kernel() {
    int i = threadIdx.x;
    if (i < E_NUM) g_cnt[i] = 0;
    if (i == 0) g_work = 0;
    if (i < NTILES_MAX) g_done[i] = 0;
}
__global__ void prefill_kernel() {
    int i = blockIdx.x * 256 + threadIdx.x;
    if (i < PSLOTS) g_tok_of_slot[i] = 0;
}

__global__ void convert_w1(const float* __restrict__ src, int isUp, int njobs) {
    int id = blockIdx.x * 256 + threadIdx.x;
    if (id >= njobs) return;
    int e = id / (F_DIM * 256);
    int rem = id - e * (F_DIM * 256);
    int f = rem >> 8;
    int kc = rem & 255;
    const float4* s4 = (const float4*)(src + ((size_t)e * F_DIM + f) * D_DIM + kc * 8);
    float4 v0 = s4[0], v1 = s4[1];
    uint4 h;
    h.x = pack2h(v0.x, v0.y); h.y = pack2h(v0.z, v0.w);
    h.z = pack2h(v1.x, v1.y); h.w = pack2h(v1.z, v1.w);
    int ftile = f >> 6, fl = f & 63;
    int wn = fl >> 5, idx = fl & 31;
    int r = wn * 64 + (isUp ? 32 : 0) + idx;
    int s = kc >> 3, kcs = kc & 7;
    char* base = g_w1p + ((size_t)((e * 12 + ftile) * NS1 + s)) * BBYTES;
    *(uint4*)(base + swz(r, kcs)) = h;
}

__global__ void convert_w2(const float* __restrict__ src, int njobs) {
    int id = blockIdx.x * 256 + threadIdx.x;
    if (id >= njobs) return;
    int e = id / (D_DIM * 96);
    int rem = id - e * (D_DIM * 96);
    int n = rem / 96;
    int kc = rem - n * 96;
    const float4* s4 = (const float4*)(src + ((size_t)e * D_DIM + n) * F_DIM + kc * 8);
    float4 v0 = s4[0], v1 = s4[1];
    uint4 h;
    h.x = pack2h(v0.x, v0.y); h.y = pack2h(v0.z, v0.w);
    h.z = pack2h(v1.x, v1.y); h.w = pack2h(v1.z, v1.w);
    int ntile = n >> 7, r = n & 127;
    int s = kc >> 3, kcs = kc & 7;
    char* base = g_w2p + ((size_t)((e * 16 + ntile) * NS2 + s)) * BBYTES;
    *(uint4*)(base + swz(r, kcs)) = h;
}

__global__ void gather_x(const float* __restrict__ x) {
    int id = blockIdx.x * 256 + threadIdx.x;
    int p = id >> 8;
    int kc = id & 255;
    if (p >= PSLOTS) return;
    int tok = g_tok_of_slot[p];
    const float4* s4 = (const float4*)(x + (size_t)tok * D_DIM + kc * 8);
    float4 v0 = s4[0], v1 = s4[1];
    uint4 h;
    h.x = pack2h(v0.x, v0.y); h.y = pack2h(v0.z, v0.w);
    h.z = pack2h(v1.x, v1.y); h.w = pack2h(v1.z, v1.w);
    int tile = p >> 7, r = p & 127;
    int s = kc >> 3, kcs = kc & 7;
    char* base = g_xg + ((size_t)(tile * NS1 + s)) * ABYTES;
    *(uint4*)(base + swz(r, kcs)) = h;
}

__global__ void router_kernel(const float* __restrict__ x,
                              const float* __restrict__ wr, int T) {
    int warp = threadIdx.x >> 5;
    int lane = threadIdx.x & 31;
    int t = blockIdx.x * 8 + warp;
    if (t >= T) return;

    const float4* x4 = (const float4*)(x + (size_t)t * D_DIM);
    const float4* w4 = (const float4*)wr;
    float acc[E_NUM];
#pragma unroll
    for (int e = 0; e < E_NUM; e++) acc[e] = 0.f;
    for (int d4 = lane; d4 < D_DIM / 4; d4 += 32) {
        float4 xv = x4[d4];
#pragma unroll
        for (int e = 0; e < E_NUM; e++) {
            float4 wv = w4[e * (D_DIM / 4) + d4];
            acc[e] += xv.x * wv.x + xv.y * wv.y + xv.z * wv.z + xv.w * wv.w;
        }
    }
#pragma unroll
    for (int e = 0; e < E_NUM; e++) {
#pragma unroll
        for (int o = 16; o > 0; o >>= 1)
            acc[e] += __shfl_xor_sync(0xffffffffu, acc[e], o);
    }
    if (lane == 0) {
        float s0 = -1e30f, s1 = -1e30f;
        int i0 = 0, i1 = 0;
#pragma unroll
        for (int e = 0; e < E_NUM; e++) {
            float v = acc[e];
            if (v > s0) { s1 = s0; i1 = i0; s0 = v; i0 = e; }
            else if (v > s1) { s1 = v; i1 = e; }
        }
        float p1 = expf(s1 - s0);
        float inv = 1.f / (1.f + p1);
        g_topk_idx[2 * t] = i0;
        g_topk_idx[2 * t + 1] = i1;
        g_topk_w[2 * t] = inv;
        g_topk_w[2 * t + 1] = p1 * inv;
        atomicAdd(&g_cnt[i0], 1);
        atomicAdd(&g_cnt[i1], 1);
    }
}

__global__ void offsets_kernel() {
    if (threadIdx.x == 0) {
        int op = 0;
        for (int e = 0; e < E_NUM; e++) {
            g_off_pad[e] = op;
            op += ((g_cnt[e] + 127) >> 7) << 7;
            g_cursor[e] = 0;
        }
        g_off_pad[E_NUM] = op;
    }
}

__global__ void assign_kernel(int T) {
    int i = blockIdx.x * 256 + threadIdx.x;
    if (i >= 2 * T) return;
    int e = g_topk_idx[i];
    int pos = atomicAdd(&g_cursor[e], 1);
    int slot = g_off_pad[e] + pos;
    g_tok_of_slot[slot] = i >> 1;
    g_slot_of[i] = slot;
}

// ---- one K-stage of MMA (KT=64), warp tile 32x64 ----
__device__ __forceinline__ void stage_mma(uint32_t stg, int wm, int wn, int lane,
                                          float acc[16][4]) {
    uint32_t rs = (uint32_t)(lane & 7);
    uint32_t rowA0 = (uint32_t)(wm * 32 + (lane & 7) + ((lane >> 3) & 1) * 8);
    uint32_t rowB  = (uint32_t)(wn * 64 + (lane & 7) + ((lane >> 4) & 1) * 8);
    uint32_t cbA = (uint32_t)(lane >> 4);
    uint32_t cbB = (uint32_t)((lane >> 3) & 1);
    uint32_t aA0 = stg + rowA0 * 128;
    uint32_t aA1 = aA0 + 16 * 128;
    uint32_t aB  = stg + (uint32_t)ABYTES + rowB * 128;
#pragma unroll
    for (int ks = 0; ks < 4; ks++) {
        uint32_t chA = ((cbA + (uint32_t)(ks * 2)) ^ rs) << 4;
        uint32_t chB = ((cbB + (uint32_t)(ks * 2)) ^ rs) << 4;
        uint32_t ah[2][4];
        ldsm4(ah[0], aA0 + chA);
        ldsm4(ah[1], aA1 + chA);
        uint32_t bh[4][4];
#pragma unroll
        for (int g2 = 0; g2 < 4; g2++)
            ldsm4(bh[g2], aB + (uint32_t)g2 * (16 * 128) + chB);
#pragma unroll
        for (int g2 = 0; g2 < 4; g2++)
#pragma unroll
            for (int t = 0; t < 2; t++) {
                mma_f16(acc[t * 8 + g2 * 2 + 0], ah[t], bh[g2][0], bh[g2][1]);
                mma_f16(acc[t * 8 + g2 * 2 + 1], ah[t], bh[g2][2], bh[g2][3]);
            }
    }
}

// ---- pipelined K-loop for one item; base = persistent stage counter ----
__device__ __forceinline__ void run_item(uint32_t sb, const char* aSrc, const char* bSrc,
                                         int NS, int& base, int tid, int wm, int wn,
                                         int lane, float acc[16][4]) {
    if (tid == 0) {
#pragma unroll
        for (int p = 0; p < NSTG; p++) {
            int idx = base + p, slot = idx % 3;
            MBARRIER_EXPECT_TX(sb + slot * 16, STG_BYTES);
            uint32_t db = sb + 1024 + (uint32_t)slot * STG_BYTES;
            bulk_ld(db, aSrc + (size_t)p * ABYTES, ABYTES, sb + slot * 16);
            bulk_ld(db + ABYTES, bSrc + (size_t)p * BBYTES, BBYTES, sb + slot * 16);
        }
    }
#pragma unroll 1
    for (int s = 0; s < NS; s++) {
        int idx = base + s, slot = idx % 3, par = (idx / 3) & 1;
        MBARRIER_WAIT_PARITY(sb + slot * 16, par);
        stage_mma(sb + 1024 + (uint32_t)slot * STG_BYTES, wm, wn, lane, acc);
        __syncthreads();
        if (s + NSTG < NS && tid == 0) {
            MBARRIER_EXPECT_TX(sb + slot * 16, STG_BYTES);
            uint32_t db = sb + 1024 + (uint32_t)slot * STG_BYTES;
            bulk_ld(db, aSrc + (size_t)(s + NSTG) * ABYTES, ABYTES, sb + slot * 16);
            bulk_ld(db + ABYTES, bSrc + (size_t)(s + NSTG) * BBYTES, BBYTES, sb + slot * 16);
        }
    }
    base += NS;
}

// ================= fused persistent GEMM1+GEMM2 =================
__global__ __launch_bounds__(256, 2) void gemm_fused() {
    extern __shared__ __align__(16) char smem[];
    __shared__ int s_item;
    __shared__ int s_off[E_NUM + 1];
    uint32_t sb = smem_u32(smem);
    int tid = threadIdx.x, w = tid >> 5, lane = tid & 31;
    int wm = w >> 1, wn = w & 1;

    if (tid < NSTG) MBARRIER_INIT(sb + tid * 16, 1);
    if (tid < E_NUM + 1) s_off[tid] = g_off_pad[tid];
    __syncthreads();

    int NT = s_off[E_NUM] >> 7;
    int N1 = NT * 12;
    int total = N1 + NT * 16;
    int base = 0;
    int q = lane >> 2, t4 = lane & 3;

    for (;;) {
        if (tid == 0) s_item = atomicAdd(&g_work, 1);
        __syncthreads();
        int item = s_item;
        if (item >= total) break;

        float acc[16][4];
#pragma unroll
        for (int g = 0; g < 16; g++)
#pragma unroll
            for (int i = 0; i < 4; i++) acc[g][i] = 0.f;

        if (item < N1) {
            // ---- GEMM1 tile ----
            int tile = item / 12, fx = item - tile * 12;
            int e = 0;
#pragma unroll
            for (int k = 1; k <= E_NUM; k++) e += (tile >= (s_off[k] >> 7));
            int cnt = g_cnt[e];
            int m0 = (tile - (s_off[e] >> 7)) * 128;
            int f0 = fx * 64;

            const char* aSrc = g_xg + (size_t)tile * NS1 * ABYTES;
            const char* bSrc = g_w1p + (size_t)((e * 12 + fx) * NS1) * BBYTES;
            run_item(sb, aSrc, bSrc, NS1, base, tid, wm, wn, lane, acc);

            // epilogue: SwiGLU + fp16 H
            char* hBase = g_hp + (size_t)tile * NS2 * ABYTES;
#pragma unroll
            for (int t = 0; t < 2; t++) {
                int rl0 = wm * 32 + t * 16 + q;
                int rl1 = rl0 + 8;
#pragma unroll
                for (int g = 0; g < 4; g++) {
                    int f = f0 + wn * 32 + g * 8 + t4 * 2;
                    int s2 = f >> 6;
                    int fl = f & 63;
                    int chunk = fl >> 3;
                    int inc = (2 * fl) & 15;
                    const float* ga = acc[t * 8 + g];
                    const float* ua = acc[t * 8 + 4 + g];
                    char* sbase = hBase + (size_t)s2 * ABYTES;
                    if (m0 + rl0 < cnt) {
                        float g0 = ga[0], g1 = ga[1], u0 = ua[0], u1 = ua[1];
                        float h0 = g0 / (1.f + __expf(-g0)) * u0;
                        float h1 = g1 / (1.f + __expf(-g1)) * u1;
                        *(uint32_t*)(sbase + swz(rl0, chunk) + inc) = pack2h(h0, h1);
                    }
                    if (m0 + rl1 < cnt) {
                        float g0 = ga[2], g1 = ga[3], u0 = ua[2], u1 = ua[3];
                        float h0 = g0 / (1.f + __expf(-g0)) * u0;
                        float h1 = g1 / (1.f + __expf(-g1)) * u1;
                        *(uint32_t*)(sbase + swz(rl1, chunk) + inc) = pack2h(h0, h1);
                    }
                }
            }
            __syncthreads();
            if (tid == 0) {
                // release: make all CTA threads' H stores visible to the async
                // proxy of other SMs, THEN publish the done-count.
                asm volatile("fence.acq_rel.gpu;" ::: "memory");
                asm volatile("fence.proxy.async;" ::: "memory");
                asm volatile("red.release.gpu.global.add.s32 [%0], 1;"
                             :: "l"(&g_done[tile]) : "memory");
            }
        } else {
            // ---- GEMM2 tile ----
            int item2 = item - N1;
            int tile = item2 / 16, nx = item2 - tile * 16;
            int e = 0;
#pragma unroll
            for (int k = 1; k <= E_NUM; k++) e += (tile >= (s_off[k] >> 7));
            int cnt = g_cnt[e];
            int m0 = (tile - (s_off[e] >> 7)) * 128;
            int n0 = nx * 128;
            int off_pad = s_off[e];

            if (tid == 0) {
                // acquire: spin with acquire loads, then fence the async proxy
                // (the TMA reads of g_hp are issued by this same thread below).
                int v;
                do {
                    asm volatile("ld.acquire.gpu.global.s32 %0, [%1];"
                                 : "=r"(v) : "l"(&g_done[tile]) : "memory");
                } while (v < 12);
                asm volatile("fence.acq_rel.gpu;" ::: "memory");
                asm volatile("fence.proxy.async;" ::: "memory");
            }
            __syncthreads();

            const char* aSrc = g_hp + (size_t)tile * NS2 * ABYTES;
            const char* bSrc = g_w2p + (size_t)((e * 16 + nx) * NS2) * BBYTES;
            run_item(sb, aSrc, bSrc, NS2, base, tid, wm, wn, lane, acc);

            // epilogue: fp32 store to g_O
#pragma unroll
            for (int t = 0; t < 2; t++) {
                int rl0 = wm * 32 + t * 16 + q;
                int rl1 = rl0 + 8;
#pragma unroll
                for (int g = 0; g < 8; g++) {
                    int ni = n0 + wn * 64 + g * 8 + t4 * 2;
                    if (m0 + rl0 < cnt) {
                        float2 v; v.x = acc[t * 8 + g][0]; v.y = acc[t * 8 + g][1];
                        *(float2*)&g_O[(size_t)(off_pad + m0 + rl0) * D_DIM + ni] = v;
                    }
                    if (m0 + rl1 < cnt) {
                        float2 v; v.x = acc[t * 8 + g][2]; v.y = acc[t * 8 + g][3];
                        *(float2*)&g_O[(size_t)(off_pad + m0 + rl1) * D_DIM + ni] = v;
                    }
                }
            }
            __syncthreads();
        }
    }
}

// ---------------- combine ----------------
__global__ void combine_kernel(float* __restrict__ out, int T) {
    int t = blockIdx.x;
    int d4 = blockIdx.y * blockDim.x + threadIdx.x;
    float w0 = g_topk_w[2 * t];
    float w1 = g_topk_w[2 * t + 1];
    int s0 = g_slot_of[2 * t];
    int s1 = g_slot_of[2 * t + 1];
    float4 a = ((const float4*)&g_O[(size_t)s0 * D_DIM])[d4];
    float4 b = ((const float4*)&g_O[(size_t)s1 * D_DIM])[d4];
    float4 r;
    r.x = w0 * a.x + w1 * b.x;
    r.y = w0 * a.y + w1 * b.y;
    r.z = w0 * a.z + w1 * b.z;
    r.w = w0 * a.w + w1 * b.w;
    ((float4*)out)[(size_t)t * (D_DIM / 4) + d4] = r;
}

// ---------------- launch ----------------
extern "C" void kernel_launch(void* const* d_in, const int* in_sizes, int n_in,
                              void* d_out, int out_size) {
    const float* x  = (const float*)d_in[0];
    const float* wr = (const float*)d_in[1];
    const float* wg = (const float*)d_in[2];
    const float* wu = (const float*)d_in[3];
    const float* wd = (const float*)d_in[4];
    int T = in_sizes[0] / D_DIM;  // 2048

    cudaFuncSetAttribute(gemm_fused, cudaFuncAttributeMaxDynamicSharedMemorySize, SMEM_TOTAL);

    reset_kernel<<<1, 64>>>();
    prefill_kernel<<<(PSLOTS + 255) / 256, 256>>>();

    int nw1 = E_NUM * F_DIM * 256;
    int nw2 = E_NUM * D_DIM * 96;
    convert_w1<<<(nw1 + 255) / 256, 256>>>(wg, 0, nw1);
    convert_w1<<<(nw1 + 255) / 256, 256>>>(wu, 1, nw1);
    convert_w2<<<(nw2 + 255) / 256, 256>>>(wd, nw2);

    router_kernel<<<(T + 7) / 8, 256>>>(x, wr, T);
    offsets_kernel<<<1, 1>>>();
    assign_kernel<<<(2 * T + 255) / 256, 256>>>(T);
    gather_x<<<(PSLOTS * 256) / 256, 256>>>(x);

    gemm_fused<<<NWORKERS, 256, SMEM_TOTAL>>>();

    combine_kernel<<<dim3(T, 2), 256>>>((float*)d_out, T);
}